// round 5
// baseline (speedup 1.0000x reference)
#include <cuda_runtime.h>
#include <math.h>

#define S4 4
#define CD 512
#define KD 128
#define HW 1024
#define NM 16384
#define CE 16
#define TAU_INV 30.0f
#define KSPLIT 16

// ---------------- scratch (device globals; no allocation allowed) ----------------
__device__ float g_wq_self[S4 * HW * KD];
__device__ float g_sc[S4 * HW * HW];
__device__ float g_t[S4 * CD * HW];
__device__ float g_wq_cross[S4 * HW * KD];
__device__ float g_wk_cross[S4 * NM * KD];
__device__ float g_part[KSPLIT * S4 * HW * 18];

// ================= projection + L2 normalize =================
// in layout: [(f*S4+s)*CD + c]*HW + n ; out [s][token][d]
// 64 tokens x 128 d per block; thread tile: 8 tok (warp-uniform) x 4 d (strided +32)
__global__ __launch_bounds__(256) void proj_kernel(
    const float* __restrict__ in, const float* __restrict__ W,
    const float* __restrict__ bias, float* __restrict__ out, int NT) {
  __shared__ float As[64 * 36];    // [tok][cc]
  __shared__ float Ws[128 * 36];   // [d][cc]
  int s = blockIdx.y;
  int tg0 = blockIdx.x * 64;
  int f = tg0 >> 10;
  int n0 = tg0 & 1023;
  const float* inb = in + ((size_t)(f * S4 + s)) * CD * HW + n0;
  int t = threadIdx.x;
  int wid = t >> 5;    // token group: 8 tokens wid*8..+7 (warp-uniform)
  int dgr = t & 31;    // d rows: dgr + 32*j, j=0..3
  float acc[8][4] = {};
  for (int c0 = 0; c0 < CD; c0 += 32) {
    int idx = t;
    #pragma unroll
    for (int r = 0; r < 8; r++, idx += 256) {
      int cc = idx >> 6, tok = idx & 63;
      As[tok * 36 + cc] = inb[(size_t)(c0 + cc) * HW + tok];
    }
    idx = t;
    #pragma unroll
    for (int r = 0; r < 16; r++, idx += 256) {
      int d = idx >> 5, cc = idx & 31;
      Ws[d * 36 + cc] = W[d * CD + c0 + cc];
    }
    __syncthreads();
    #pragma unroll
    for (int cc4 = 0; cc4 < 8; cc4++) {
      float4 b[4];
      #pragma unroll
      for (int j = 0; j < 4; j++)
        b[j] = *(const float4*)(Ws + (dgr + 32 * j) * 36 + cc4 * 4);
      #pragma unroll
      for (int i = 0; i < 8; i++) {
        float4 a = *(const float4*)(As + (wid * 8 + i) * 36 + cc4 * 4);
        #pragma unroll
        for (int j = 0; j < 4; j++) {
          acc[i][j] = fmaf(a.x, b[j].x, acc[i][j]);
          acc[i][j] = fmaf(a.y, b[j].y, acc[i][j]);
          acc[i][j] = fmaf(a.z, b[j].z, acc[i][j]);
          acc[i][j] = fmaf(a.w, b[j].w, acc[i][j]);
        }
      }
    }
    __syncthreads();
  }
  float bv[4];
  #pragma unroll
  for (int j = 0; j < 4; j++) bv[j] = bias[dgr + 32 * j];
  float ssp[8];
  #pragma unroll
  for (int i = 0; i < 8; i++) {
    float s0 = 0.0f;
    #pragma unroll
    for (int j = 0; j < 4; j++) {
      acc[i][j] += bv[j];
      s0 = fmaf(acc[i][j], acc[i][j], s0);
    }
    ssp[i] = s0;
  }
  #pragma unroll
  for (int o = 16; o; o >>= 1)
    #pragma unroll
    for (int i = 0; i < 8; i++)
      ssp[i] += __shfl_xor_sync(0xffffffffu, ssp[i], o);
  #pragma unroll
  for (int i = 0; i < 8; i++) {
    float scl = 1.0f / fmaxf(sqrtf(ssp[i]), 1e-12f);
    float* ob = out + ((size_t)s * NT + tg0 + wid * 8 + i) * KD;
    #pragma unroll
    for (int j = 0; j < 4; j++)
      ob[dgr + 32 * j] = acc[i][j] * scl;
  }
}

// ================= self-attention raw scores (x30) =================
__global__ __launch_bounds__(256) void self_scores_kernel(
    const float* __restrict__ wq, float* __restrict__ sc) {
  __shared__ float QK[2][64][65];
  int s = blockIdx.z;
  int q0 = blockIdx.x * 64, k0 = blockIdx.y * 64;
  const float* base = wq + (size_t)s * HW * KD;
  int t = threadIdx.x;
  int qg = t & 15, kg = t >> 4;
  float acc[4][4] = {};
  for (int d0 = 0; d0 < KD; d0 += 64) {
    int idx = t;
    #pragma unroll
    for (int r = 0; r < 16; r++, idx += 256) {
      int row = idx >> 6, dd = idx & 63;
      QK[0][row][dd] = base[(size_t)(q0 + row) * KD + d0 + dd];
      QK[1][row][dd] = base[(size_t)(k0 + row) * KD + d0 + dd];
    }
    __syncthreads();
    #pragma unroll 8
    for (int k = 0; k < 64; k++) {
      float a[4], b[4];
      #pragma unroll
      for (int i = 0; i < 4; i++) a[i] = QK[0][qg * 4 + i][k];
      #pragma unroll
      for (int j = 0; j < 4; j++) b[j] = QK[1][kg * 4 + j][k];
      #pragma unroll
      for (int i = 0; i < 4; i++)
        #pragma unroll
        for (int j = 0; j < 4; j++)
          acc[i][j] = fmaf(a[i], b[j], acc[i][j]);
    }
    __syncthreads();
  }
  float* Cs = &QK[0][0][0];   // reuse as [64][65]
  #pragma unroll
  for (int i = 0; i < 4; i++)
    #pragma unroll
    for (int j = 0; j < 4; j++)
      Cs[(qg * 4 + i) * 65 + kg * 4 + j] = acc[i][j] * TAU_INV;
  __syncthreads();
  int idx = t;
  #pragma unroll
  for (int r = 0; r < 16; r++, idx += 256) {
    int row = idx >> 6, col = idx & 63;
    sc[((size_t)s * HW + q0 + row) * HW + k0 + col] = Cs[row * 65 + col];
  }
}

// ================= row softmax over 1024 =================
__global__ __launch_bounds__(256) void softmax_kernel(float* __restrict__ sc) {
  __shared__ float redm[8];
  __shared__ float reds[8];
  float* p = sc + (size_t)blockIdx.x * HW;
  int t = threadIdx.x, lane = t & 31, warp = t >> 5;
  float v0 = p[t], v1 = p[t + 256], v2 = p[t + 512], v3 = p[t + 768];
  float mx = fmaxf(fmaxf(v0, v1), fmaxf(v2, v3));
  #pragma unroll
  for (int o = 16; o; o >>= 1) mx = fmaxf(mx, __shfl_xor_sync(0xffffffffu, mx, o));
  if (lane == 0) redm[warp] = mx;
  __syncthreads();
  mx = redm[0];
  #pragma unroll
  for (int i = 1; i < 8; i++) mx = fmaxf(mx, redm[i]);
  v0 = __expf(v0 - mx); v1 = __expf(v1 - mx);
  v2 = __expf(v2 - mx); v3 = __expf(v3 - mx);
  float sum = v0 + v1 + v2 + v3;
  #pragma unroll
  for (int o = 16; o; o >>= 1) sum += __shfl_xor_sync(0xffffffffu, sum, o);
  if (lane == 0) reds[warp] = sum;
  __syncthreads();
  float tot = reds[0];
  #pragma unroll
  for (int i = 1; i < 8; i++) tot += reds[i];
  float inv = 1.0f / tot;
  p[t] = v0 * inv; p[t + 256] = v1 * inv;
  p[t + 512] = v2 * inv; p[t + 768] = v3 * inv;
}

// ================= self P.V + residual =================
// 128 n x 64 c per block; thread: 8 n (warp-uniform-ish) x 4 c (strided +16)
__global__ __launch_bounds__(256) void pv_self_kernel(
    const float* __restrict__ sc, const float* __restrict__ tgt,
    float* __restrict__ tout) {
  __shared__ float As[128 * 36];  // [n][m]
  __shared__ float Bs[64 * 36];   // [c][m]
  int s = blockIdx.z;
  int n0 = blockIdx.x * 128, c0 = blockIdx.y * 64;
  const float* P = sc + (size_t)s * HW * HW;
  const float* V = tgt + (size_t)s * CD * HW;
  int t = threadIdx.x;
  int cgr = t & 15;   // c rows: cgr + 16*j
  int ngr = t >> 4;   // n rows: ngr*8..+7
  float acc[8][4] = {};
  for (int m0 = 0; m0 < HW; m0 += 32) {
    int idx = t;
    #pragma unroll
    for (int r = 0; r < 16; r++, idx += 256) {
      int n = idx >> 5, m = idx & 31;
      As[n * 36 + m] = P[(size_t)(n0 + n) * HW + m0 + m];
    }
    idx = t;
    #pragma unroll
    for (int r = 0; r < 8; r++, idx += 256) {
      int c = idx >> 5, m = idx & 31;
      Bs[c * 36 + m] = V[(size_t)(c0 + c) * HW + m0 + m];
    }
    __syncthreads();
    #pragma unroll
    for (int m4 = 0; m4 < 8; m4++) {
      float4 b[4];
      #pragma unroll
      for (int j = 0; j < 4; j++)
        b[j] = *(const float4*)(Bs + (cgr + 16 * j) * 36 + m4 * 4);
      #pragma unroll
      for (int i = 0; i < 8; i++) {
        float4 a = *(const float4*)(As + (ngr * 8 + i) * 36 + m4 * 4);
        #pragma unroll
        for (int j = 0; j < 4; j++) {
          acc[i][j] = fmaf(a.x, b[j].x, acc[i][j]);
          acc[i][j] = fmaf(a.y, b[j].y, acc[i][j]);
          acc[i][j] = fmaf(a.z, b[j].z, acc[i][j]);
          acc[i][j] = fmaf(a.w, b[j].w, acc[i][j]);
        }
      }
    }
    __syncthreads();
  }
  #pragma unroll
  for (int j = 0; j < 4; j++) {
    int c = c0 + cgr + 16 * j;
    size_t g = (size_t)(s * CD + c) * HW + n0 + ngr * 8;
    #pragma unroll
    for (int i4 = 0; i4 < 8; i4 += 4) {
      float4 tg4 = *(const float4*)(tgt + g + i4);
      tg4.x += acc[i4 + 0][j]; tg4.y += acc[i4 + 1][j];
      tg4.z += acc[i4 + 2][j]; tg4.w += acc[i4 + 3][j];
      *(float4*)(tout + g + i4) = tg4;
    }
  }
}

// ================= instance norm =================
__global__ __launch_bounds__(256) void instnorm_kernel(float* __restrict__ x) {
  __shared__ float redS[8];
  __shared__ float redQ[8];
  float* p = x + (size_t)blockIdx.x * HW;
  int t = threadIdx.x, lane = t & 31, warp = t >> 5;
  float v0 = p[t], v1 = p[t + 256], v2 = p[t + 512], v3 = p[t + 768];
  float sum = v0 + v1 + v2 + v3;
  float sq = v0 * v0 + v1 * v1 + v2 * v2 + v3 * v3;
  #pragma unroll
  for (int o = 16; o; o >>= 1) {
    sum += __shfl_xor_sync(0xffffffffu, sum, o);
    sq  += __shfl_xor_sync(0xffffffffu, sq, o);
  }
  if (lane == 0) { redS[warp] = sum; redQ[warp] = sq; }
  __syncthreads();
  sum = redS[0]; sq = redQ[0];
  #pragma unroll
  for (int i = 1; i < 8; i++) { sum += redS[i]; sq += redQ[i]; }
  float mean = sum * (1.0f / HW);
  float var = sq * (1.0f / HW) - mean * mean;
  float rstd = rsqrtf(var + 1e-5f);
  p[t]       = (v0 - mean) * rstd;
  p[t + 256] = (v1 - mean) * rstd;
  p[t + 512] = (v2 - mean) * rstd;
  p[t + 768] = (v3 - mean) * rstd;
}

// ================= cross attention: flash-style, 64q x 128k tiles =================
__global__ __launch_bounds__(256, 1) void cross_attn_kernel(
    const float* __restrict__ wq, const float* __restrict__ wk,
    const float* __restrict__ pe, float* __restrict__ part) {
  extern __shared__ float sm[];
  float* Qs   = sm;                  // [64][132]
  float* Ks   = Qs + 64 * 132;       // [128][132]
  float* Ps   = Ks + 128 * 132;      // [64][132]
  float* Vs   = Ps + 64 * 132;       // [128][16]
  float* Os   = Vs + 128 * 16;       // [64][16]
  float* Om   = Os + 64 * 16;        // [64]
  float* Ol   = Om + 64;             // [64]
  float* Msc  = Ol + 64;             // [64]
  float* Pred = Msc + 64;            // [64][17]
  int qt = blockIdx.x, s = blockIdx.y, ksp = blockIdx.z;
  int q0 = qt * 64;
  int t = threadIdx.x;
  int qgr = t & 15;   // q rows: qgr + 16*i, i=0..3
  int kgr = t >> 4;   // k rows: kgr*8..+7 (warp-uniform pairs)
  // load Q tile scaled by TAU_INV
  {
    const float4* src = (const float4*)(wq + ((size_t)s * HW + q0) * KD);
    int idx = t;
    #pragma unroll
    for (int r = 0; r < 8; r++, idx += 256) {
      int q = idx >> 5, d4 = idx & 31;
      float4 v = src[idx];
      v.x *= TAU_INV; v.y *= TAU_INV; v.z *= TAU_INV; v.w *= TAU_INV;
      *(float4*)(Qs + q * 132 + d4 * 4) = v;
    }
  }
  if (t < 64) { Om[t] = -1e30f; Ol[t] = 0.0f; Msc[t] = 0.0f; }
  {
    int idx = t;
    #pragma unroll
    for (int r = 0; r < 4; r++, idx += 256) Os[idx] = 0.0f;
  }
  int pvq = t >> 2, pve = (t & 3) * 4;

  for (int kt = 0; kt < NM / (KSPLIT * 128); kt++) {
    int kk0 = ksp * (NM / KSPLIT) + kt * 128;
    __syncthreads();   // protect Ks/Vs/Ps from prev iter consumers
    {
      const float4* src = (const float4*)(wk + ((size_t)s * NM + kk0) * KD);
      int idx = t;
      #pragma unroll
      for (int r = 0; r < 16; r++, idx += 256) {
        int k = idx >> 5, d4 = idx & 31;
        *(float4*)(Ks + k * 132 + d4 * 4) = src[idx];
      }
    }
    {
      int f = kk0 >> 10, nn0 = kk0 & 1023;
      const float* pb = pe + ((size_t)(f * S4 + s)) * CE * HW + nn0;
      int idx = t;
      #pragma unroll
      for (int r = 0; r < 8; r++, idx += 256) {
        int e = idx >> 7, k = idx & 127;
        Vs[k * 16 + e] = pb[(size_t)e * HW + k];
      }
    }
    __syncthreads();
    // ---- scores: 4q x 8k per thread ----
    float acc[4][8] = {};
    #pragma unroll 8
    for (int d4 = 0; d4 < 32; d4++) {
      float4 b[8];
      #pragma unroll
      for (int jj = 0; jj < 8; jj++)
        b[jj] = *(const float4*)(Ks + (kgr * 8 + jj) * 132 + d4 * 4);
      #pragma unroll
      for (int i = 0; i < 4; i++) {
        float4 a = *(const float4*)(Qs + (qgr + 16 * i) * 132 + d4 * 4);
        #pragma unroll
        for (int jj = 0; jj < 8; jj++) {
          acc[i][jj] = fmaf(a.x, b[jj].x, acc[i][jj]);
          acc[i][jj] = fmaf(a.y, b[jj].y, acc[i][jj]);
          acc[i][jj] = fmaf(a.z, b[jj].z, acc[i][jj]);
          acc[i][jj] = fmaf(a.w, b[jj].w, acc[i][jj]);
        }
      }
    }
    // ---- per-thread row-max partials ----
    #pragma unroll
    for (int i = 0; i < 4; i++) {
      float tm = acc[i][0];
      #pragma unroll
      for (int jj = 1; jj < 8; jj++) tm = fmaxf(tm, acc[i][jj]);
      Pred[(qgr + 16 * i) * 17 + kgr] = tm;
    }
    __syncthreads();
    if (t < 64) {
      float m = Pred[t * 17];
      #pragma unroll
      for (int i = 1; i < 16; i++) m = fmaxf(m, Pred[t * 17 + i]);
      float mo = Om[t];
      float M = fmaxf(mo, m);
      Msc[t] = __expf(mo - M);
      Om[t] = M;
    }
    __syncthreads();
    // ---- exp, write P, row-sum partials ----
    #pragma unroll
    for (int i = 0; i < 4; i++) {
      int row = qgr + 16 * i;
      float M = Om[row];
      float psum = 0.0f;
      float4 p0, p1;
      p0.x = __expf(acc[i][0] - M); p0.y = __expf(acc[i][1] - M);
      p0.z = __expf(acc[i][2] - M); p0.w = __expf(acc[i][3] - M);
      p1.x = __expf(acc[i][4] - M); p1.y = __expf(acc[i][5] - M);
      p1.z = __expf(acc[i][6] - M); p1.w = __expf(acc[i][7] - M);
      psum = p0.x + p0.y + p0.z + p0.w + p1.x + p1.y + p1.z + p1.w;
      *(float4*)(Ps + row * 132 + kgr * 8) = p0;
      *(float4*)(Ps + row * 132 + kgr * 8 + 4) = p1;
      Pred[row * 17 + kgr] = psum;
    }
    __syncthreads();
    if (t < 64) {
      float sum = 0.0f;
      #pragma unroll
      for (int i = 0; i < 16; i++) sum += Pred[t * 17 + i];
      Ol[t] = Ol[t] * Msc[t] + sum;
    }
    // ---- PV: thread = (q, 4 e's) ----
    {
      float scl = Msc[pvq];
      float4 o = *(float4*)(Os + pvq * 16 + pve);
      o.x *= scl; o.y *= scl; o.z *= scl; o.w *= scl;
      const float* prow = Ps + pvq * 132;
      #pragma unroll 8
      for (int k = 0; k < 128; k++) {
        float p = prow[k];
        float4 v = *(const float4*)(Vs + k * 16 + pve);
        o.x = fmaf(p, v.x, o.x); o.y = fmaf(p, v.y, o.y);
        o.z = fmaf(p, v.z, o.z); o.w = fmaf(p, v.w, o.w);
      }
      *(float4*)(Os + pvq * 16 + pve) = o;
    }
  }
  __syncthreads();
  if (t < 64) {
    float* pp = part + ((size_t)((ksp * S4 + s) * HW) + q0 + t) * 18;
    #pragma unroll
    for (int e = 0; e < 16; e++) pp[e] = Os[t * 16 + e];
    pp[16] = Om[t];
    pp[17] = Ol[t];
  }
}

// ================= merge split-K partials + sigmoid =================
__global__ __launch_bounds__(256) void merge_kernel(
    const float* __restrict__ part, float* __restrict__ out) {
  int g = blockIdx.x * 256 + threadIdx.x;   // 16384 threads = (s,n) x 4 e-groups
  int eg = (g & 3) * 4;
  int sn = g >> 2;
  int n = sn & 1023, s = sn >> 10;
  float M = -1e30f;
  #pragma unroll
  for (int z = 0; z < KSPLIT; z++)
    M = fmaxf(M, part[((size_t)((z * S4 + s) * HW) + n) * 18 + 16]);
  float L = 0.0f;
  float O[4] = {};
  #pragma unroll
  for (int z = 0; z < KSPLIT; z++) {
    const float* pp = part + ((size_t)((z * S4 + s) * HW) + n) * 18;
    float w = __expf(pp[16] - M);
    L += pp[17] * w;
    #pragma unroll
    for (int e = 0; e < 4; e++) O[e] += pp[eg + e] * w;
  }
  float inv = 1.0f / L;
  #pragma unroll
  for (int e = 0; e < 4; e++) {
    float v = O[e] * inv;
    out[(size_t)(s * CE + eg + e) * HW + n] = 1.0f / (1.0f + __expf(-v));
  }
}

// ================= host =================
extern "C" void kernel_launch(void* const* d_in, const int* in_sizes, int n_in,
                              void* d_out, int out_size) {
  const float* tgt = (const float*)d_in[0];
  const float* mem = (const float*)d_in[1];
  const float* pe  = (const float*)d_in[2];
  const float* wks = (const float*)d_in[3];
  const float* bks = (const float*)d_in[4];
  const float* wkc = (const float*)d_in[5];
  const float* bkc = (const float*)d_in[6];
  float* out = (float*)d_out;

  float *p_wq_self, *p_sc, *p_t, *p_wq_cross, *p_wk_cross, *p_part;
  cudaGetSymbolAddress((void**)&p_wq_self, g_wq_self);
  cudaGetSymbolAddress((void**)&p_sc, g_sc);
  cudaGetSymbolAddress((void**)&p_t, g_t);
  cudaGetSymbolAddress((void**)&p_wq_cross, g_wq_cross);
  cudaGetSymbolAddress((void**)&p_wk_cross, g_wk_cross);
  cudaGetSymbolAddress((void**)&p_part, g_part);

  // self-attention
  proj_kernel<<<dim3(16, 4), 256>>>(tgt, wks, bks, p_wq_self, HW);
  self_scores_kernel<<<dim3(16, 16, 4), 256>>>(p_wq_self, p_sc);
  softmax_kernel<<<4096, 256>>>(p_sc);
  pv_self_kernel<<<dim3(8, 8, 4), 256>>>(p_sc, tgt, p_t);
  instnorm_kernel<<<2048, 256>>>(p_t);

  // cross-attention projections
  proj_kernel<<<dim3(16, 4), 256>>>(p_t, wkc, bkc, p_wq_cross, HW);
  proj_kernel<<<dim3(256, 4), 256>>>(mem, wkc, bkc, p_wk_cross, NM);

  // flash cross-attention with split-K=16
  const int smem_bytes = (64 * 132 + 128 * 132 + 64 * 132 + 128 * 16 +
                          64 * 16 + 64 * 3 + 64 * 17) * 4;   // 152576 B
  cudaFuncSetAttribute(cross_attn_kernel,
                       cudaFuncAttributeMaxDynamicSharedMemorySize, smem_bytes);
  cross_attn_kernel<<<dim3(16, 4, KSPLIT), 256, smem_bytes>>>(p_wq_cross, p_wk_cross, pe, p_part);
  merge_kernel<<<64, 256>>>(p_part, out);
}

// round 6
// speedup vs baseline: 1.0094x; 1.0094x over previous
#include <cuda_runtime.h>
#include <math.h>

#define S4 4
#define CD 512
#define KD 128
#define HW 1024
#define NM 16384
#define CE 16
#define TAU_INV 30.0f
#define KSPLIT 16

typedef unsigned long long ull;
__device__ __forceinline__ void fma2(ull& d, ull a, ull b) {
  asm("fma.rn.f32x2 %0, %1, %2, %0;" : "+l"(d) : "l"(a), "l"(b));
}
__device__ __forceinline__ float red2(ull v) {
  float lo, hi;
  asm("mov.b64 {%0,%1}, %2;" : "=f"(lo), "=f"(hi) : "l"(v));
  return lo + hi;
}
__device__ __forceinline__ ull dup2(float x) {
  ull r; asm("mov.b64 %0, {%1,%1};" : "=l"(r) : "f"(x)); return r;
}

// ---------------- scratch ----------------
__device__ float g_wq_self[S4 * HW * KD];
__device__ float g_sc[S4 * HW * HW];
__device__ float g_t[S4 * CD * HW];
__device__ float g_wq_cross[S4 * HW * KD];
__device__ float g_wk_cross[S4 * NM * KD];
__device__ float g_part[KSPLIT * S4 * HW * 18];

// ================= projection + L2 normalize (unchanged from R4) =================
__global__ __launch_bounds__(256) void proj_kernel(
    const float* __restrict__ in, const float* __restrict__ W,
    const float* __restrict__ bias, float* __restrict__ out, int NT) {
  __shared__ float As[64 * 36];
  __shared__ float Ws[128 * 36];
  int s = blockIdx.y;
  int tg0 = blockIdx.x * 64;
  int f = tg0 >> 10;
  int n0 = tg0 & 1023;
  const float* inb = in + ((size_t)(f * S4 + s)) * CD * HW + n0;
  int t = threadIdx.x;
  int wid = t >> 5;
  int dgr = t & 31;
  float acc[8][4] = {};
  for (int c0 = 0; c0 < CD; c0 += 32) {
    int idx = t;
    #pragma unroll
    for (int r = 0; r < 8; r++, idx += 256) {
      int cc = idx >> 6, tok = idx & 63;
      As[tok * 36 + cc] = inb[(size_t)(c0 + cc) * HW + tok];
    }
    idx = t;
    #pragma unroll
    for (int r = 0; r < 16; r++, idx += 256) {
      int d = idx >> 5, cc = idx & 31;
      Ws[d * 36 + cc] = W[d * CD + c0 + cc];
    }
    __syncthreads();
    #pragma unroll
    for (int cc4 = 0; cc4 < 8; cc4++) {
      float4 b[4];
      #pragma unroll
      for (int j = 0; j < 4; j++)
        b[j] = *(const float4*)(Ws + (dgr + 32 * j) * 36 + cc4 * 4);
      #pragma unroll
      for (int i = 0; i < 8; i++) {
        float4 a = *(const float4*)(As + (wid * 8 + i) * 36 + cc4 * 4);
        #pragma unroll
        for (int j = 0; j < 4; j++) {
          acc[i][j] = fmaf(a.x, b[j].x, acc[i][j]);
          acc[i][j] = fmaf(a.y, b[j].y, acc[i][j]);
          acc[i][j] = fmaf(a.z, b[j].z, acc[i][j]);
          acc[i][j] = fmaf(a.w, b[j].w, acc[i][j]);
        }
      }
    }
    __syncthreads();
  }
  float bv[4];
  #pragma unroll
  for (int j = 0; j < 4; j++) bv[j] = bias[dgr + 32 * j];
  float ssp[8];
  #pragma unroll
  for (int i = 0; i < 8; i++) {
    float s0 = 0.0f;
    #pragma unroll
    for (int j = 0; j < 4; j++) {
      acc[i][j] += bv[j];
      s0 = fmaf(acc[i][j], acc[i][j], s0);
    }
    ssp[i] = s0;
  }
  #pragma unroll
  for (int o = 16; o; o >>= 1)
    #pragma unroll
    for (int i = 0; i < 8; i++)
      ssp[i] += __shfl_xor_sync(0xffffffffu, ssp[i], o);
  #pragma unroll
  for (int i = 0; i < 8; i++) {
    float scl = 1.0f / fmaxf(sqrtf(ssp[i]), 1e-12f);
    float* ob = out + ((size_t)s * NT + tg0 + wid * 8 + i) * KD;
    #pragma unroll
    for (int j = 0; j < 4; j++)
      ob[dgr + 32 * j] = acc[i][j] * scl;
  }
}

// ================= self-attention raw scores (unchanged) =================
__global__ __launch_bounds__(256) void self_scores_kernel(
    const float* __restrict__ wq, float* __restrict__ sc) {
  __shared__ float QK[2][64][65];
  int s = blockIdx.z;
  int q0 = blockIdx.x * 64, k0 = blockIdx.y * 64;
  const float* base = wq + (size_t)s * HW * KD;
  int t = threadIdx.x;
  int qg = t & 15, kg = t >> 4;
  float acc[4][4] = {};
  for (int d0 = 0; d0 < KD; d0 += 64) {
    int idx = t;
    #pragma unroll
    for (int r = 0; r < 16; r++, idx += 256) {
      int row = idx >> 6, dd = idx & 63;
      QK[0][row][dd] = base[(size_t)(q0 + row) * KD + d0 + dd];
      QK[1][row][dd] = base[(size_t)(k0 + row) * KD + d0 + dd];
    }
    __syncthreads();
    #pragma unroll 8
    for (int k = 0; k < 64; k++) {
      float a[4], b[4];
      #pragma unroll
      for (int i = 0; i < 4; i++) a[i] = QK[0][qg * 4 + i][k];
      #pragma unroll
      for (int j = 0; j < 4; j++) b[j] = QK[1][kg * 4 + j][k];
      #pragma unroll
      for (int i = 0; i < 4; i++)
        #pragma unroll
        for (int j = 0; j < 4; j++)
          acc[i][j] = fmaf(a[i], b[j], acc[i][j]);
    }
    __syncthreads();
  }
  float* Cs = &QK[0][0][0];
  #pragma unroll
  for (int i = 0; i < 4; i++)
    #pragma unroll
    for (int j = 0; j < 4; j++)
      Cs[(qg * 4 + i) * 65 + kg * 4 + j] = acc[i][j] * TAU_INV;
  __syncthreads();
  int idx = t;
  #pragma unroll
  for (int r = 0; r < 16; r++, idx += 256) {
    int row = idx >> 6, col = idx & 63;
    sc[((size_t)s * HW + q0 + row) * HW + k0 + col] = Cs[row * 65 + col];
  }
}

// ================= row softmax, static max = 30 =================
__global__ __launch_bounds__(256) void softmax_kernel(float* __restrict__ sc) {
  __shared__ float reds[8];
  float* p = sc + (size_t)blockIdx.x * HW;
  int t = threadIdx.x, lane = t & 31, warp = t >> 5;
  float v0 = __expf(p[t] - 30.0f),       v1 = __expf(p[t + 256] - 30.0f);
  float v2 = __expf(p[t + 512] - 30.0f), v3 = __expf(p[t + 768] - 30.0f);
  float sum = v0 + v1 + v2 + v3;
  #pragma unroll
  for (int o = 16; o; o >>= 1) sum += __shfl_xor_sync(0xffffffffu, sum, o);
  if (lane == 0) reds[warp] = sum;
  __syncthreads();
  float tot = reds[0];
  #pragma unroll
  for (int i = 1; i < 8; i++) tot += reds[i];
  float inv = 1.0f / tot;
  p[t] = v0 * inv; p[t + 256] = v1 * inv;
  p[t + 512] = v2 * inv; p[t + 768] = v3 * inv;
}

// ================= self P.V + residual (unchanged) =================
__global__ __launch_bounds__(256) void pv_self_kernel(
    const float* __restrict__ sc, const float* __restrict__ tgt,
    float* __restrict__ tout) {
  __shared__ float As[128 * 36];
  __shared__ float Bs[64 * 36];
  int s = blockIdx.z;
  int n0 = blockIdx.x * 128, c0 = blockIdx.y * 64;
  const float* P = sc + (size_t)s * HW * HW;
  const float* V = tgt + (size_t)s * CD * HW;
  int t = threadIdx.x;
  int cgr = t & 15;
  int ngr = t >> 4;
  float acc[8][4] = {};
  for (int m0 = 0; m0 < HW; m0 += 32) {
    int idx = t;
    #pragma unroll
    for (int r = 0; r < 16; r++, idx += 256) {
      int n = idx >> 5, m = idx & 31;
      As[n * 36 + m] = P[(size_t)(n0 + n) * HW + m0 + m];
    }
    idx = t;
    #pragma unroll
    for (int r = 0; r < 8; r++, idx += 256) {
      int c = idx >> 5, m = idx & 31;
      Bs[c * 36 + m] = V[(size_t)(c0 + c) * HW + m0 + m];
    }
    __syncthreads();
    #pragma unroll
    for (int m4 = 0; m4 < 8; m4++) {
      float4 b[4];
      #pragma unroll
      for (int j = 0; j < 4; j++)
        b[j] = *(const float4*)(Bs + (cgr + 16 * j) * 36 + m4 * 4);
      #pragma unroll
      for (int i = 0; i < 8; i++) {
        float4 a = *(const float4*)(As + (ngr * 8 + i) * 36 + m4 * 4);
        #pragma unroll
        for (int j = 0; j < 4; j++) {
          acc[i][j] = fmaf(a.x, b[j].x, acc[i][j]);
          acc[i][j] = fmaf(a.y, b[j].y, acc[i][j]);
          acc[i][j] = fmaf(a.z, b[j].z, acc[i][j]);
          acc[i][j] = fmaf(a.w, b[j].w, acc[i][j]);
        }
      }
    }
    __syncthreads();
  }
  #pragma unroll
  for (int j = 0; j < 4; j++) {
    int c = c0 + cgr + 16 * j;
    size_t g = (size_t)(s * CD + c) * HW + n0 + ngr * 8;
    #pragma unroll
    for (int i4 = 0; i4 < 8; i4 += 4) {
      float4 tg4 = *(const float4*)(tgt + g + i4);
      tg4.x += acc[i4 + 0][j]; tg4.y += acc[i4 + 1][j];
      tg4.z += acc[i4 + 2][j]; tg4.w += acc[i4 + 3][j];
      *(float4*)(tout + g + i4) = tg4;
    }
  }
}

// ================= instance norm (unchanged) =================
__global__ __launch_bounds__(256) void instnorm_kernel(float* __restrict__ x) {
  __shared__ float redS[8];
  __shared__ float redQ[8];
  float* p = x + (size_t)blockIdx.x * HW;
  int t = threadIdx.x, lane = t & 31, warp = t >> 5;
  float v0 = p[t], v1 = p[t + 256], v2 = p[t + 512], v3 = p[t + 768];
  float sum = v0 + v1 + v2 + v3;
  float sq = v0 * v0 + v1 * v1 + v2 * v2 + v3 * v3;
  #pragma unroll
  for (int o = 16; o; o >>= 1) {
    sum += __shfl_xor_sync(0xffffffffu, sum, o);
    sq  += __shfl_xor_sync(0xffffffffu, sq, o);
  }
  if (lane == 0) { redS[warp] = sum; redQ[warp] = sq; }
  __syncthreads();
  sum = redS[0]; sq = redQ[0];
  #pragma unroll
  for (int i = 1; i < 8; i++) { sum += redS[i]; sq += redQ[i]; }
  float mean = sum * (1.0f / HW);
  float var = sq * (1.0f / HW) - mean * mean;
  float rstd = rsqrtf(var + 1e-5f);
  p[t]       = (v0 - mean) * rstd;
  p[t + 256] = (v1 - mean) * rstd;
  p[t + 512] = (v2 - mean) * rstd;
  p[t + 768] = (v3 - mean) * rstd;
}

// ================= cross attention: f32x2 scores, static max =================
__global__ __launch_bounds__(256, 1) void cross_attn_kernel(
    const float* __restrict__ wq, const float* __restrict__ wk,
    const float* __restrict__ pe, float* __restrict__ part) {
  extern __shared__ float sm[];
  float* Qs   = sm;                  // [64][132]
  float* Ks   = Qs + 64 * 132;       // [128][132]
  float* Ps   = Ks + 128 * 132;      // [64][132]
  float* Vs   = Ps + 64 * 132;       // [128][16]
  float* Os   = Vs + 128 * 16;       // [64][16]
  float* Ol   = Os + 64 * 16;        // [64]
  float* Pred = Ol + 64;             // [64][17]
  int qt = blockIdx.x, s = blockIdx.y, ksp = blockIdx.z;
  int q0 = qt * 64;
  int t = threadIdx.x;
  int qgr = t & 15;
  int kgr = t >> 4;
  {
    const float4* src = (const float4*)(wq + ((size_t)s * HW + q0) * KD);
    int idx = t;
    #pragma unroll
    for (int r = 0; r < 8; r++, idx += 256) {
      int q = idx >> 5, d4 = idx & 31;
      float4 v = src[idx];
      v.x *= TAU_INV; v.y *= TAU_INV; v.z *= TAU_INV; v.w *= TAU_INV;
      *(float4*)(Qs + q * 132 + d4 * 4) = v;
    }
  }
  if (t < 64) Ol[t] = 0.0f;
  {
    int idx = t;
    #pragma unroll
    for (int r = 0; r < 4; r++, idx += 256) Os[idx] = 0.0f;
  }
  int pvq = t >> 2, pve = (t & 3) * 4;

  for (int kt = 0; kt < NM / (KSPLIT * 128); kt++) {
    int kk0 = ksp * (NM / KSPLIT) + kt * 128;
    __syncthreads();
    {
      const float4* src = (const float4*)(wk + ((size_t)s * NM + kk0) * KD);
      int idx = t;
      #pragma unroll
      for (int r = 0; r < 16; r++, idx += 256) {
        int k = idx >> 5, d4 = idx & 31;
        *(float4*)(Ks + k * 132 + d4 * 4) = src[idx];
      }
    }
    {
      int f = kk0 >> 10, nn0 = kk0 & 1023;
      const float* pb = pe + ((size_t)(f * S4 + s)) * CE * HW + nn0;
      int idx = t;
      #pragma unroll
      for (int r = 0; r < 8; r++, idx += 256) {
        int e = idx >> 7, k = idx & 127;
        Vs[k * 16 + e] = pb[(size_t)e * HW + k];
      }
    }
    __syncthreads();
    // ---- scores: 4q x 8k per thread, f32x2 packed over d ----
    ull acc2[4][8] = {};
    #pragma unroll 4
    for (int d4 = 0; d4 < 32; d4++) {
      ulonglong2 b[8];
      #pragma unroll
      for (int jj = 0; jj < 8; jj++)
        b[jj] = *(const ulonglong2*)(Ks + (kgr * 8 + jj) * 132 + d4 * 4);
      #pragma unroll
      for (int i = 0; i < 4; i++) {
        ulonglong2 a = *(const ulonglong2*)(Qs + (qgr + 16 * i) * 132 + d4 * 4);
        #pragma unroll
        for (int jj = 0; jj < 8; jj++) {
          fma2(acc2[i][jj], a.x, b[jj].x);
          fma2(acc2[i][jj], a.y, b[jj].y);
        }
      }
    }
    // ---- exp(s - 30), write P, row-sum partials ----
    #pragma unroll
    for (int i = 0; i < 4; i++) {
      int row = qgr + 16 * i;
      float4 p0, p1;
      p0.x = __expf(red2(acc2[i][0]) - 30.0f);
      p0.y = __expf(red2(acc2[i][1]) - 30.0f);
      p0.z = __expf(red2(acc2[i][2]) - 30.0f);
      p0.w = __expf(red2(acc2[i][3]) - 30.0f);
      p1.x = __expf(red2(acc2[i][4]) - 30.0f);
      p1.y = __expf(red2(acc2[i][5]) - 30.0f);
      p1.z = __expf(red2(acc2[i][6]) - 30.0f);
      p1.w = __expf(red2(acc2[i][7]) - 30.0f);
      float psum = p0.x + p0.y + p0.z + p0.w + p1.x + p1.y + p1.z + p1.w;
      *(float4*)(Ps + row * 132 + kgr * 8) = p0;
      *(float4*)(Ps + row * 132 + kgr * 8 + 4) = p1;
      Pred[row * 17 + kgr] = psum;
    }
    __syncthreads();
    if (t < 64) {
      float sum = 0.0f;
      #pragma unroll
      for (int i = 0; i < 16; i++) sum += Pred[t * 17 + i];
      Ol[t] += sum;
    }
    // ---- PV: thread = (q, 4 e's), f32x2 ----
    {
      ulonglong2 o = *(ulonglong2*)(Os + pvq * 16 + pve);
      const float* prow = Ps + pvq * 132;
      #pragma unroll 8
      for (int k = 0; k < 128; k++) {
        ull pp = dup2(prow[k]);
        ulonglong2 v = *(const ulonglong2*)(Vs + k * 16 + pve);
        fma2(o.x, pp, v.x);
        fma2(o.y, pp, v.y);
      }
      *(ulonglong2*)(Os + pvq * 16 + pve) = o;
    }
  }
  __syncthreads();
  if (t < 64) {
    float* pp = part + ((size_t)((ksp * S4 + s) * HW) + q0 + t) * 18;
    #pragma unroll
    for (int e = 0; e < 16; e++) pp[e] = Os[t * 16 + e];
    pp[16] = Ol[t];
  }
}

// ================= merge split-K partials + sigmoid (plain sums) =================
__global__ __launch_bounds__(256) void merge_kernel(
    const float* __restrict__ part, float* __restrict__ out) {
  int g = blockIdx.x * 256 + threadIdx.x;   // (s,n) x 4 e-groups
  int eg = (g & 3) * 4;
  int sn = g >> 2;
  int n = sn & 1023, s = sn >> 10;
  float L = 0.0f;
  float O[4] = {};
  #pragma unroll
  for (int z = 0; z < KSPLIT; z++) {
    const float* pp = part + ((size_t)((z * S4 + s) * HW) + n) * 18;
    L += pp[16];
    #pragma unroll
    for (int e = 0; e < 4; e++) O[e] += pp[eg + e];
  }
  float inv = 1.0f / L;
  #pragma unroll
  for (int e = 0; e < 4; e++) {
    float v = O[e] * inv;
    out[(size_t)(s * CE + eg + e) * HW + n] = 1.0f / (1.0f + __expf(-v));
  }
}

// ================= host =================
extern "C" void kernel_launch(void* const* d_in, const int* in_sizes, int n_in,
                              void* d_out, int out_size) {
  const float* tgt = (const float*)d_in[0];
  const float* mem = (const float*)d_in[1];
  const float* pe  = (const float*)d_in[2];
  const float* wks = (const float*)d_in[3];
  const float* bks = (const float*)d_in[4];
  const float* wkc = (const float*)d_in[5];
  const float* bkc = (const float*)d_in[6];
  float* out = (float*)d_out;

  float *p_wq_self, *p_sc, *p_t, *p_wq_cross, *p_wk_cross, *p_part;
  cudaGetSymbolAddress((void**)&p_wq_self, g_wq_self);
  cudaGetSymbolAddress((void**)&p_sc, g_sc);
  cudaGetSymbolAddress((void**)&p_t, g_t);
  cudaGetSymbolAddress((void**)&p_wq_cross, g_wq_cross);
  cudaGetSymbolAddress((void**)&p_wk_cross, g_wk_cross);
  cudaGetSymbolAddress((void**)&p_part, g_part);

  // self-attention
  proj_kernel<<<dim3(16, 4), 256>>>(tgt, wks, bks, p_wq_self, HW);
  self_scores_kernel<<<dim3(16, 16, 4), 256>>>(p_wq_self, p_sc);
  softmax_kernel<<<4096, 256>>>(p_sc);
  pv_self_kernel<<<dim3(8, 8, 4), 256>>>(p_sc, tgt, p_t);
  instnorm_kernel<<<2048, 256>>>(p_t);

  // cross-attention projections
  proj_kernel<<<dim3(16, 4), 256>>>(p_t, wkc, bkc, p_wq_cross, HW);
  proj_kernel<<<dim3(256, 4), 256>>>(mem, wkc, bkc, p_wk_cross, NM);

  // flash cross-attention with split-K=16
  const int smem_bytes = (64 * 132 + 128 * 132 + 64 * 132 + 128 * 16 +
                          64 * 16 + 64 + 64 * 17) * 4;
  cudaFuncSetAttribute(cross_attn_kernel,
                       cudaFuncAttributeMaxDynamicSharedMemorySize, smem_bytes);
  cross_attn_kernel<<<dim3(16, 4, KSPLIT), 256, smem_bytes>>>(p_wq_cross, p_wk_cross, pe, p_part);
  merge_kernel<<<64, 256>>>(p_part, out);
}

// round 8
// speedup vs baseline: 1.2346x; 1.2231x over previous
#include <cuda_runtime.h>
#include <cuda_bf16.h>
#include <math.h>
#include <stdint.h>

#define S4 4
#define CD 512
#define KD 128
#define HW 1024
#define NM 16384
#define CE 16
#define TAU_INV 30.0f
#define KSPLIT 16

// ---------------- scratch ----------------
__device__ float g_wq_self[S4 * HW * KD];
__device__ float g_sc[S4 * HW * HW];
__device__ float g_t[S4 * CD * HW];
__device__ float g_wq_cross[S4 * HW * KD];
__device__ __nv_bfloat16 g_wk_hi[S4 * NM * KD];
__device__ __nv_bfloat16 g_wk_lo[S4 * NM * KD];
__device__ float g_part[KSPLIT * S4 * HW * 18];

__device__ __forceinline__ void mma_bf16(float* c, uint32_t a0, uint32_t a1,
                                         uint32_t a2, uint32_t a3,
                                         uint32_t b0, uint32_t b1) {
  asm("mma.sync.aligned.m16n8k16.row.col.f32.bf16.bf16.f32 "
      "{%0,%1,%2,%3}, {%4,%5,%6,%7}, {%8,%9}, {%0,%1,%2,%3};"
      : "+f"(c[0]), "+f"(c[1]), "+f"(c[2]), "+f"(c[3])
      : "r"(a0), "r"(a1), "r"(a2), "r"(a3), "r"(b0), "r"(b1));
}

// ================= projection + L2 normalize =================
__global__ __launch_bounds__(256) void proj_kernel(
    const float* __restrict__ in, const float* __restrict__ W,
    const float* __restrict__ bias, float* __restrict__ out,
    __nv_bfloat16* __restrict__ out_hi, __nv_bfloat16* __restrict__ out_lo,
    int NT) {
  __shared__ float As[64 * 36];
  __shared__ float Ws[128 * 36];
  int s = blockIdx.y;
  int tg0 = blockIdx.x * 64;
  int f = tg0 >> 10;
  int n0 = tg0 & 1023;
  const float* inb = in + ((size_t)(f * S4 + s)) * CD * HW + n0;
  int t = threadIdx.x;
  int wid = t >> 5;
  int dgr = t & 31;
  float acc[8][4] = {};
  for (int c0 = 0; c0 < CD; c0 += 32) {
    int idx = t;
    #pragma unroll
    for (int r = 0; r < 8; r++, idx += 256) {
      int cc = idx >> 6, tok = idx & 63;
      As[tok * 36 + cc] = inb[(size_t)(c0 + cc) * HW + tok];
    }
    idx = t;
    #pragma unroll
    for (int r = 0; r < 16; r++, idx += 256) {
      int d = idx >> 5, cc = idx & 31;
      Ws[d * 36 + cc] = W[d * CD + c0 + cc];
    }
    __syncthreads();
    #pragma unroll
    for (int cc4 = 0; cc4 < 8; cc4++) {
      float4 b[4];
      #pragma unroll
      for (int j = 0; j < 4; j++)
        b[j] = *(const float4*)(Ws + (dgr + 32 * j) * 36 + cc4 * 4);
      #pragma unroll
      for (int i = 0; i < 8; i++) {
        float4 a = *(const float4*)(As + (wid * 8 + i) * 36 + cc4 * 4);
        #pragma unroll
        for (int j = 0; j < 4; j++) {
          acc[i][j] = fmaf(a.x, b[j].x, acc[i][j]);
          acc[i][j] = fmaf(a.y, b[j].y, acc[i][j]);
          acc[i][j] = fmaf(a.z, b[j].z, acc[i][j]);
          acc[i][j] = fmaf(a.w, b[j].w, acc[i][j]);
        }
      }
    }
    __syncthreads();
  }
  float bv[4];
  #pragma unroll
  for (int j = 0; j < 4; j++) bv[j] = bias[dgr + 32 * j];
  float ssp[8];
  #pragma unroll
  for (int i = 0; i < 8; i++) {
    float s0 = 0.0f;
    #pragma unroll
    for (int j = 0; j < 4; j++) {
      acc[i][j] += bv[j];
      s0 = fmaf(acc[i][j], acc[i][j], s0);
    }
    ssp[i] = s0;
  }
  #pragma unroll
  for (int o = 16; o; o >>= 1)
    #pragma unroll
    for (int i = 0; i < 8; i++)
      ssp[i] += __shfl_xor_sync(0xffffffffu, ssp[i], o);
  #pragma unroll
  for (int i = 0; i < 8; i++) {
    float scl = 1.0f / fmaxf(sqrtf(ssp[i]), 1e-12f);
    size_t rb = ((size_t)s * NT + tg0 + wid * 8 + i) * KD;
    #pragma unroll
    for (int j = 0; j < 4; j++) {
      float v = acc[i][j] * scl;
      if (out) out[rb + dgr + 32 * j] = v;
      if (out_hi) {
        __nv_bfloat16 h = __float2bfloat16(v);
        out_hi[rb + dgr + 32 * j] = h;
        out_lo[rb + dgr + 32 * j] = __float2bfloat16(v - __bfloat162float(h));
      }
    }
  }
}

// ================= self-attention raw scores =================
__global__ __launch_bounds__(256) void self_scores_kernel(
    const float* __restrict__ wq, float* __restrict__ sc) {
  __shared__ float QK[2][64][65];
  int s = blockIdx.z;
  int q0 = blockIdx.x * 64, k0 = blockIdx.y * 64;
  const float* base = wq + (size_t)s * HW * KD;
  int t = threadIdx.x;
  int qg = t & 15, kg = t >> 4;
  float acc[4][4] = {};
  for (int d0 = 0; d0 < KD; d0 += 64) {
    int idx = t;
    #pragma unroll
    for (int r = 0; r < 16; r++, idx += 256) {
      int row = idx >> 6, dd = idx & 63;
      QK[0][row][dd] = base[(size_t)(q0 + row) * KD + d0 + dd];
      QK[1][row][dd] = base[(size_t)(k0 + row) * KD + d0 + dd];
    }
    __syncthreads();
    #pragma unroll 8
    for (int k = 0; k < 64; k++) {
      float a[4], b[4];
      #pragma unroll
      for (int i = 0; i < 4; i++) a[i] = QK[0][qg * 4 + i][k];
      #pragma unroll
      for (int j = 0; j < 4; j++) b[j] = QK[1][kg * 4 + j][k];
      #pragma unroll
      for (int i = 0; i < 4; i++)
        #pragma unroll
        for (int j = 0; j < 4; j++)
          acc[i][j] = fmaf(a[i], b[j], acc[i][j]);
    }
    __syncthreads();
  }
  float* Cs = &QK[0][0][0];
  #pragma unroll
  for (int i = 0; i < 4; i++)
    #pragma unroll
    for (int j = 0; j < 4; j++)
      Cs[(qg * 4 + i) * 65 + kg * 4 + j] = acc[i][j] * TAU_INV;
  __syncthreads();
  int idx = t;
  #pragma unroll
  for (int r = 0; r < 16; r++, idx += 256) {
    int row = idx >> 6, col = idx & 63;
    sc[((size_t)s * HW + q0 + row) * HW + k0 + col] = Cs[row * 65 + col];
  }
}

// ================= row softmax, static max = 30 =================
__global__ __launch_bounds__(256) void softmax_kernel(float* __restrict__ sc) {
  __shared__ float reds[8];
  float* p = sc + (size_t)blockIdx.x * HW;
  int t = threadIdx.x, lane = t & 31, warp = t >> 5;
  float v0 = __expf(p[t] - 30.0f),       v1 = __expf(p[t + 256] - 30.0f);
  float v2 = __expf(p[t + 512] - 30.0f), v3 = __expf(p[t + 768] - 30.0f);
  float sum = v0 + v1 + v2 + v3;
  #pragma unroll
  for (int o = 16; o; o >>= 1) sum += __shfl_xor_sync(0xffffffffu, sum, o);
  if (lane == 0) reds[warp] = sum;
  __syncthreads();
  float tot = reds[0];
  #pragma unroll
  for (int i = 1; i < 8; i++) tot += reds[i];
  float inv = 1.0f / tot;
  p[t] = v0 * inv; p[t + 256] = v1 * inv;
  p[t + 512] = v2 * inv; p[t + 768] = v3 * inv;
}

// ================= self P.V + residual =================
__global__ __launch_bounds__(256) void pv_self_kernel(
    const float* __restrict__ sc, const float* __restrict__ tgt,
    float* __restrict__ tout) {
  __shared__ float As[128 * 36];
  __shared__ float Bs[64 * 36];
  int s = blockIdx.z;
  int n0 = blockIdx.x * 128, c0 = blockIdx.y * 64;
  const float* P = sc + (size_t)s * HW * HW;
  const float* V = tgt + (size_t)s * CD * HW;
  int t = threadIdx.x;
  int cgr = t & 15;
  int ngr = t >> 4;
  float acc[8][4] = {};
  for (int m0 = 0; m0 < HW; m0 += 32) {
    int idx = t;
    #pragma unroll
    for (int r = 0; r < 16; r++, idx += 256) {
      int n = idx >> 5, m = idx & 31;
      As[n * 36 + m] = P[(size_t)(n0 + n) * HW + m0 + m];
    }
    idx = t;
    #pragma unroll
    for (int r = 0; r < 8; r++, idx += 256) {
      int c = idx >> 5, m = idx & 31;
      Bs[c * 36 + m] = V[(size_t)(c0 + c) * HW + m0 + m];
    }
    __syncthreads();
    #pragma unroll
    for (int m4 = 0; m4 < 8; m4++) {
      float4 b[4];
      #pragma unroll
      for (int j = 0; j < 4; j++)
        b[j] = *(const float4*)(Bs + (cgr + 16 * j) * 36 + m4 * 4);
      #pragma unroll
      for (int i = 0; i < 8; i++) {
        float4 a = *(const float4*)(As + (ngr * 8 + i) * 36 + m4 * 4);
        #pragma unroll
        for (int j = 0; j < 4; j++) {
          acc[i][j] = fmaf(a.x, b[j].x, acc[i][j]);
          acc[i][j] = fmaf(a.y, b[j].y, acc[i][j]);
          acc[i][j] = fmaf(a.z, b[j].z, acc[i][j]);
          acc[i][j] = fmaf(a.w, b[j].w, acc[i][j]);
        }
      }
    }
    __syncthreads();
  }
  #pragma unroll
  for (int j = 0; j < 4; j++) {
    int c = c0 + cgr + 16 * j;
    size_t g = (size_t)(s * CD + c) * HW + n0 + ngr * 8;
    #pragma unroll
    for (int i4 = 0; i4 < 8; i4 += 4) {
      float4 tg4 = *(const float4*)(tgt + g + i4);
      tg4.x += acc[i4 + 0][j]; tg4.y += acc[i4 + 1][j];
      tg4.z += acc[i4 + 2][j]; tg4.w += acc[i4 + 3][j];
      *(float4*)(tout + g + i4) = tg4;
    }
  }
}

// ================= instance norm =================
__global__ __launch_bounds__(256) void instnorm_kernel(float* __restrict__ x) {
  __shared__ float redS[8];
  __shared__ float redQ[8];
  float* p = x + (size_t)blockIdx.x * HW;
  int t = threadIdx.x, lane = t & 31, warp = t >> 5;
  float v0 = p[t], v1 = p[t + 256], v2 = p[t + 512], v3 = p[t + 768];
  float sum = v0 + v1 + v2 + v3;
  float sq = v0 * v0 + v1 * v1 + v2 * v2 + v3 * v3;
  #pragma unroll
  for (int o = 16; o; o >>= 1) {
    sum += __shfl_xor_sync(0xffffffffu, sum, o);
    sq  += __shfl_xor_sync(0xffffffffu, sq, o);
  }
  if (lane == 0) { redS[warp] = sum; redQ[warp] = sq; }
  __syncthreads();
  sum = redS[0]; sq = redQ[0];
  #pragma unroll
  for (int i = 1; i < 8; i++) { sum += redS[i]; sq += redQ[i]; }
  float mean = sum * (1.0f / HW);
  float var = sq * (1.0f / HW) - mean * mean;
  float rstd = rsqrtf(var + 1e-5f);
  p[t]       = (v0 - mean) * rstd;
  p[t + 256] = (v1 - mean) * rstd;
  p[t + 512] = (v2 - mean) * rstd;
  p[t + 768] = (v3 - mean) * rstd;
}

// ================= cross attention: HMMA split-bf16 scores =================
// smem byte offsets
#define QSTR 136
#define PSTR 132
#define OFF_QH 0
#define OFF_QL 17408
#define OFF_KH 34816
#define OFF_KL 69632
#define OFF_PS 104448
#define OFF_VS 138240
#define OFF_OL 146432
#define OFF_PR 146688
#define SMEM_CROSS 147712

__global__ __launch_bounds__(256, 1) void cross_attn_kernel(
    const float* __restrict__ wq,
    const __nv_bfloat16* __restrict__ khi, const __nv_bfloat16* __restrict__ klo,
    const float* __restrict__ pe, float* __restrict__ part) {
  extern __shared__ char smc[];
  __nv_bfloat16* Qh = (__nv_bfloat16*)(smc + OFF_QH);
  __nv_bfloat16* Ql = (__nv_bfloat16*)(smc + OFF_QL);
  __nv_bfloat16* Kh = (__nv_bfloat16*)(smc + OFF_KH);
  __nv_bfloat16* Kl = (__nv_bfloat16*)(smc + OFF_KL);
  float* Ps   = (float*)(smc + OFF_PS);
  float* Vs   = (float*)(smc + OFF_VS);
  float* Ol   = (float*)(smc + OFF_OL);
  float* Pred = (float*)(smc + OFF_PR);
  int qt = blockIdx.x, s = blockIdx.y, ksp = blockIdx.z;
  int q0 = qt * 64;
  int t = threadIdx.x;
  int w = t >> 5, lane = t & 31;
  int lr = lane >> 2, lc = lane & 3;

  // ---- Q: load f32, scale by TAU_INV, split into bf16 hi/lo ----
  {
    const float4* src = (const float4*)(wq + ((size_t)s * HW + q0) * KD);
    #pragma unroll
    for (int r = 0; r < 8; r++) {
      int idx = t + r * 256;
      int q = idx >> 5, d4 = (idx & 31) * 4;
      float4 v = src[idx];
      v.x *= TAU_INV; v.y *= TAU_INV; v.z *= TAU_INV; v.w *= TAU_INV;
      __nv_bfloat16 h0 = __float2bfloat16(v.x), h1 = __float2bfloat16(v.y);
      __nv_bfloat16 h2 = __float2bfloat16(v.z), h3 = __float2bfloat16(v.w);
      __nv_bfloat16 l0 = __float2bfloat16(v.x - __bfloat162float(h0));
      __nv_bfloat16 l1 = __float2bfloat16(v.y - __bfloat162float(h1));
      __nv_bfloat16 l2 = __float2bfloat16(v.z - __bfloat162float(h2));
      __nv_bfloat16 l3 = __float2bfloat16(v.w - __bfloat162float(h3));
      uint2 uh, ul;
      uh.x = (uint32_t)__bfloat16_as_ushort(h0) | ((uint32_t)__bfloat16_as_ushort(h1) << 16);
      uh.y = (uint32_t)__bfloat16_as_ushort(h2) | ((uint32_t)__bfloat16_as_ushort(h3) << 16);
      ul.x = (uint32_t)__bfloat16_as_ushort(l0) | ((uint32_t)__bfloat16_as_ushort(l1) << 16);
      ul.y = (uint32_t)__bfloat16_as_ushort(l2) | ((uint32_t)__bfloat16_as_ushort(l3) << 16);
      *(uint2*)(Qh + q * QSTR + d4) = uh;
      *(uint2*)(Ql + q * QSTR + d4) = ul;
    }
  }
  if (t < 64) Ol[t] = 0.0f;

  // score-warp tile bases
  int mq = (w & 3) * 16;   // 16 q rows
  int kb = (w >> 2) * 64;  // 64 k cols
  // PV mapping (register accumulator across all tiles)
  int pq = t >> 2, pve = (t & 3) * 4;
  float4 o = make_float4(0.f, 0.f, 0.f, 0.f);

  for (int kt = 0; kt < NM / (KSPLIT * 128); kt++) {
    int kk0 = ksp * (NM / KSPLIT) + kt * 128;
    __syncthreads();   // prev consumers of Kh/Kl/Vs/Ps done
    // ---- K hi/lo tiles (uint4 = 8 bf16) ----
    {
      const uint4* gh = (const uint4*)(khi + ((size_t)s * NM + kk0) * KD);
      const uint4* gl = (const uint4*)(klo + ((size_t)s * NM + kk0) * KD);
      #pragma unroll
      for (int r = 0; r < 8; r++) {
        int idx = t + r * 256;
        int key = idx >> 4, d8 = (idx & 15) * 8;
        *(uint4*)(Kh + key * QSTR + d8) = gh[idx];
        *(uint4*)(Kl + key * QSTR + d8) = gl[idx];
      }
    }
    // ---- V tile ----
    {
      int f = kk0 >> 10, nn0 = kk0 & 1023;
      const float* pb = pe + ((size_t)(f * S4 + s)) * CE * HW + nn0;
      #pragma unroll
      for (int r = 0; r < 8; r++) {
        int idx = t + r * 256;
        int e = idx >> 7, k = idx & 127;
        Vs[k * 16 + e] = pb[(size_t)e * HW + k];
      }
    }
    __syncthreads();
    // ---- scores via HMMA: 3 passes (qh*kh, ql*kh, qh*kl) ----
    float c[8][4];
    #pragma unroll
    for (int nt = 0; nt < 8; nt++)
      #pragma unroll
      for (int j = 0; j < 4; j++) c[nt][j] = 0.0f;
    const __nv_bfloat16* Ap[3] = {Qh, Ql, Qh};
    const __nv_bfloat16* Bp[3] = {Kh, Kh, Kl};
    #pragma unroll
    for (int pass = 0; pass < 3; pass++) {
      const __nv_bfloat16* A = Ap[pass];
      const __nv_bfloat16* B = Bp[pass];
      #pragma unroll
      for (int ds = 0; ds < 8; ds++) {
        int d0 = ds * 16 + lc * 2;
        uint32_t a0 = *(const uint32_t*)(A + (mq + lr) * QSTR + d0);
        uint32_t a1 = *(const uint32_t*)(A + (mq + 8 + lr) * QSTR + d0);
        uint32_t a2 = *(const uint32_t*)(A + (mq + lr) * QSTR + d0 + 8);
        uint32_t a3 = *(const uint32_t*)(A + (mq + 8 + lr) * QSTR + d0 + 8);
        #pragma unroll
        for (int nt = 0; nt < 8; nt++) {
          const __nv_bfloat16* br = B + (kb + nt * 8 + lr) * QSTR + d0;
          uint32_t b0 = *(const uint32_t*)(br);
          uint32_t b1 = *(const uint32_t*)(br + 8);
          mma_bf16(c[nt], a0, a1, a2, a3, b0, b1);
        }
      }
    }
    // ---- exp(s-30), write Ps, row-sum partials ----
    float sl = 0.0f, sh = 0.0f;
    #pragma unroll
    for (int nt = 0; nt < 8; nt++) {
      float e0 = __expf(c[nt][0] - 30.0f);
      float e1 = __expf(c[nt][1] - 30.0f);
      float e2 = __expf(c[nt][2] - 30.0f);
      float e3 = __expf(c[nt][3] - 30.0f);
      int col = kb + nt * 8 + lc * 2;
      *(float2*)(Ps + (mq + lr) * PSTR + col)     = make_float2(e0, e1);
      *(float2*)(Ps + (mq + 8 + lr) * PSTR + col) = make_float2(e2, e3);
      sl += e0 + e1; sh += e2 + e3;
    }
    sl += __shfl_xor_sync(0xffffffffu, sl, 1);
    sl += __shfl_xor_sync(0xffffffffu, sl, 2);
    sh += __shfl_xor_sync(0xffffffffu, sh, 1);
    sh += __shfl_xor_sync(0xffffffffu, sh, 2);
    if (lc == 0) {
      Pred[(mq + lr) * 4 + (w >> 2)]     = sl;
      Pred[(mq + 8 + lr) * 4 + (w >> 2)] = sh;
    }
    __syncthreads();
    if (t < 64) Ol[t] += Pred[t * 4] + Pred[t * 4 + 1];
    // ---- PV: thread = (q, 4 e's), full 128-k loop ----
    {
      const float* prow = Ps + pq * PSTR;
      const float* vb = Vs + pve;
      #pragma unroll 8
      for (int k = 0; k < 128; k++) {
        float p = prow[k];
        float4 v = *(const float4*)(vb + k * 16);
        o.x = fmaf(p, v.x, o.x); o.y = fmaf(p, v.y, o.y);
        o.z = fmaf(p, v.z, o.z); o.w = fmaf(p, v.w, o.w);
      }
    }
  }
  __syncthreads();
  {
    float* pp = part + ((size_t)((ksp * S4 + s) * HW) + q0 + pq) * 18;
    pp[pve + 0] = o.x; pp[pve + 1] = o.y;
    pp[pve + 2] = o.z; pp[pve + 3] = o.w;
    if ((t & 3) == 0) pp[16] = Ol[pq];
  }
}

// ================= merge split-K partials + sigmoid =================
__global__ __launch_bounds__(256) void merge_kernel(
    const float* __restrict__ part, float* __restrict__ out) {
  int g = blockIdx.x * 256 + threadIdx.x;
  int eg = (g & 3) * 4;
  int sn = g >> 2;
  int n = sn & 1023, s = sn >> 10;
  float L = 0.0f;
  float O[4] = {};
  #pragma unroll
  for (int z = 0; z < KSPLIT; z++) {
    const float* pp = part + ((size_t)((z * S4 + s) * HW) + n) * 18;
    L += pp[16];
    #pragma unroll
    for (int e = 0; e < 4; e++) O[e] += pp[eg + e];
  }
  float inv = 1.0f / L;
  #pragma unroll
  for (int e = 0; e < 4; e++) {
    float v = O[e] * inv;
    out[(size_t)(s * CE + eg + e) * HW + n] = 1.0f / (1.0f + __expf(-v));
  }
}

// ================= host =================
extern "C" void kernel_launch(void* const* d_in, const int* in_sizes, int n_in,
                              void* d_out, int out_size) {
  const float* tgt = (const float*)d_in[0];
  const float* mem = (const float*)d_in[1];
  const float* pe  = (const float*)d_in[2];
  const float* wks = (const float*)d_in[3];
  const float* bks = (const float*)d_in[4];
  const float* wkc = (const float*)d_in[5];
  const float* bkc = (const float*)d_in[6];
  float* out = (float*)d_out;

  float *p_wq_self, *p_sc, *p_t, *p_wq_cross, *p_part;
  __nv_bfloat16 *p_wk_hi, *p_wk_lo;
  cudaGetSymbolAddress((void**)&p_wq_self, g_wq_self);
  cudaGetSymbolAddress((void**)&p_sc, g_sc);
  cudaGetSymbolAddress((void**)&p_t, g_t);
  cudaGetSymbolAddress((void**)&p_wq_cross, g_wq_cross);
  cudaGetSymbolAddress((void**)&p_wk_hi, g_wk_hi);
  cudaGetSymbolAddress((void**)&p_wk_lo, g_wk_lo);
  cudaGetSymbolAddress((void**)&p_part, g_part);

  // self-attention
  proj_kernel<<<dim3(16, 4), 256>>>(tgt, wks, bks, p_wq_self, nullptr, nullptr, HW);
  self_scores_kernel<<<dim3(16, 16, 4), 256>>>(p_wq_self, p_sc);
  softmax_kernel<<<4096, 256>>>(p_sc);
  pv_self_kernel<<<dim3(8, 8, 4), 256>>>(p_sc, tgt, p_t);
  instnorm_kernel<<<2048, 256>>>(p_t);

  // cross projections: Q as f32, memory K as bf16 hi/lo
  proj_kernel<<<dim3(16, 4), 256>>>(p_t, wkc, bkc, p_wq_cross, nullptr, nullptr, HW);
  proj_kernel<<<dim3(256, 4), 256>>>(mem, wkc, bkc, nullptr, p_wk_hi, p_wk_lo, NM);

  // HMMA cross-attention
  cudaFuncSetAttribute(cross_attn_kernel,
                       cudaFuncAttributeMaxDynamicSharedMemorySize, SMEM_CROSS);
  cross_attn_kernel<<<dim3(16, 4, KSPLIT), 256, SMEM_CROSS>>>(
      p_wq_cross, p_wk_hi, p_wk_lo, pe, p_part);
  merge_kernel<<<64, 256>>>(p_part, out);
}

// round 9
// speedup vs baseline: 1.4031x; 1.1364x over previous
#include <cuda_runtime.h>
#include <cuda_bf16.h>
#include <math.h>
#include <stdint.h>

#define S4 4
#define CD 512
#define KD 128
#define HW 1024
#define NM 16384
#define CE 16
#define TAU_INV 30.0f
#define KSPLIT 16

// ---------------- scratch ----------------
__device__ float g_wq_self[S4 * HW * KD];
__device__ float g_sc[S4 * HW * HW];
__device__ float g_t[S4 * CD * HW];
__device__ float g_wq_cross[S4 * HW * KD];
__device__ __nv_bfloat16 g_wk_hi[S4 * NM * KD];
__device__ __nv_bfloat16 g_wk_lo[S4 * NM * KD];
__device__ float g_part[KSPLIT * S4 * HW * 18];

__device__ __forceinline__ void mma_bf16(float* c, uint32_t a0, uint32_t a1,
                                         uint32_t a2, uint32_t a3,
                                         uint32_t b0, uint32_t b1) {
  asm("mma.sync.aligned.m16n8k16.row.col.f32.bf16.bf16.f32 "
      "{%0,%1,%2,%3}, {%4,%5,%6,%7}, {%8,%9}, {%0,%1,%2,%3};"
      : "+f"(c[0]), "+f"(c[1]), "+f"(c[2]), "+f"(c[3])
      : "r"(a0), "r"(a1), "r"(a2), "r"(a3), "r"(b0), "r"(b1));
}
__device__ __forceinline__ uint32_t pack_split(float v, uint32_t& lo_out_shift,
                                               int hi) { return 0; }

// ================= projection + L2 normalize (fp32, for HW-sized inputs) =================
__global__ __launch_bounds__(256) void proj_kernel(
    const float* __restrict__ in, const float* __restrict__ W,
    const float* __restrict__ bias, float* __restrict__ out, int NT) {
  __shared__ float As[64 * 36];
  __shared__ float Ws[128 * 36];
  int s = blockIdx.y;
  int tg0 = blockIdx.x * 64;
  int f = tg0 >> 10;
  int n0 = tg0 & 1023;
  const float* inb = in + ((size_t)(f * S4 + s)) * CD * HW + n0;
  int t = threadIdx.x;
  int wid = t >> 5;
  int dgr = t & 31;
  float acc[8][4] = {};
  for (int c0 = 0; c0 < CD; c0 += 32) {
    int idx = t;
    #pragma unroll
    for (int r = 0; r < 8; r++, idx += 256) {
      int cc = idx >> 6, tok = idx & 63;
      As[tok * 36 + cc] = inb[(size_t)(c0 + cc) * HW + tok];
    }
    idx = t;
    #pragma unroll
    for (int r = 0; r < 16; r++, idx += 256) {
      int d = idx >> 5, cc = idx & 31;
      Ws[d * 36 + cc] = W[d * CD + c0 + cc];
    }
    __syncthreads();
    #pragma unroll
    for (int cc4 = 0; cc4 < 8; cc4++) {
      float4 b[4];
      #pragma unroll
      for (int j = 0; j < 4; j++)
        b[j] = *(const float4*)(Ws + (dgr + 32 * j) * 36 + cc4 * 4);
      #pragma unroll
      for (int i = 0; i < 8; i++) {
        float4 a = *(const float4*)(As + (wid * 8 + i) * 36 + cc4 * 4);
        #pragma unroll
        for (int j = 0; j < 4; j++) {
          acc[i][j] = fmaf(a.x, b[j].x, acc[i][j]);
          acc[i][j] = fmaf(a.y, b[j].y, acc[i][j]);
          acc[i][j] = fmaf(a.z, b[j].z, acc[i][j]);
          acc[i][j] = fmaf(a.w, b[j].w, acc[i][j]);
        }
      }
    }
    __syncthreads();
  }
  float bv[4];
  #pragma unroll
  for (int j = 0; j < 4; j++) bv[j] = bias[dgr + 32 * j];
  float ssp[8];
  #pragma unroll
  for (int i = 0; i < 8; i++) {
    float s0 = 0.0f;
    #pragma unroll
    for (int j = 0; j < 4; j++) {
      acc[i][j] += bv[j];
      s0 = fmaf(acc[i][j], acc[i][j], s0);
    }
    ssp[i] = s0;
  }
  #pragma unroll
  for (int o = 16; o; o >>= 1)
    #pragma unroll
    for (int i = 0; i < 8; i++)
      ssp[i] += __shfl_xor_sync(0xffffffffu, ssp[i], o);
  #pragma unroll
  for (int i = 0; i < 8; i++) {
    float scl = 1.0f / fmaxf(sqrtf(ssp[i]), 1e-12f);
    float* ob = out + ((size_t)s * NT + tg0 + wid * 8 + i) * KD;
    #pragma unroll
    for (int j = 0; j < 4; j++)
      ob[dgr + 32 * j] = acc[i][j] * scl;
  }
}

// ================= HMMA projection + L2 normalize -> bf16 hi/lo =================
// 64 tokens x 128 d per block; 8 warps = (4 q-tiles x 2 d-halves); K-chunks of 64 c.
#define PASTR 72
#define POFF_AH 0
#define POFF_AL 9216
#define POFF_BH 18432
#define POFF_BL 36864
#define POFF_RED 55296
#define SMEM_PROJ 55808

__global__ __launch_bounds__(256, 1) void proj_mma_kernel(
    const float* __restrict__ in, const float* __restrict__ W,
    const float* __restrict__ bias,
    __nv_bfloat16* __restrict__ out_hi, __nv_bfloat16* __restrict__ out_lo,
    int NT) {
  extern __shared__ char smp[];
  __nv_bfloat16* Ah = (__nv_bfloat16*)(smp + POFF_AH);
  __nv_bfloat16* Al = (__nv_bfloat16*)(smp + POFF_AL);
  __nv_bfloat16* Bh = (__nv_bfloat16*)(smp + POFF_BH);
  __nv_bfloat16* Bl = (__nv_bfloat16*)(smp + POFF_BL);
  float* red = (float*)(smp + POFF_RED);   // [64][2]
  int s = blockIdx.y;
  int tg0 = blockIdx.x * 64;
  int f = tg0 >> 10;
  int n0 = tg0 & 1023;
  const float* inb = in + ((size_t)(f * S4 + s)) * CD * HW + n0;
  int t = threadIdx.x;
  int w = t >> 5, lane = t & 31;
  int lr = lane >> 2, lc = lane & 3;
  int mq = (w & 3) * 16;     // 16 token rows
  int db = (w >> 2) * 64;    // 64 d cols
  float c[8][4];
  #pragma unroll
  for (int nt = 0; nt < 8; nt++)
    #pragma unroll
    for (int j = 0; j < 4; j++) c[nt][j] = 0.0f;

  for (int c0 = 0; c0 < CD; c0 += 64) {
    __syncthreads();
    // A chunk: 64 tok x 64 c, split bf16
    #pragma unroll
    for (int r = 0; r < 16; r++) {
      int idx = t + r * 256;
      int tok = idx & 63, cc = idx >> 6;
      float v = inb[(size_t)(c0 + cc) * HW + tok];
      __nv_bfloat16 h = __float2bfloat16(v);
      Ah[tok * PASTR + cc] = h;
      Al[tok * PASTR + cc] = __float2bfloat16(v - __bfloat162float(h));
    }
    // B chunk: 128 d x 64 c, split bf16
    #pragma unroll
    for (int r = 0; r < 32; r++) {
      int idx = t + r * 256;
      int cc = idx & 63, d = idx >> 6;
      float v = W[d * CD + c0 + cc];
      __nv_bfloat16 h = __float2bfloat16(v);
      Bh[d * PASTR + cc] = h;
      Bl[d * PASTR + cc] = __float2bfloat16(v - __bfloat162float(h));
    }
    __syncthreads();
    const __nv_bfloat16* Ap[3] = {Ah, Al, Ah};
    const __nv_bfloat16* Bp[3] = {Bh, Bh, Bl};
    #pragma unroll
    for (int pass = 0; pass < 3; pass++) {
      const __nv_bfloat16* A = Ap[pass];
      const __nv_bfloat16* B = Bp[pass];
      #pragma unroll
      for (int ds = 0; ds < 4; ds++) {
        int d0 = ds * 16 + lc * 2;
        uint32_t a0 = *(const uint32_t*)(A + (mq + lr) * PASTR + d0);
        uint32_t a1 = *(const uint32_t*)(A + (mq + 8 + lr) * PASTR + d0);
        uint32_t a2 = *(const uint32_t*)(A + (mq + lr) * PASTR + d0 + 8);
        uint32_t a3 = *(const uint32_t*)(A + (mq + 8 + lr) * PASTR + d0 + 8);
        #pragma unroll
        for (int nt = 0; nt < 8; nt++) {
          const __nv_bfloat16* br = B + (db + nt * 8 + lr) * PASTR + d0;
          uint32_t b0 = *(const uint32_t*)(br);
          uint32_t b1 = *(const uint32_t*)(br + 8);
          mma_bf16(c[nt], a0, a1, a2, a3, b0, b1);
        }
      }
    }
  }
  // bias + sum-of-squares partials
  float ssl = 0.0f, ssh = 0.0f;
  #pragma unroll
  for (int nt = 0; nt < 8; nt++) {
    int d = db + nt * 8 + lc * 2;
    float b0 = bias[d], b1 = bias[d + 1];
    c[nt][0] += b0; c[nt][1] += b1;
    c[nt][2] += b0; c[nt][3] += b1;
    ssl = fmaf(c[nt][0], c[nt][0], fmaf(c[nt][1], c[nt][1], ssl));
    ssh = fmaf(c[nt][2], c[nt][2], fmaf(c[nt][3], c[nt][3], ssh));
  }
  ssl += __shfl_xor_sync(0xffffffffu, ssl, 1);
  ssl += __shfl_xor_sync(0xffffffffu, ssl, 2);
  ssh += __shfl_xor_sync(0xffffffffu, ssh, 1);
  ssh += __shfl_xor_sync(0xffffffffu, ssh, 2);
  __syncthreads();
  if (lc == 0) {
    red[(mq + lr) * 2 + (w >> 2)]     = ssl;
    red[(mq + 8 + lr) * 2 + (w >> 2)] = ssh;
  }
  __syncthreads();
  float sl = 1.0f / fmaxf(sqrtf(red[(mq + lr) * 2] + red[(mq + lr) * 2 + 1]), 1e-12f);
  float sh = 1.0f / fmaxf(sqrtf(red[(mq + 8 + lr) * 2] + red[(mq + 8 + lr) * 2 + 1]), 1e-12f);
  size_t rb0 = ((size_t)s * NT + tg0 + mq + lr) * KD;
  size_t rb1 = ((size_t)s * NT + tg0 + mq + 8 + lr) * KD;
  #pragma unroll
  for (int nt = 0; nt < 8; nt++) {
    int d = db + nt * 8 + lc * 2;
    float v0 = c[nt][0] * sl, v1 = c[nt][1] * sl;
    float v2 = c[nt][2] * sh, v3 = c[nt][3] * sh;
    __nv_bfloat16 h0 = __float2bfloat16(v0), h1 = __float2bfloat16(v1);
    __nv_bfloat16 h2 = __float2bfloat16(v2), h3 = __float2bfloat16(v3);
    uint32_t uh0 = (uint32_t)__bfloat16_as_ushort(h0) | ((uint32_t)__bfloat16_as_ushort(h1) << 16);
    uint32_t uh1 = (uint32_t)__bfloat16_as_ushort(h2) | ((uint32_t)__bfloat16_as_ushort(h3) << 16);
    __nv_bfloat16 l0 = __float2bfloat16(v0 - __bfloat162float(h0));
    __nv_bfloat16 l1 = __float2bfloat16(v1 - __bfloat162float(h1));
    __nv_bfloat16 l2 = __float2bfloat16(v2 - __bfloat162float(h2));
    __nv_bfloat16 l3 = __float2bfloat16(v3 - __bfloat162float(h3));
    uint32_t ul0 = (uint32_t)__bfloat16_as_ushort(l0) | ((uint32_t)__bfloat16_as_ushort(l1) << 16);
    uint32_t ul1 = (uint32_t)__bfloat16_as_ushort(l2) | ((uint32_t)__bfloat16_as_ushort(l3) << 16);
    *(uint32_t*)(out_hi + rb0 + d) = uh0;
    *(uint32_t*)(out_hi + rb1 + d) = uh1;
    *(uint32_t*)(out_lo + rb0 + d) = ul0;
    *(uint32_t*)(out_lo + rb1 + d) = ul1;
  }
}

// ================= self-attention raw scores =================
__global__ __launch_bounds__(256) void self_scores_kernel(
    const float* __restrict__ wq, float* __restrict__ sc) {
  __shared__ float QK[2][64][65];
  int s = blockIdx.z;
  int q0 = blockIdx.x * 64, k0 = blockIdx.y * 64;
  const float* base = wq + (size_t)s * HW * KD;
  int t = threadIdx.x;
  int qg = t & 15, kg = t >> 4;
  float acc[4][4] = {};
  for (int d0 = 0; d0 < KD; d0 += 64) {
    int idx = t;
    #pragma unroll
    for (int r = 0; r < 16; r++, idx += 256) {
      int row = idx >> 6, dd = idx & 63;
      QK[0][row][dd] = base[(size_t)(q0 + row) * KD + d0 + dd];
      QK[1][row][dd] = base[(size_t)(k0 + row) * KD + d0 + dd];
    }
    __syncthreads();
    #pragma unroll 8
    for (int k = 0; k < 64; k++) {
      float a[4], b[4];
      #pragma unroll
      for (int i = 0; i < 4; i++) a[i] = QK[0][qg * 4 + i][k];
      #pragma unroll
      for (int j = 0; j < 4; j++) b[j] = QK[1][kg * 4 + j][k];
      #pragma unroll
      for (int i = 0; i < 4; i++)
        #pragma unroll
        for (int j = 0; j < 4; j++)
          acc[i][j] = fmaf(a[i], b[j], acc[i][j]);
    }
    __syncthreads();
  }
  float* Cs = &QK[0][0][0];
  #pragma unroll
  for (int i = 0; i < 4; i++)
    #pragma unroll
    for (int j = 0; j < 4; j++)
      Cs[(qg * 4 + i) * 65 + kg * 4 + j] = acc[i][j] * TAU_INV;
  __syncthreads();
  int idx = t;
  #pragma unroll
  for (int r = 0; r < 16; r++, idx += 256) {
    int row = idx >> 6, col = idx & 63;
    sc[((size_t)s * HW + q0 + row) * HW + k0 + col] = Cs[row * 65 + col];
  }
}

// ================= row softmax, static max = 30 =================
__global__ __launch_bounds__(256) void softmax_kernel(float* __restrict__ sc) {
  __shared__ float reds[8];
  float* p = sc + (size_t)blockIdx.x * HW;
  int t = threadIdx.x, lane = t & 31, warp = t >> 5;
  float v0 = __expf(p[t] - 30.0f),       v1 = __expf(p[t + 256] - 30.0f);
  float v2 = __expf(p[t + 512] - 30.0f), v3 = __expf(p[t + 768] - 30.0f);
  float sum = v0 + v1 + v2 + v3;
  #pragma unroll
  for (int o = 16; o; o >>= 1) sum += __shfl_xor_sync(0xffffffffu, sum, o);
  if (lane == 0) reds[warp] = sum;
  __syncthreads();
  float tot = reds[0];
  #pragma unroll
  for (int i = 1; i < 8; i++) tot += reds[i];
  float inv = 1.0f / tot;
  p[t] = v0 * inv; p[t + 256] = v1 * inv;
  p[t + 512] = v2 * inv; p[t + 768] = v3 * inv;
}

// ================= self P.V + residual =================
__global__ __launch_bounds__(256) void pv_self_kernel(
    const float* __restrict__ sc, const float* __restrict__ tgt,
    float* __restrict__ tout) {
  __shared__ float As[128 * 36];
  __shared__ float Bs[64 * 36];
  int s = blockIdx.z;
  int n0 = blockIdx.x * 128, c0 = blockIdx.y * 64;
  const float* P = sc + (size_t)s * HW * HW;
  const float* V = tgt + (size_t)s * CD * HW;
  int t = threadIdx.x;
  int cgr = t & 15;
  int ngr = t >> 4;
  float acc[8][4] = {};
  for (int m0 = 0; m0 < HW; m0 += 32) {
    int idx = t;
    #pragma unroll
    for (int r = 0; r < 16; r++, idx += 256) {
      int n = idx >> 5, m = idx & 31;
      As[n * 36 + m] = P[(size_t)(n0 + n) * HW + m0 + m];
    }
    idx = t;
    #pragma unroll
    for (int r = 0; r < 8; r++, idx += 256) {
      int c = idx >> 5, m = idx & 31;
      Bs[c * 36 + m] = V[(size_t)(c0 + c) * HW + m0 + m];
    }
    __syncthreads();
    #pragma unroll
    for (int m4 = 0; m4 < 8; m4++) {
      float4 b[4];
      #pragma unroll
      for (int j = 0; j < 4; j++)
        b[j] = *(const float4*)(Bs + (cgr + 16 * j) * 36 + m4 * 4);
      #pragma unroll
      for (int i = 0; i < 8; i++) {
        float4 a = *(const float4*)(As + (ngr * 8 + i) * 36 + m4 * 4);
        #pragma unroll
        for (int j = 0; j < 4; j++) {
          acc[i][j] = fmaf(a.x, b[j].x, acc[i][j]);
          acc[i][j] = fmaf(a.y, b[j].y, acc[i][j]);
          acc[i][j] = fmaf(a.z, b[j].z, acc[i][j]);
          acc[i][j] = fmaf(a.w, b[j].w, acc[i][j]);
        }
      }
    }
    __syncthreads();
  }
  #pragma unroll
  for (int j = 0; j < 4; j++) {
    int c = c0 + cgr + 16 * j;
    size_t g = (size_t)(s * CD + c) * HW + n0 + ngr * 8;
    #pragma unroll
    for (int i4 = 0; i4 < 8; i4 += 4) {
      float4 tg4 = *(const float4*)(tgt + g + i4);
      tg4.x += acc[i4 + 0][j]; tg4.y += acc[i4 + 1][j];
      tg4.z += acc[i4 + 2][j]; tg4.w += acc[i4 + 3][j];
      *(float4*)(tout + g + i4) = tg4;
    }
  }
}

// ================= instance norm =================
__global__ __launch_bounds__(256) void instnorm_kernel(float* __restrict__ x) {
  __shared__ float redS[8];
  __shared__ float redQ[8];
  float* p = x + (size_t)blockIdx.x * HW;
  int t = threadIdx.x, lane = t & 31, warp = t >> 5;
  float v0 = p[t], v1 = p[t + 256], v2 = p[t + 512], v3 = p[t + 768];
  float sum = v0 + v1 + v2 + v3;
  float sq = v0 * v0 + v1 * v1 + v2 * v2 + v3 * v3;
  #pragma unroll
  for (int o = 16; o; o >>= 1) {
    sum += __shfl_xor_sync(0xffffffffu, sum, o);
    sq  += __shfl_xor_sync(0xffffffffu, sq, o);
  }
  if (lane == 0) { redS[warp] = sum; redQ[warp] = sq; }
  __syncthreads();
  sum = redS[0]; sq = redQ[0];
  #pragma unroll
  for (int i = 1; i < 8; i++) { sum += redS[i]; sq += redQ[i]; }
  float mean = sum * (1.0f / HW);
  float var = sq * (1.0f / HW) - mean * mean;
  float rstd = rsqrtf(var + 1e-5f);
  p[t]       = (v0 - mean) * rstd;
  p[t + 256] = (v1 - mean) * rstd;
  p[t + 512] = (v2 - mean) * rstd;
  p[t + 768] = (v3 - mean) * rstd;
}

// ================= cross attention: HMMA split-bf16 scores =================
#define QSTR 136
#define PSTR 132
#define OFF_QH 0
#define OFF_QL 17408
#define OFF_KH 34816
#define OFF_KL 69632
#define OFF_PS 104448
#define OFF_VS 138240
#define OFF_OL 146432
#define OFF_PR 146688
#define SMEM_CROSS 147712

__global__ __launch_bounds__(256, 1) void cross_attn_kernel(
    const float* __restrict__ wq,
    const __nv_bfloat16* __restrict__ khi, const __nv_bfloat16* __restrict__ klo,
    const float* __restrict__ pe, float* __restrict__ part) {
  extern __shared__ char smc[];
  __nv_bfloat16* Qh = (__nv_bfloat16*)(smc + OFF_QH);
  __nv_bfloat16* Ql = (__nv_bfloat16*)(smc + OFF_QL);
  __nv_bfloat16* Kh = (__nv_bfloat16*)(smc + OFF_KH);
  __nv_bfloat16* Kl = (__nv_bfloat16*)(smc + OFF_KL);
  float* Ps   = (float*)(smc + OFF_PS);
  float* Vs   = (float*)(smc + OFF_VS);
  float* Ol   = (float*)(smc + OFF_OL);
  float* Pred = (float*)(smc + OFF_PR);
  int qt = blockIdx.x, s = blockIdx.y, ksp = blockIdx.z;
  int q0 = qt * 64;
  int t = threadIdx.x;
  int w = t >> 5, lane = t & 31;
  int lr = lane >> 2, lc = lane & 3;

  {
    const float4* src = (const float4*)(wq + ((size_t)s * HW + q0) * KD);
    #pragma unroll
    for (int r = 0; r < 8; r++) {
      int idx = t + r * 256;
      int q = idx >> 5, d4 = (idx & 31) * 4;
      float4 v = src[idx];
      v.x *= TAU_INV; v.y *= TAU_INV; v.z *= TAU_INV; v.w *= TAU_INV;
      __nv_bfloat16 h0 = __float2bfloat16(v.x), h1 = __float2bfloat16(v.y);
      __nv_bfloat16 h2 = __float2bfloat16(v.z), h3 = __float2bfloat16(v.w);
      __nv_bfloat16 l0 = __float2bfloat16(v.x - __bfloat162float(h0));
      __nv_bfloat16 l1 = __float2bfloat16(v.y - __bfloat162float(h1));
      __nv_bfloat16 l2 = __float2bfloat16(v.z - __bfloat162float(h2));
      __nv_bfloat16 l3 = __float2bfloat16(v.w - __bfloat162float(h3));
      uint2 uh, ul;
      uh.x = (uint32_t)__bfloat16_as_ushort(h0) | ((uint32_t)__bfloat16_as_ushort(h1) << 16);
      uh.y = (uint32_t)__bfloat16_as_ushort(h2) | ((uint32_t)__bfloat16_as_ushort(h3) << 16);
      ul.x = (uint32_t)__bfloat16_as_ushort(l0) | ((uint32_t)__bfloat16_as_ushort(l1) << 16);
      ul.y = (uint32_t)__bfloat16_as_ushort(l2) | ((uint32_t)__bfloat16_as_ushort(l3) << 16);
      *(uint2*)(Qh + q * QSTR + d4) = uh;
      *(uint2*)(Ql + q * QSTR + d4) = ul;
    }
  }
  if (t < 64) Ol[t] = 0.0f;

  int mq = (w & 3) * 16;
  int kb = (w >> 2) * 64;
  int pq = t >> 2, pve = (t & 3) * 4;
  float4 o = make_float4(0.f, 0.f, 0.f, 0.f);

  for (int kt = 0; kt < NM / (KSPLIT * 128); kt++) {
    int kk0 = ksp * (NM / KSPLIT) + kt * 128;
    __syncthreads();
    {
      const uint4* gh = (const uint4*)(khi + ((size_t)s * NM + kk0) * KD);
      const uint4* gl = (const uint4*)(klo + ((size_t)s * NM + kk0) * KD);
      #pragma unroll
      for (int r = 0; r < 8; r++) {
        int idx = t + r * 256;
        int key = idx >> 4, d8 = (idx & 15) * 8;
        *(uint4*)(Kh + key * QSTR + d8) = gh[idx];
        *(uint4*)(Kl + key * QSTR + d8) = gl[idx];
      }
    }
    {
      int f = kk0 >> 10, nn0 = kk0 & 1023;
      const float* pb = pe + ((size_t)(f * S4 + s)) * CE * HW + nn0;
      #pragma unroll
      for (int r = 0; r < 8; r++) {
        int idx = t + r * 256;
        int e = idx >> 7, k = idx & 127;
        Vs[k * 16 + e] = pb[(size_t)e * HW + k];
      }
    }
    __syncthreads();
    float c[8][4];
    #pragma unroll
    for (int nt = 0; nt < 8; nt++)
      #pragma unroll
      for (int j = 0; j < 4; j++) c[nt][j] = 0.0f;
    const __nv_bfloat16* Ap[3] = {Qh, Ql, Qh};
    const __nv_bfloat16* Bp[3] = {Kh, Kh, Kl};
    #pragma unroll
    for (int pass = 0; pass < 3; pass++) {
      const __nv_bfloat16* A = Ap[pass];
      const __nv_bfloat16* B = Bp[pass];
      #pragma unroll
      for (int ds = 0; ds < 8; ds++) {
        int d0 = ds * 16 + lc * 2;
        uint32_t a0 = *(const uint32_t*)(A + (mq + lr) * QSTR + d0);
        uint32_t a1 = *(const uint32_t*)(A + (mq + 8 + lr) * QSTR + d0);
        uint32_t a2 = *(const uint32_t*)(A + (mq + lr) * QSTR + d0 + 8);
        uint32_t a3 = *(const uint32_t*)(A + (mq + 8 + lr) * QSTR + d0 + 8);
        #pragma unroll
        for (int nt = 0; nt < 8; nt++) {
          const __nv_bfloat16* br = B + (kb + nt * 8 + lr) * QSTR + d0;
          uint32_t b0 = *(const uint32_t*)(br);
          uint32_t b1 = *(const uint32_t*)(br + 8);
          mma_bf16(c[nt], a0, a1, a2, a3, b0, b1);
        }
      }
    }
    float sl = 0.0f, sh = 0.0f;
    #pragma unroll
    for (int nt = 0; nt < 8; nt++) {
      float e0 = __expf(c[nt][0] - 30.0f);
      float e1 = __expf(c[nt][1] - 30.0f);
      float e2 = __expf(c[nt][2] - 30.0f);
      float e3 = __expf(c[nt][3] - 30.0f);
      int col = kb + nt * 8 + lc * 2;
      *(float2*)(Ps + (mq + lr) * PSTR + col)     = make_float2(e0, e1);
      *(float2*)(Ps + (mq + 8 + lr) * PSTR + col) = make_float2(e2, e3);
      sl += e0 + e1; sh += e2 + e3;
    }
    sl += __shfl_xor_sync(0xffffffffu, sl, 1);
    sl += __shfl_xor_sync(0xffffffffu, sl, 2);
    sh += __shfl_xor_sync(0xffffffffu, sh, 1);
    sh += __shfl_xor_sync(0xffffffffu, sh, 2);
    if (lc == 0) {
      Pred[(mq + lr) * 4 + (w >> 2)]     = sl;
      Pred[(mq + 8 + lr) * 4 + (w >> 2)] = sh;
    }
    __syncthreads();
    if (t < 64) Ol[t] += Pred[t * 4] + Pred[t * 4 + 1];
    {
      const float* prow = Ps + pq * PSTR;
      const float* vb = Vs + pve;
      #pragma unroll 8
      for (int k = 0; k < 128; k++) {
        float p = prow[k];
        float4 v = *(const float4*)(vb + k * 16);
        o.x = fmaf(p, v.x, o.x); o.y = fmaf(p, v.y, o.y);
        o.z = fmaf(p, v.z, o.z); o.w = fmaf(p, v.w, o.w);
      }
    }
  }
  __syncthreads();
  {
    float* pp = part + ((size_t)((ksp * S4 + s) * HW) + q0 + pq) * 18;
    pp[pve + 0] = o.x; pp[pve + 1] = o.y;
    pp[pve + 2] = o.z; pp[pve + 3] = o.w;
    if ((t & 3) == 0) pp[16] = Ol[pq];
  }
}

// ================= merge split-K partials + sigmoid =================
__global__ __launch_bounds__(256) void merge_kernel(
    const float* __restrict__ part, float* __restrict__ out) {
  int g = blockIdx.x * 256 + threadIdx.x;
  int eg = (g & 3) * 4;
  int sn = g >> 2;
  int n = sn & 1023, s = sn >> 10;
  float L = 0.0f;
  float O[4] = {};
  #pragma unroll
  for (int z = 0; z < KSPLIT; z++) {
    const float* pp = part + ((size_t)((z * S4 + s) * HW) + n) * 18;
    L += pp[16];
    #pragma unroll
    for (int e = 0; e < 4; e++) O[e] += pp[eg + e];
  }
  float inv = 1.0f / L;
  #pragma unroll
  for (int e = 0; e < 4; e++) {
    float v = O[e] * inv;
    out[(size_t)(s * CE + eg + e) * HW + n] = 1.0f / (1.0f + __expf(-v));
  }
}

// ================= host =================
extern "C" void kernel_launch(void* const* d_in, const int* in_sizes, int n_in,
                              void* d_out, int out_size) {
  const float* tgt = (const float*)d_in[0];
  const float* mem = (const float*)d_in[1];
  const float* pe  = (const float*)d_in[2];
  const float* wks = (const float*)d_in[3];
  const float* bks = (const float*)d_in[4];
  const float* wkc = (const float*)d_in[5];
  const float* bkc = (const float*)d_in[6];
  float* out = (float*)d_out;

  float *p_wq_self, *p_sc, *p_t, *p_wq_cross, *p_part;
  __nv_bfloat16 *p_wk_hi, *p_wk_lo;
  cudaGetSymbolAddress((void**)&p_wq_self, g_wq_self);
  cudaGetSymbolAddress((void**)&p_sc, g_sc);
  cudaGetSymbolAddress((void**)&p_t, g_t);
  cudaGetSymbolAddress((void**)&p_wq_cross, g_wq_cross);
  cudaGetSymbolAddress((void**)&p_wk_hi, g_wk_hi);
  cudaGetSymbolAddress((void**)&p_wk_lo, g_wk_lo);
  cudaGetSymbolAddress((void**)&p_part, g_part);

  // self-attention
  proj_kernel<<<dim3(16, 4), 256>>>(tgt, wks, bks, p_wq_self, HW);
  self_scores_kernel<<<dim3(16, 16, 4), 256>>>(p_wq_self, p_sc);
  softmax_kernel<<<4096, 256>>>(p_sc);
  pv_self_kernel<<<dim3(8, 8, 4), 256>>>(p_sc, tgt, p_t);
  instnorm_kernel<<<2048, 256>>>(p_t);

  // cross projections: Q fp32; memory K via HMMA split-bf16
  proj_kernel<<<dim3(16, 4), 256>>>(p_t, wkc, bkc, p_wq_cross, HW);
  cudaFuncSetAttribute(proj_mma_kernel,
                       cudaFuncAttributeMaxDynamicSharedMemorySize, SMEM_PROJ);
  proj_mma_kernel<<<dim3(256, 4), 256, SMEM_PROJ>>>(mem, wkc, bkc, p_wk_hi, p_wk_lo, NM);

  // HMMA cross-attention
  cudaFuncSetAttribute(cross_attn_kernel,
                       cudaFuncAttributeMaxDynamicSharedMemorySize, SMEM_CROSS);
  cross_attn_kernel<<<dim3(16, 4, KSPLIT), 256, SMEM_CROSS>>>(
      p_wq_cross, p_wk_hi, p_wk_lo, pe, p_part);
  merge_kernel<<<64, 256>>>(p_part, out);
}

// round 10
// speedup vs baseline: 1.5609x; 1.1125x over previous
#include <cuda_runtime.h>
#include <cuda_bf16.h>
#include <math.h>
#include <stdint.h>

#define S4 4
#define CD 512
#define KD 128
#define HW 1024
#define NM 16384
#define CE 16
#define TAU_INV 30.0f
#define KSPLIT 16

// ---------------- scratch ----------------
__device__ float g_wq_self[S4 * HW * KD];
__device__ float g_sc[S4 * HW * HW];
__device__ __nv_bfloat16 g_p_hi[S4 * HW * HW];
__device__ __nv_bfloat16 g_p_lo[S4 * HW * HW];
__device__ __nv_bfloat16 g_v_hi[S4 * CD * HW];
__device__ __nv_bfloat16 g_v_lo[S4 * CD * HW];
__device__ float g_t[S4 * CD * HW];
__device__ float g_wq_cross[S4 * HW * KD];
__device__ __nv_bfloat16 g_wk_hi[S4 * NM * KD];
__device__ __nv_bfloat16 g_wk_lo[S4 * NM * KD];
__device__ float g_part[KSPLIT * S4 * HW * 18];

__device__ __forceinline__ void mma_bf16(float* c, uint32_t a0, uint32_t a1,
                                         uint32_t a2, uint32_t a3,
                                         uint32_t b0, uint32_t b1) {
  asm("mma.sync.aligned.m16n8k16.row.col.f32.bf16.bf16.f32 "
      "{%0,%1,%2,%3}, {%4,%5,%6,%7}, {%8,%9}, {%0,%1,%2,%3};"
      : "+f"(c[0]), "+f"(c[1]), "+f"(c[2]), "+f"(c[3])
      : "r"(a0), "r"(a1), "r"(a2), "r"(a3), "r"(b0), "r"(b1));
}

// ================= projection + L2 normalize (fp32) =================
__global__ __launch_bounds__(256) void proj_kernel(
    const float* __restrict__ in, const float* __restrict__ W,
    const float* __restrict__ bias, float* __restrict__ out, int NT) {
  __shared__ float As[64 * 36];
  __shared__ float Ws[128 * 36];
  int s = blockIdx.y;
  int tg0 = blockIdx.x * 64;
  int f = tg0 >> 10;
  int n0 = tg0 & 1023;
  const float* inb = in + ((size_t)(f * S4 + s)) * CD * HW + n0;
  int t = threadIdx.x;
  int wid = t >> 5;
  int dgr = t & 31;
  float acc[8][4] = {};
  for (int c0 = 0; c0 < CD; c0 += 32) {
    int idx = t;
    #pragma unroll
    for (int r = 0; r < 8; r++, idx += 256) {
      int cc = idx >> 6, tok = idx & 63;
      As[tok * 36 + cc] = inb[(size_t)(c0 + cc) * HW + tok];
    }
    idx = t;
    #pragma unroll
    for (int r = 0; r < 16; r++, idx += 256) {
      int d = idx >> 5, cc = idx & 31;
      Ws[d * 36 + cc] = W[d * CD + c0 + cc];
    }
    __syncthreads();
    #pragma unroll
    for (int cc4 = 0; cc4 < 8; cc4++) {
      float4 b[4];
      #pragma unroll
      for (int j = 0; j < 4; j++)
        b[j] = *(const float4*)(Ws + (dgr + 32 * j) * 36 + cc4 * 4);
      #pragma unroll
      for (int i = 0; i < 8; i++) {
        float4 a = *(const float4*)(As + (wid * 8 + i) * 36 + cc4 * 4);
        #pragma unroll
        for (int j = 0; j < 4; j++) {
          acc[i][j] = fmaf(a.x, b[j].x, acc[i][j]);
          acc[i][j] = fmaf(a.y, b[j].y, acc[i][j]);
          acc[i][j] = fmaf(a.z, b[j].z, acc[i][j]);
          acc[i][j] = fmaf(a.w, b[j].w, acc[i][j]);
        }
      }
    }
    __syncthreads();
  }
  float bv[4];
  #pragma unroll
  for (int j = 0; j < 4; j++) bv[j] = bias[dgr + 32 * j];
  float ssp[8];
  #pragma unroll
  for (int i = 0; i < 8; i++) {
    float s0 = 0.0f;
    #pragma unroll
    for (int j = 0; j < 4; j++) {
      acc[i][j] += bv[j];
      s0 = fmaf(acc[i][j], acc[i][j], s0);
    }
    ssp[i] = s0;
  }
  #pragma unroll
  for (int o = 16; o; o >>= 1)
    #pragma unroll
    for (int i = 0; i < 8; i++)
      ssp[i] += __shfl_xor_sync(0xffffffffu, ssp[i], o);
  #pragma unroll
  for (int i = 0; i < 8; i++) {
    float scl = 1.0f / fmaxf(sqrtf(ssp[i]), 1e-12f);
    float* ob = out + ((size_t)s * NT + tg0 + wid * 8 + i) * KD;
    #pragma unroll
    for (int j = 0; j < 4; j++)
      ob[dgr + 32 * j] = acc[i][j] * scl;
  }
}

// ================= HMMA projection + L2 normalize -> bf16 hi/lo =================
#define PASTR 72
#define POFF_AH 0
#define POFF_AL 9216
#define POFF_BH 18432
#define POFF_BL 36864
#define POFF_RED 55296
#define SMEM_PROJ 55808

__global__ __launch_bounds__(256, 1) void proj_mma_kernel(
    const float* __restrict__ in, const float* __restrict__ W,
    const float* __restrict__ bias,
    __nv_bfloat16* __restrict__ out_hi, __nv_bfloat16* __restrict__ out_lo,
    int NT) {
  extern __shared__ char smp[];
  __nv_bfloat16* Ah = (__nv_bfloat16*)(smp + POFF_AH);
  __nv_bfloat16* Al = (__nv_bfloat16*)(smp + POFF_AL);
  __nv_bfloat16* Bh = (__nv_bfloat16*)(smp + POFF_BH);
  __nv_bfloat16* Bl = (__nv_bfloat16*)(smp + POFF_BL);
  float* red = (float*)(smp + POFF_RED);
  int s = blockIdx.y;
  int tg0 = blockIdx.x * 64;
  int f = tg0 >> 10;
  int n0 = tg0 & 1023;
  const float* inb = in + ((size_t)(f * S4 + s)) * CD * HW + n0;
  int t = threadIdx.x;
  int w = t >> 5, lane = t & 31;
  int lr = lane >> 2, lc = lane & 3;
  int mq = (w & 3) * 16;
  int db = (w >> 2) * 64;
  float c[8][4];
  #pragma unroll
  for (int nt = 0; nt < 8; nt++)
    #pragma unroll
    for (int j = 0; j < 4; j++) c[nt][j] = 0.0f;

  for (int c0 = 0; c0 < CD; c0 += 64) {
    __syncthreads();
    #pragma unroll
    for (int r = 0; r < 16; r++) {
      int idx = t + r * 256;
      int tok = idx & 63, cc = idx >> 6;
      float v = inb[(size_t)(c0 + cc) * HW + tok];
      __nv_bfloat16 h = __float2bfloat16(v);
      Ah[tok * PASTR + cc] = h;
      Al[tok * PASTR + cc] = __float2bfloat16(v - __bfloat162float(h));
    }
    #pragma unroll
    for (int r = 0; r < 32; r++) {
      int idx = t + r * 256;
      int cc = idx & 63, d = idx >> 6;
      float v = W[d * CD + c0 + cc];
      __nv_bfloat16 h = __float2bfloat16(v);
      Bh[d * PASTR + cc] = h;
      Bl[d * PASTR + cc] = __float2bfloat16(v - __bfloat162float(h));
    }
    __syncthreads();
    const __nv_bfloat16* Ap[3] = {Ah, Al, Ah};
    const __nv_bfloat16* Bp[3] = {Bh, Bh, Bl};
    #pragma unroll
    for (int pass = 0; pass < 3; pass++) {
      const __nv_bfloat16* A = Ap[pass];
      const __nv_bfloat16* B = Bp[pass];
      #pragma unroll
      for (int ds = 0; ds < 4; ds++) {
        int d0 = ds * 16 + lc * 2;
        uint32_t a0 = *(const uint32_t*)(A + (mq + lr) * PASTR + d0);
        uint32_t a1 = *(const uint32_t*)(A + (mq + 8 + lr) * PASTR + d0);
        uint32_t a2 = *(const uint32_t*)(A + (mq + lr) * PASTR + d0 + 8);
        uint32_t a3 = *(const uint32_t*)(A + (mq + 8 + lr) * PASTR + d0 + 8);
        #pragma unroll
        for (int nt = 0; nt < 8; nt++) {
          const __nv_bfloat16* br = B + (db + nt * 8 + lr) * PASTR + d0;
          uint32_t b0 = *(const uint32_t*)(br);
          uint32_t b1 = *(const uint32_t*)(br + 8);
          mma_bf16(c[nt], a0, a1, a2, a3, b0, b1);
        }
      }
    }
  }
  float ssl = 0.0f, ssh = 0.0f;
  #pragma unroll
  for (int nt = 0; nt < 8; nt++) {
    int d = db + nt * 8 + lc * 2;
    float b0 = bias[d], b1 = bias[d + 1];
    c[nt][0] += b0; c[nt][1] += b1;
    c[nt][2] += b0; c[nt][3] += b1;
    ssl = fmaf(c[nt][0], c[nt][0], fmaf(c[nt][1], c[nt][1], ssl));
    ssh = fmaf(c[nt][2], c[nt][2], fmaf(c[nt][3], c[nt][3], ssh));
  }
  ssl += __shfl_xor_sync(0xffffffffu, ssl, 1);
  ssl += __shfl_xor_sync(0xffffffffu, ssl, 2);
  ssh += __shfl_xor_sync(0xffffffffu, ssh, 1);
  ssh += __shfl_xor_sync(0xffffffffu, ssh, 2);
  __syncthreads();
  if (lc == 0) {
    red[(mq + lr) * 2 + (w >> 2)]     = ssl;
    red[(mq + 8 + lr) * 2 + (w >> 2)] = ssh;
  }
  __syncthreads();
  float sl = 1.0f / fmaxf(sqrtf(red[(mq + lr) * 2] + red[(mq + lr) * 2 + 1]), 1e-12f);
  float sh = 1.0f / fmaxf(sqrtf(red[(mq + 8 + lr) * 2] + red[(mq + 8 + lr) * 2 + 1]), 1e-12f);
  size_t rb0 = ((size_t)s * NT + tg0 + mq + lr) * KD;
  size_t rb1 = ((size_t)s * NT + tg0 + mq + 8 + lr) * KD;
  #pragma unroll
  for (int nt = 0; nt < 8; nt++) {
    int d = db + nt * 8 + lc * 2;
    float v0 = c[nt][0] * sl, v1 = c[nt][1] * sl;
    float v2 = c[nt][2] * sh, v3 = c[nt][3] * sh;
    __nv_bfloat16 h0 = __float2bfloat16(v0), h1 = __float2bfloat16(v1);
    __nv_bfloat16 h2 = __float2bfloat16(v2), h3 = __float2bfloat16(v3);
    uint32_t uh0 = (uint32_t)__bfloat16_as_ushort(h0) | ((uint32_t)__bfloat16_as_ushort(h1) << 16);
    uint32_t uh1 = (uint32_t)__bfloat16_as_ushort(h2) | ((uint32_t)__bfloat16_as_ushort(h3) << 16);
    __nv_bfloat16 l0 = __float2bfloat16(v0 - __bfloat162float(h0));
    __nv_bfloat16 l1 = __float2bfloat16(v1 - __bfloat162float(h1));
    __nv_bfloat16 l2 = __float2bfloat16(v2 - __bfloat162float(h2));
    __nv_bfloat16 l3 = __float2bfloat16(v3 - __bfloat162float(h3));
    uint32_t ul0 = (uint32_t)__bfloat16_as_ushort(l0) | ((uint32_t)__bfloat16_as_ushort(l1) << 16);
    uint32_t ul1 = (uint32_t)__bfloat16_as_ushort(l2) | ((uint32_t)__bfloat16_as_ushort(l3) << 16);
    *(uint32_t*)(out_hi + rb0 + d) = uh0;
    *(uint32_t*)(out_hi + rb1 + d) = uh1;
    *(uint32_t*)(out_lo + rb0 + d) = ul0;
    *(uint32_t*)(out_lo + rb1 + d) = ul1;
  }
}

// ================= self-attention raw scores =================
__global__ __launch_bounds__(256) void self_scores_kernel(
    const float* __restrict__ wq, float* __restrict__ sc) {
  __shared__ float QK[2][64][65];
  int s = blockIdx.z;
  int q0 = blockIdx.x * 64, k0 = blockIdx.y * 64;
  const float* base = wq + (size_t)s * HW * KD;
  int t = threadIdx.x;
  int qg = t & 15, kg = t >> 4;
  float acc[4][4] = {};
  for (int d0 = 0; d0 < KD; d0 += 64) {
    int idx = t;
    #pragma unroll
    for (int r = 0; r < 16; r++, idx += 256) {
      int row = idx >> 6, dd = idx & 63;
      QK[0][row][dd] = base[(size_t)(q0 + row) * KD + d0 + dd];
      QK[1][row][dd] = base[(size_t)(k0 + row) * KD + d0 + dd];
    }
    __syncthreads();
    #pragma unroll 8
    for (int k = 0; k < 64; k++) {
      float a[4], b[4];
      #pragma unroll
      for (int i = 0; i < 4; i++) a[i] = QK[0][qg * 4 + i][k];
      #pragma unroll
      for (int j = 0; j < 4; j++) b[j] = QK[1][kg * 4 + j][k];
      #pragma unroll
      for (int i = 0; i < 4; i++)
        #pragma unroll
        for (int j = 0; j < 4; j++)
          acc[i][j] = fmaf(a[i], b[j], acc[i][j]);
    }
    __syncthreads();
  }
  float* Cs = &QK[0][0][0];
  #pragma unroll
  for (int i = 0; i < 4; i++)
    #pragma unroll
    for (int j = 0; j < 4; j++)
      Cs[(qg * 4 + i) * 65 + kg * 4 + j] = acc[i][j] * TAU_INV;
  __syncthreads();
  int idx = t;
  #pragma unroll
  for (int r = 0; r < 16; r++, idx += 256) {
    int row = idx >> 6, col = idx & 63;
    sc[((size_t)s * HW + q0 + row) * HW + k0 + col] = Cs[row * 65 + col];
  }
}

// ================= row softmax, static max = 30, emit bf16 hi/lo =================
__global__ __launch_bounds__(256) void softmax_kernel(
    const float* __restrict__ sc,
    __nv_bfloat16* __restrict__ phi, __nv_bfloat16* __restrict__ plo) {
  __shared__ float reds[8];
  const float* p = sc + (size_t)blockIdx.x * HW;
  size_t ob = (size_t)blockIdx.x * HW;
  int t = threadIdx.x, lane = t & 31, warp = t >> 5;
  float v0 = __expf(p[t] - 30.0f),       v1 = __expf(p[t + 256] - 30.0f);
  float v2 = __expf(p[t + 512] - 30.0f), v3 = __expf(p[t + 768] - 30.0f);
  float sum = v0 + v1 + v2 + v3;
  #pragma unroll
  for (int o = 16; o; o >>= 1) sum += __shfl_xor_sync(0xffffffffu, sum, o);
  if (lane == 0) reds[warp] = sum;
  __syncthreads();
  float tot = reds[0];
  #pragma unroll
  for (int i = 1; i < 8; i++) tot += reds[i];
  float inv = 1.0f / tot;
  v0 *= inv; v1 *= inv; v2 *= inv; v3 *= inv;
  __nv_bfloat16 h0 = __float2bfloat16(v0), h1 = __float2bfloat16(v1);
  __nv_bfloat16 h2 = __float2bfloat16(v2), h3 = __float2bfloat16(v3);
  phi[ob + t] = h0; phi[ob + t + 256] = h1;
  phi[ob + t + 512] = h2; phi[ob + t + 768] = h3;
  plo[ob + t]       = __float2bfloat16(v0 - __bfloat162float(h0));
  plo[ob + t + 256] = __float2bfloat16(v1 - __bfloat162float(h1));
  plo[ob + t + 512] = __float2bfloat16(v2 - __bfloat162float(h2));
  plo[ob + t + 768] = __float2bfloat16(v3 - __bfloat162float(h3));
}

// ================= split tgt into bf16 hi/lo =================
__global__ __launch_bounds__(256) void split_v_kernel(
    const float* __restrict__ x,
    __nv_bfloat16* __restrict__ hi, __nv_bfloat16* __restrict__ lo) {
  int i = blockIdx.x * 1024 + threadIdx.x;
  #pragma unroll
  for (int r = 0; r < 4; r++, i += 256) {
    float v = x[i];
    __nv_bfloat16 h = __float2bfloat16(v);
    hi[i] = h;
    lo[i] = __float2bfloat16(v - __bfloat162float(h));
  }
}

// ================= self P.V via HMMA + residual =================
// block: 64 n x 128 c; chunks of 64 m; operands bf16 hi/lo precomputed.
#define CSTR 133
#define VOFF_AH 0
#define VOFF_AL 9216
#define VOFF_BH 18432
#define VOFF_BL 36864
#define SMEM_PV 55296

__global__ __launch_bounds__(256) void pv_mma_kernel(
    const __nv_bfloat16* __restrict__ phi, const __nv_bfloat16* __restrict__ plo,
    const __nv_bfloat16* __restrict__ vhi, const __nv_bfloat16* __restrict__ vlo,
    const float* __restrict__ tgt, float* __restrict__ tout) {
  extern __shared__ char smv[];
  __nv_bfloat16* Ah = (__nv_bfloat16*)(smv + VOFF_AH);
  __nv_bfloat16* Al = (__nv_bfloat16*)(smv + VOFF_AL);
  __nv_bfloat16* Bh = (__nv_bfloat16*)(smv + VOFF_BH);
  __nv_bfloat16* Bl = (__nv_bfloat16*)(smv + VOFF_BL);
  float* Cs = (float*)smv;   // alias, used after mainloop
  int s = blockIdx.z;
  int n0 = blockIdx.x * 64, c0 = blockIdx.y * 128;
  int t = threadIdx.x;
  int w = t >> 5, lane = t & 31;
  int lr = lane >> 2, lc = lane & 3;
  int mq = (w & 3) * 16;     // n rows
  int db = (w >> 2) * 64;    // c cols
  float c[8][4];
  #pragma unroll
  for (int nt = 0; nt < 8; nt++)
    #pragma unroll
    for (int j = 0; j < 4; j++) c[nt][j] = 0.0f;

  for (int m0 = 0; m0 < HW; m0 += 64) {
    __syncthreads();
    // A: P tile 64 n x 64 m (hi/lo), uint4 = 8 bf16
    {
      const __nv_bfloat16* gph = phi + ((size_t)s * HW + n0) * HW + m0;
      const __nv_bfloat16* gpl = plo + ((size_t)s * HW + n0) * HW + m0;
      #pragma unroll
      for (int r = 0; r < 2; r++) {
        int idx = t + r * 256;
        int row = idx >> 3, u4 = (idx & 7) * 8;
        *(uint4*)(Ah + row * PASTR + u4) = *(const uint4*)(gph + (size_t)row * HW + u4);
        *(uint4*)(Al + row * PASTR + u4) = *(const uint4*)(gpl + (size_t)row * HW + u4);
      }
    }
    // B: V tile 128 c x 64 m (hi/lo)
    {
      const __nv_bfloat16* gvh = vhi + ((size_t)s * CD + c0) * HW + m0;
      const __nv_bfloat16* gvl = vlo + ((size_t)s * CD + c0) * HW + m0;
      #pragma unroll
      for (int r = 0; r < 4; r++) {
        int idx = t + r * 256;
        int row = idx >> 3, u4 = (idx & 7) * 8;
        *(uint4*)(Bh + row * PASTR + u4) = *(const uint4*)(gvh + (size_t)row * HW + u4);
        *(uint4*)(Bl + row * PASTR + u4) = *(const uint4*)(gvl + (size_t)row * HW + u4);
      }
    }
    __syncthreads();
    const __nv_bfloat16* Ap[3] = {Ah, Al, Ah};
    const __nv_bfloat16* Bp[3] = {Bh, Bh, Bl};
    #pragma unroll
    for (int pass = 0; pass < 3; pass++) {
      const __nv_bfloat16* A = Ap[pass];
      const __nv_bfloat16* B = Bp[pass];
      #pragma unroll
      for (int ds = 0; ds < 4; ds++) {
        int d0 = ds * 16 + lc * 2;
        uint32_t a0 = *(const uint32_t*)(A + (mq + lr) * PASTR + d0);
        uint32_t a1 = *(const uint32_t*)(A + (mq + 8 + lr) * PASTR + d0);
        uint32_t a2 = *(const uint32_t*)(A + (mq + lr) * PASTR + d0 + 8);
        uint32_t a3 = *(const uint32_t*)(A + (mq + 8 + lr) * PASTR + d0 + 8);
        #pragma unroll
        for (int nt = 0; nt < 8; nt++) {
          const __nv_bfloat16* br = B + (db + nt * 8 + lr) * PASTR + d0;
          uint32_t b0 = *(const uint32_t*)(br);
          uint32_t b1 = *(const uint32_t*)(br + 8);
          mma_bf16(c[nt], a0, a1, a2, a3, b0, b1);
        }
      }
    }
  }
  __syncthreads();   // operands dead; alias Cs
  #pragma unroll
  for (int nt = 0; nt < 8; nt++) {
    int col = db + nt * 8 + lc * 2;
    Cs[(mq + lr) * CSTR + col]         = c[nt][0];
    Cs[(mq + lr) * CSTR + col + 1]     = c[nt][1];
    Cs[(mq + 8 + lr) * CSTR + col]     = c[nt][2];
    Cs[(mq + 8 + lr) * CSTR + col + 1] = c[nt][3];
  }
  __syncthreads();
  #pragma unroll
  for (int r = 0; r < 32; r++) {
    int idx = t + r * 256;
    int cc = idx >> 6, n = idx & 63;
    size_t g = (size_t)(s * CD + c0 + cc) * HW + n0 + n;
    tout[g] = tgt[g] + Cs[n * CSTR + cc];
  }
}

// ================= instance norm =================
__global__ __launch_bounds__(256) void instnorm_kernel(float* __restrict__ x) {
  __shared__ float redS[8];
  __shared__ float redQ[8];
  float* p = x + (size_t)blockIdx.x * HW;
  int t = threadIdx.x, lane = t & 31, warp = t >> 5;
  float v0 = p[t], v1 = p[t + 256], v2 = p[t + 512], v3 = p[t + 768];
  float sum = v0 + v1 + v2 + v3;
  float sq = v0 * v0 + v1 * v1 + v2 * v2 + v3 * v3;
  #pragma unroll
  for (int o = 16; o; o >>= 1) {
    sum += __shfl_xor_sync(0xffffffffu, sum, o);
    sq  += __shfl_xor_sync(0xffffffffu, sq, o);
  }
  if (lane == 0) { redS[warp] = sum; redQ[warp] = sq; }
  __syncthreads();
  sum = redS[0]; sq = redQ[0];
  #pragma unroll
  for (int i = 1; i < 8; i++) { sum += redS[i]; sq += redQ[i]; }
  float mean = sum * (1.0f / HW);
  float var = sq * (1.0f / HW) - mean * mean;
  float rstd = rsqrtf(var + 1e-5f);
  p[t]       = (v0 - mean) * rstd;
  p[t + 256] = (v1 - mean) * rstd;
  p[t + 512] = (v2 - mean) * rstd;
  p[t + 768] = (v3 - mean) * rstd;
}

// ================= cross attention: HMMA split-bf16 scores =================
#define QSTR 136
#define PSTR 132
#define OFF_QH 0
#define OFF_QL 17408
#define OFF_KH 34816
#define OFF_KL 69632
#define OFF_PS 104448
#define OFF_VS 138240
#define OFF_OL 146432
#define OFF_PR 146688
#define SMEM_CROSS 147712

__global__ __launch_bounds__(256, 1) void cross_attn_kernel(
    const float* __restrict__ wq,
    const __nv_bfloat16* __restrict__ khi, const __nv_bfloat16* __restrict__ klo,
    const float* __restrict__ pe, float* __restrict__ part) {
  extern __shared__ char smc[];
  __nv_bfloat16* Qh = (__nv_bfloat16*)(smc + OFF_QH);
  __nv_bfloat16* Ql = (__nv_bfloat16*)(smc + OFF_QL);
  __nv_bfloat16* Kh = (__nv_bfloat16*)(smc + OFF_KH);
  __nv_bfloat16* Kl = (__nv_bfloat16*)(smc + OFF_KL);
  float* Ps   = (float*)(smc + OFF_PS);
  float* Vs   = (float*)(smc + OFF_VS);
  float* Ol   = (float*)(smc + OFF_OL);
  float* Pred = (float*)(smc + OFF_PR);
  int qt = blockIdx.x, s = blockIdx.y, ksp = blockIdx.z;
  int q0 = qt * 64;
  int t = threadIdx.x;
  int w = t >> 5, lane = t & 31;
  int lr = lane >> 2, lc = lane & 3;

  {
    const float4* src = (const float4*)(wq + ((size_t)s * HW + q0) * KD);
    #pragma unroll
    for (int r = 0; r < 8; r++) {
      int idx = t + r * 256;
      int q = idx >> 5, d4 = (idx & 31) * 4;
      float4 v = src[idx];
      v.x *= TAU_INV; v.y *= TAU_INV; v.z *= TAU_INV; v.w *= TAU_INV;
      __nv_bfloat16 h0 = __float2bfloat16(v.x), h1 = __float2bfloat16(v.y);
      __nv_bfloat16 h2 = __float2bfloat16(v.z), h3 = __float2bfloat16(v.w);
      __nv_bfloat16 l0 = __float2bfloat16(v.x - __bfloat162float(h0));
      __nv_bfloat16 l1 = __float2bfloat16(v.y - __bfloat162float(h1));
      __nv_bfloat16 l2 = __float2bfloat16(v.z - __bfloat162float(h2));
      __nv_bfloat16 l3 = __float2bfloat16(v.w - __bfloat162float(h3));
      uint2 uh, ul;
      uh.x = (uint32_t)__bfloat16_as_ushort(h0) | ((uint32_t)__bfloat16_as_ushort(h1) << 16);
      uh.y = (uint32_t)__bfloat16_as_ushort(h2) | ((uint32_t)__bfloat16_as_ushort(h3) << 16);
      ul.x = (uint32_t)__bfloat16_as_ushort(l0) | ((uint32_t)__bfloat16_as_ushort(l1) << 16);
      ul.y = (uint32_t)__bfloat16_as_ushort(l2) | ((uint32_t)__bfloat16_as_ushort(l3) << 16);
      *(uint2*)(Qh + q * QSTR + d4) = uh;
      *(uint2*)(Ql + q * QSTR + d4) = ul;
    }
  }
  if (t < 64) Ol[t] = 0.0f;

  int mq = (w & 3) * 16;
  int kb = (w >> 2) * 64;
  int pq = t >> 2, pve = (t & 3) * 4;
  float4 o = make_float4(0.f, 0.f, 0.f, 0.f);

  for (int kt = 0; kt < NM / (KSPLIT * 128); kt++) {
    int kk0 = ksp * (NM / KSPLIT) + kt * 128;
    __syncthreads();
    {
      const uint4* gh = (const uint4*)(khi + ((size_t)s * NM + kk0) * KD);
      const uint4* gl = (const uint4*)(klo + ((size_t)s * NM + kk0) * KD);
      #pragma unroll
      for (int r = 0; r < 8; r++) {
        int idx = t + r * 256;
        int key = idx >> 4, d8 = (idx & 15) * 8;
        *(uint4*)(Kh + key * QSTR + d8) = gh[idx];
        *(uint4*)(Kl + key * QSTR + d8) = gl[idx];
      }
    }
    {
      int f = kk0 >> 10, nn0 = kk0 & 1023;
      const float* pb = pe + ((size_t)(f * S4 + s)) * CE * HW + nn0;
      #pragma unroll
      for (int r = 0; r < 8; r++) {
        int idx = t + r * 256;
        int e = idx >> 7, k = idx & 127;
        Vs[k * 16 + e] = pb[(size_t)e * HW + k];
      }
    }
    __syncthreads();
    float c[8][4];
    #pragma unroll
    for (int nt = 0; nt < 8; nt++)
      #pragma unroll
      for (int j = 0; j < 4; j++) c[nt][j] = 0.0f;
    const __nv_bfloat16* Ap[3] = {Qh, Ql, Qh};
    const __nv_bfloat16* Bp[3] = {Kh, Kh, Kl};
    #pragma unroll
    for (int pass = 0; pass < 3; pass++) {
      const __nv_bfloat16* A = Ap[pass];
      const __nv_bfloat16* B = Bp[pass];
      #pragma unroll
      for (int ds = 0; ds < 8; ds++) {
        int d0 = ds * 16 + lc * 2;
        uint32_t a0 = *(const uint32_t*)(A + (mq + lr) * QSTR + d0);
        uint32_t a1 = *(const uint32_t*)(A + (mq + 8 + lr) * QSTR + d0);
        uint32_t a2 = *(const uint32_t*)(A + (mq + lr) * QSTR + d0 + 8);
        uint32_t a3 = *(const uint32_t*)(A + (mq + 8 + lr) * QSTR + d0 + 8);
        #pragma unroll
        for (int nt = 0; nt < 8; nt++) {
          const __nv_bfloat16* br = B + (kb + nt * 8 + lr) * QSTR + d0;
          uint32_t b0 = *(const uint32_t*)(br);
          uint32_t b1 = *(const uint32_t*)(br + 8);
          mma_bf16(c[nt], a0, a1, a2, a3, b0, b1);
        }
      }
    }
    float sl = 0.0f, sh = 0.0f;
    #pragma unroll
    for (int nt = 0; nt < 8; nt++) {
      float e0 = __expf(c[nt][0] - 30.0f);
      float e1 = __expf(c[nt][1] - 30.0f);
      float e2 = __expf(c[nt][2] - 30.0f);
      float e3 = __expf(c[nt][3] - 30.0f);
      int col = kb + nt * 8 + lc * 2;
      *(float2*)(Ps + (mq + lr) * PSTR + col)     = make_float2(e0, e1);
      *(float2*)(Ps + (mq + 8 + lr) * PSTR + col) = make_float2(e2, e3);
      sl += e0 + e1; sh += e2 + e3;
    }
    sl += __shfl_xor_sync(0xffffffffu, sl, 1);
    sl += __shfl_xor_sync(0xffffffffu, sl, 2);
    sh += __shfl_xor_sync(0xffffffffu, sh, 1);
    sh += __shfl_xor_sync(0xffffffffu, sh, 2);
    if (lc == 0) {
      Pred[(mq + lr) * 4 + (w >> 2)]     = sl;
      Pred[(mq + 8 + lr) * 4 + (w >> 2)] = sh;
    }
    __syncthreads();
    if (t < 64) Ol[t] += Pred[t * 4] + Pred[t * 4 + 1];
    {
      const float* prow = Ps + pq * PSTR;
      const float* vb = Vs + pve;
      #pragma unroll 8
      for (int k = 0; k < 128; k++) {
        float p = prow[k];
        float4 v = *(const float4*)(vb + k * 16);
        o.x = fmaf(p, v.x, o.x); o.y = fmaf(p, v.y, o.y);
        o.z = fmaf(p, v.z, o.z); o.w = fmaf(p, v.w, o.w);
      }
    }
  }
  __syncthreads();
  {
    float* pp = part + ((size_t)((ksp * S4 + s) * HW) + q0 + pq) * 18;
    pp[pve + 0] = o.x; pp[pve + 1] = o.y;
    pp[pve + 2] = o.z; pp[pve + 3] = o.w;
    if ((t & 3) == 0) pp[16] = Ol[pq];
  }
}

// ================= merge split-K partials + sigmoid =================
__global__ __launch_bounds__(256) void merge_kernel(
    const float* __restrict__ part, float* __restrict__ out) {
  int g = blockIdx.x * 256 + threadIdx.x;
  int eg = (g & 3) * 4;
  int sn = g >> 2;
  int n = sn & 1023, s = sn >> 10;
  float L = 0.0f;
  float O[4] = {};
  #pragma unroll
  for (int z = 0; z < KSPLIT; z++) {
    const float* pp = part + ((size_t)((z * S4 + s) * HW) + n) * 18;
    L += pp[16];
    #pragma unroll
    for (int e = 0; e < 4; e++) O[e] += pp[eg + e];
  }
  float inv = 1.0f / L;
  #pragma unroll
  for (int e = 0; e < 4; e++) {
    float v = O[e] * inv;
    out[(size_t)(s * CE + eg + e) * HW + n] = 1.0f / (1.0f + __expf(-v));
  }
}

// ================= host =================
extern "C" void kernel_launch(void* const* d_in, const int* in_sizes, int n_in,
                              void* d_out, int out_size) {
  const float* tgt = (const float*)d_in[0];
  const float* mem = (const float*)d_in[1];
  const float* pe  = (const float*)d_in[2];
  const float* wks = (const float*)d_in[3];
  const float* bks = (const float*)d_in[4];
  const float* wkc = (const float*)d_in[5];
  const float* bkc = (const float*)d_in[6];
  float* out = (float*)d_out;

  float *p_wq_self, *p_sc, *p_t, *p_wq_cross, *p_part;
  __nv_bfloat16 *p_wk_hi, *p_wk_lo, *p_p_hi, *p_p_lo, *p_v_hi, *p_v_lo;
  cudaGetSymbolAddress((void**)&p_wq_self, g_wq_self);
  cudaGetSymbolAddress((void**)&p_sc, g_sc);
  cudaGetSymbolAddress((void**)&p_t, g_t);
  cudaGetSymbolAddress((void**)&p_wq_cross, g_wq_cross);
  cudaGetSymbolAddress((void**)&p_wk_hi, g_wk_hi);
  cudaGetSymbolAddress((void**)&p_wk_lo, g_wk_lo);
  cudaGetSymbolAddress((void**)&p_p_hi, g_p_hi);
  cudaGetSymbolAddress((void**)&p_p_lo, g_p_lo);
  cudaGetSymbolAddress((void**)&p_v_hi, g_v_hi);
  cudaGetSymbolAddress((void**)&p_v_lo, g_v_lo);
  cudaGetSymbolAddress((void**)&p_part, g_part);

  // self-attention
  proj_kernel<<<dim3(16, 4), 256>>>(tgt, wks, bks, p_wq_self, HW);
  self_scores_kernel<<<dim3(16, 16, 4), 256>>>(p_wq_self, p_sc);
  softmax_kernel<<<4096, 256>>>(p_sc, p_p_hi, p_p_lo);
  split_v_kernel<<<2048, 256>>>(tgt, p_v_hi, p_v_lo);
  cudaFuncSetAttribute(pv_mma_kernel,
                       cudaFuncAttributeMaxDynamicSharedMemorySize, SMEM_PV);
  pv_mma_kernel<<<dim3(16, 4, 4), 256, SMEM_PV>>>(p_p_hi, p_p_lo, p_v_hi, p_v_lo, tgt, p_t);
  instnorm_kernel<<<2048, 256>>>(p_t);

  // cross projections: Q fp32; memory K via HMMA split-bf16
  proj_kernel<<<dim3(16, 4), 256>>>(p_t, wkc, bkc, p_wq_cross, HW);
  cudaFuncSetAttribute(proj_mma_kernel,
                       cudaFuncAttributeMaxDynamicSharedMemorySize, SMEM_PROJ);
  proj_mma_kernel<<<dim3(256, 4), 256, SMEM_PROJ>>>(mem, wkc, bkc, p_wk_hi, p_wk_lo, NM);

  // HMMA cross-attention
  cudaFuncSetAttribute(cross_attn_kernel,
                       cudaFuncAttributeMaxDynamicSharedMemorySize, SMEM_CROSS);
  cross_attn_kernel<<<dim3(16, 4, KSPLIT), 256, SMEM_CROSS>>>(
      p_wq_cross, p_wk_hi, p_wk_lo, pe, p_part);
  merge_kernel<<<64, 256>>>(p_part, out);
}

// round 11
// speedup vs baseline: 1.7279x; 1.1070x over previous
#include <cuda_runtime.h>
#include <cuda_bf16.h>
#include <math.h>
#include <stdint.h>

#define S4 4
#define CD 512
#define KD 128
#define HW 1024
#define NM 16384
#define CE 16
#define KSPLIT 16

// ---------------- scratch ----------------
__device__ float g_sc[S4 * HW * HW];
__device__ __nv_bfloat16 g_p_hi[S4 * HW * HW];
__device__ __nv_bfloat16 g_p_lo[S4 * HW * HW];
__device__ __nv_bfloat16 g_v_hi[S4 * CD * HW];
__device__ __nv_bfloat16 g_v_lo[S4 * CD * HW];
__device__ float g_t[S4 * CD * HW];
__device__ __nv_bfloat16 g_qs_hi[S4 * HW * KD];
__device__ __nv_bfloat16 g_qs_lo[S4 * HW * KD];
__device__ __nv_bfloat16 g_qc_hi[S4 * HW * KD];
__device__ __nv_bfloat16 g_qc_lo[S4 * HW * KD];
__device__ __nv_bfloat16 g_wk_hi[S4 * NM * KD];
__device__ __nv_bfloat16 g_wk_lo[S4 * NM * KD];
__device__ float g_part[KSPLIT * S4 * HW * 18];

__device__ __forceinline__ void mma_bf16(float* c, uint32_t a0, uint32_t a1,
                                         uint32_t a2, uint32_t a3,
                                         uint32_t b0, uint32_t b1) {
  asm("mma.sync.aligned.m16n8k16.row.col.f32.bf16.bf16.f32 "
      "{%0,%1,%2,%3}, {%4,%5,%6,%7}, {%8,%9}, {%0,%1,%2,%3};"
      : "+f"(c[0]), "+f"(c[1]), "+f"(c[2]), "+f"(c[3])
      : "r"(a0), "r"(a1), "r"(a2), "r"(a3), "r"(b0), "r"(b1));
}

// ================= HMMA projection + L2 normalize -> bf16 hi/lo =================
#define PASTR 72
#define POFF_AH 0
#define POFF_AL 9216
#define POFF_BH 18432
#define POFF_BL 36864
#define POFF_RED 55296
#define SMEM_PROJ 55808

__global__ __launch_bounds__(256, 1) void proj_mma_kernel(
    const float* __restrict__ in, const float* __restrict__ W,
    const float* __restrict__ bias,
    __nv_bfloat16* __restrict__ out_hi, __nv_bfloat16* __restrict__ out_lo,
    int NT) {
  extern __shared__ char smp[];
  __nv_bfloat16* Ah = (__nv_bfloat16*)(smp + POFF_AH);
  __nv_bfloat16* Al = (__nv_bfloat16*)(smp + POFF_AL);
  __nv_bfloat16* Bh = (__nv_bfloat16*)(smp + POFF_BH);
  __nv_bfloat16* Bl = (__nv_bfloat16*)(smp + POFF_BL);
  float* red = (float*)(smp + POFF_RED);
  int s = blockIdx.y;
  int tg0 = blockIdx.x * 64;
  int f = tg0 >> 10;
  int n0 = tg0 & 1023;
  const float* inb = in + ((size_t)(f * S4 + s)) * CD * HW + n0;
  int t = threadIdx.x;
  int w = t >> 5, lane = t & 31;
  int lr = lane >> 2, lc = lane & 3;
  int mq = (w & 3) * 16;
  int db = (w >> 2) * 64;
  float c[8][4];
  #pragma unroll
  for (int nt = 0; nt < 8; nt++)
    #pragma unroll
    for (int j = 0; j < 4; j++) c[nt][j] = 0.0f;

  for (int c0 = 0; c0 < CD; c0 += 64) {
    __syncthreads();
    #pragma unroll
    for (int r = 0; r < 16; r++) {
      int idx = t + r * 256;
      int tok = idx & 63, cc = idx >> 6;
      float v = inb[(size_t)(c0 + cc) * HW + tok];
      __nv_bfloat16 h = __float2bfloat16(v);
      Ah[tok * PASTR + cc] = h;
      Al[tok * PASTR + cc] = __float2bfloat16(v - __bfloat162float(h));
    }
    #pragma unroll
    for (int r = 0; r < 32; r++) {
      int idx = t + r * 256;
      int cc = idx & 63, d = idx >> 6;
      float v = W[d * CD + c0 + cc];
      __nv_bfloat16 h = __float2bfloat16(v);
      Bh[d * PASTR + cc] = h;
      Bl[d * PASTR + cc] = __float2bfloat16(v - __bfloat162float(h));
    }
    __syncthreads();
    const __nv_bfloat16* Ap[3] = {Ah, Al, Ah};
    const __nv_bfloat16* Bp[3] = {Bh, Bh, Bl};
    #pragma unroll
    for (int pass = 0; pass < 3; pass++) {
      const __nv_bfloat16* A = Ap[pass];
      const __nv_bfloat16* B = Bp[pass];
      #pragma unroll
      for (int ds = 0; ds < 4; ds++) {
        int d0 = ds * 16 + lc * 2;
        uint32_t a0 = *(const uint32_t*)(A + (mq + lr) * PASTR + d0);
        uint32_t a1 = *(const uint32_t*)(A + (mq + 8 + lr) * PASTR + d0);
        uint32_t a2 = *(const uint32_t*)(A + (mq + lr) * PASTR + d0 + 8);
        uint32_t a3 = *(const uint32_t*)(A + (mq + 8 + lr) * PASTR + d0 + 8);
        #pragma unroll
        for (int nt = 0; nt < 8; nt++) {
          const __nv_bfloat16* br = B + (db + nt * 8 + lr) * PASTR + d0;
          uint32_t b0 = *(const uint32_t*)(br);
          uint32_t b1 = *(const uint32_t*)(br + 8);
          mma_bf16(c[nt], a0, a1, a2, a3, b0, b1);
        }
      }
    }
  }
  float ssl = 0.0f, ssh = 0.0f;
  #pragma unroll
  for (int nt = 0; nt < 8; nt++) {
    int d = db + nt * 8 + lc * 2;
    float b0 = bias[d], b1 = bias[d + 1];
    c[nt][0] += b0; c[nt][1] += b1;
    c[nt][2] += b0; c[nt][3] += b1;
    ssl = fmaf(c[nt][0], c[nt][0], fmaf(c[nt][1], c[nt][1], ssl));
    ssh = fmaf(c[nt][2], c[nt][2], fmaf(c[nt][3], c[nt][3], ssh));
  }
  ssl += __shfl_xor_sync(0xffffffffu, ssl, 1);
  ssl += __shfl_xor_sync(0xffffffffu, ssl, 2);
  ssh += __shfl_xor_sync(0xffffffffu, ssh, 1);
  ssh += __shfl_xor_sync(0xffffffffu, ssh, 2);
  __syncthreads();
  if (lc == 0) {
    red[(mq + lr) * 2 + (w >> 2)]     = ssl;
    red[(mq + 8 + lr) * 2 + (w >> 2)] = ssh;
  }
  __syncthreads();
  float sl = 1.0f / fmaxf(sqrtf(red[(mq + lr) * 2] + red[(mq + lr) * 2 + 1]), 1e-12f);
  float sh = 1.0f / fmaxf(sqrtf(red[(mq + 8 + lr) * 2] + red[(mq + 8 + lr) * 2 + 1]), 1e-12f);
  size_t rb0 = ((size_t)s * NT + tg0 + mq + lr) * KD;
  size_t rb1 = ((size_t)s * NT + tg0 + mq + 8 + lr) * KD;
  #pragma unroll
  for (int nt = 0; nt < 8; nt++) {
    int d = db + nt * 8 + lc * 2;
    float v0 = c[nt][0] * sl, v1 = c[nt][1] * sl;
    float v2 = c[nt][2] * sh, v3 = c[nt][3] * sh;
    __nv_bfloat16 h0 = __float2bfloat16(v0), h1 = __float2bfloat16(v1);
    __nv_bfloat16 h2 = __float2bfloat16(v2), h3 = __float2bfloat16(v3);
    uint32_t uh0 = (uint32_t)__bfloat16_as_ushort(h0) | ((uint32_t)__bfloat16_as_ushort(h1) << 16);
    uint32_t uh1 = (uint32_t)__bfloat16_as_ushort(h2) | ((uint32_t)__bfloat16_as_ushort(h3) << 16);
    __nv_bfloat16 l0 = __float2bfloat16(v0 - __bfloat162float(h0));
    __nv_bfloat16 l1 = __float2bfloat16(v1 - __bfloat162float(h1));
    __nv_bfloat16 l2 = __float2bfloat16(v2 - __bfloat162float(h2));
    __nv_bfloat16 l3 = __float2bfloat16(v3 - __bfloat162float(h3));
    uint32_t ul0 = (uint32_t)__bfloat16_as_ushort(l0) | ((uint32_t)__bfloat16_as_ushort(l1) << 16);
    uint32_t ul1 = (uint32_t)__bfloat16_as_ushort(l2) | ((uint32_t)__bfloat16_as_ushort(l3) << 16);
    *(uint32_t*)(out_hi + rb0 + d) = uh0;
    *(uint32_t*)(out_hi + rb1 + d) = uh1;
    *(uint32_t*)(out_lo + rb0 + d) = ul0;
    *(uint32_t*)(out_lo + rb1 + d) = ul1;
  }
}

// ================= self-attention scores via HMMA (x30) =================
#define SQSTR 136
#define SOFF_AH 0
#define SOFF_AL 17408
#define SOFF_BH 34816
#define SOFF_BL 52224
#define SMEM_SS 69632

__global__ __launch_bounds__(256) void self_scores_mma(
    const __nv_bfloat16* __restrict__ qhi, const __nv_bfloat16* __restrict__ qlo,
    float* __restrict__ sc) {
  extern __shared__ char sms[];
  __nv_bfloat16* Ah = (__nv_bfloat16*)(sms + SOFF_AH);
  __nv_bfloat16* Al = (__nv_bfloat16*)(sms + SOFF_AL);
  __nv_bfloat16* Bh = (__nv_bfloat16*)(sms + SOFF_BH);
  __nv_bfloat16* Bl = (__nv_bfloat16*)(sms + SOFF_BL);
  int s = blockIdx.z;
  int q0 = blockIdx.x * 64, k0 = blockIdx.y * 64;
  int t = threadIdx.x;
  int w = t >> 5, lane = t & 31;
  int lr = lane >> 2, lc = lane & 3;
  {
    const uint4* gah = (const uint4*)(qhi + ((size_t)s * HW + q0) * KD);
    const uint4* gal = (const uint4*)(qlo + ((size_t)s * HW + q0) * KD);
    const uint4* gbh = (const uint4*)(qhi + ((size_t)s * HW + k0) * KD);
    const uint4* gbl = (const uint4*)(qlo + ((size_t)s * HW + k0) * KD);
    #pragma unroll
    for (int r = 0; r < 4; r++) {
      int idx = t + r * 256;
      int row = idx >> 4, u8 = (idx & 15) * 8;
      *(uint4*)(Ah + row * SQSTR + u8) = gah[idx];
      *(uint4*)(Al + row * SQSTR + u8) = gal[idx];
      *(uint4*)(Bh + row * SQSTR + u8) = gbh[idx];
      *(uint4*)(Bl + row * SQSTR + u8) = gbl[idx];
    }
  }
  __syncthreads();
  int mq = (w & 3) * 16;
  int kb = (w >> 2) * 32;
  float c[4][4];
  #pragma unroll
  for (int nt = 0; nt < 4; nt++)
    #pragma unroll
    for (int j = 0; j < 4; j++) c[nt][j] = 0.0f;
  const __nv_bfloat16* Ap[3] = {Ah, Al, Ah};
  const __nv_bfloat16* Bp[3] = {Bh, Bh, Bl};
  #pragma unroll
  for (int pass = 0; pass < 3; pass++) {
    const __nv_bfloat16* A = Ap[pass];
    const __nv_bfloat16* B = Bp[pass];
    #pragma unroll
    for (int ds = 0; ds < 8; ds++) {
      int d0 = ds * 16 + lc * 2;
      uint32_t a0 = *(const uint32_t*)(A + (mq + lr) * SQSTR + d0);
      uint32_t a1 = *(const uint32_t*)(A + (mq + 8 + lr) * SQSTR + d0);
      uint32_t a2 = *(const uint32_t*)(A + (mq + lr) * SQSTR + d0 + 8);
      uint32_t a3 = *(const uint32_t*)(A + (mq + 8 + lr) * SQSTR + d0 + 8);
      #pragma unroll
      for (int nt = 0; nt < 4; nt++) {
        const __nv_bfloat16* br = B + (kb + nt * 8 + lr) * SQSTR + d0;
        uint32_t b0 = *(const uint32_t*)(br);
        uint32_t b1 = *(const uint32_t*)(br + 8);
        mma_bf16(c[nt], a0, a1, a2, a3, b0, b1);
      }
    }
  }
  #pragma unroll
  for (int nt = 0; nt < 4; nt++) {
    int col = k0 + kb + nt * 8 + lc * 2;
    size_t g0 = ((size_t)s * HW + q0 + mq + lr) * HW + col;
    size_t g1 = ((size_t)s * HW + q0 + mq + 8 + lr) * HW + col;
    *(float2*)(sc + g0) = make_float2(c[nt][0] * 30.0f, c[nt][1] * 30.0f);
    *(float2*)(sc + g1) = make_float2(c[nt][2] * 30.0f, c[nt][3] * 30.0f);
  }
}

// ================= row softmax, static max = 30, emit bf16 hi/lo =================
__global__ __launch_bounds__(256) void softmax_kernel(
    const float* __restrict__ sc,
    __nv_bfloat16* __restrict__ phi, __nv_bfloat16* __restrict__ plo) {
  __shared__ float reds[8];
  const float* p = sc + (size_t)blockIdx.x * HW;
  size_t ob = (size_t)blockIdx.x * HW;
  int t = threadIdx.x, lane = t & 31, warp = t >> 5;
  float v0 = __expf(p[t] - 30.0f),       v1 = __expf(p[t + 256] - 30.0f);
  float v2 = __expf(p[t + 512] - 30.0f), v3 = __expf(p[t + 768] - 30.0f);
  float sum = v0 + v1 + v2 + v3;
  #pragma unroll
  for (int o = 16; o; o >>= 1) sum += __shfl_xor_sync(0xffffffffu, sum, o);
  if (lane == 0) reds[warp] = sum;
  __syncthreads();
  float tot = reds[0];
  #pragma unroll
  for (int i = 1; i < 8; i++) tot += reds[i];
  float inv = 1.0f / tot;
  v0 *= inv; v1 *= inv; v2 *= inv; v3 *= inv;
  __nv_bfloat16 h0 = __float2bfloat16(v0), h1 = __float2bfloat16(v1);
  __nv_bfloat16 h2 = __float2bfloat16(v2), h3 = __float2bfloat16(v3);
  phi[ob + t] = h0; phi[ob + t + 256] = h1;
  phi[ob + t + 512] = h2; phi[ob + t + 768] = h3;
  plo[ob + t]       = __float2bfloat16(v0 - __bfloat162float(h0));
  plo[ob + t + 256] = __float2bfloat16(v1 - __bfloat162float(h1));
  plo[ob + t + 512] = __float2bfloat16(v2 - __bfloat162float(h2));
  plo[ob + t + 768] = __float2bfloat16(v3 - __bfloat162float(h3));
}

// ================= split tgt into bf16 hi/lo =================
__global__ __launch_bounds__(256) void split_v_kernel(
    const float* __restrict__ x,
    __nv_bfloat16* __restrict__ hi, __nv_bfloat16* __restrict__ lo) {
  int i = blockIdx.x * 1024 + threadIdx.x;
  #pragma unroll
  for (int r = 0; r < 4; r++, i += 256) {
    float v = x[i];
    __nv_bfloat16 h = __float2bfloat16(v);
    hi[i] = h;
    lo[i] = __float2bfloat16(v - __bfloat162float(h));
  }
}

// ================= self P.V via HMMA + residual =================
#define CSTR 133
#define SMEM_PV 55296

__global__ __launch_bounds__(256) void pv_mma_kernel(
    const __nv_bfloat16* __restrict__ phi, const __nv_bfloat16* __restrict__ plo,
    const __nv_bfloat16* __restrict__ vhi, const __nv_bfloat16* __restrict__ vlo,
    const float* __restrict__ tgt, float* __restrict__ tout) {
  extern __shared__ char smv[];
  __nv_bfloat16* Ah = (__nv_bfloat16*)(smv + POFF_AH);
  __nv_bfloat16* Al = (__nv_bfloat16*)(smv + POFF_AL);
  __nv_bfloat16* Bh = (__nv_bfloat16*)(smv + POFF_BH);
  __nv_bfloat16* Bl = (__nv_bfloat16*)(smv + POFF_BL);
  float* Cs = (float*)smv;
  int s = blockIdx.z;
  int n0 = blockIdx.x * 64, c0 = blockIdx.y * 128;
  int t = threadIdx.x;
  int w = t >> 5, lane = t & 31;
  int lr = lane >> 2, lc = lane & 3;
  int mq = (w & 3) * 16;
  int db = (w >> 2) * 64;
  float c[8][4];
  #pragma unroll
  for (int nt = 0; nt < 8; nt++)
    #pragma unroll
    for (int j = 0; j < 4; j++) c[nt][j] = 0.0f;

  for (int m0 = 0; m0 < HW; m0 += 64) {
    __syncthreads();
    {
      const __nv_bfloat16* gph = phi + ((size_t)s * HW + n0) * HW + m0;
      const __nv_bfloat16* gpl = plo + ((size_t)s * HW + n0) * HW + m0;
      #pragma unroll
      for (int r = 0; r < 2; r++) {
        int idx = t + r * 256;
        int row = idx >> 3, u4 = (idx & 7) * 8;
        *(uint4*)(Ah + row * PASTR + u4) = *(const uint4*)(gph + (size_t)row * HW + u4);
        *(uint4*)(Al + row * PASTR + u4) = *(const uint4*)(gpl + (size_t)row * HW + u4);
      }
    }
    {
      const __nv_bfloat16* gvh = vhi + ((size_t)s * CD + c0) * HW + m0;
      const __nv_bfloat16* gvl = vlo + ((size_t)s * CD + c0) * HW + m0;
      #pragma unroll
      for (int r = 0; r < 4; r++) {
        int idx = t + r * 256;
        int row = idx >> 3, u4 = (idx & 7) * 8;
        *(uint4*)(Bh + row * PASTR + u4) = *(const uint4*)(gvh + (size_t)row * HW + u4);
        *(uint4*)(Bl + row * PASTR + u4) = *(const uint4*)(gvl + (size_t)row * HW + u4);
      }
    }
    __syncthreads();
    const __nv_bfloat16* Ap[3] = {Ah, Al, Ah};
    const __nv_bfloat16* Bp[3] = {Bh, Bh, Bl};
    #pragma unroll
    for (int pass = 0; pass < 3; pass++) {
      const __nv_bfloat16* A = Ap[pass];
      const __nv_bfloat16* B = Bp[pass];
      #pragma unroll
      for (int ds = 0; ds < 4; ds++) {
        int d0 = ds * 16 + lc * 2;
        uint32_t a0 = *(const uint32_t*)(A + (mq + lr) * PASTR + d0);
        uint32_t a1 = *(const uint32_t*)(A + (mq + 8 + lr) * PASTR + d0);
        uint32_t a2 = *(const uint32_t*)(A + (mq + lr) * PASTR + d0 + 8);
        uint32_t a3 = *(const uint32_t*)(A + (mq + 8 + lr) * PASTR + d0 + 8);
        #pragma unroll
        for (int nt = 0; nt < 8; nt++) {
          const __nv_bfloat16* br = B + (db + nt * 8 + lr) * PASTR + d0;
          uint32_t b0 = *(const uint32_t*)(br);
          uint32_t b1 = *(const uint32_t*)(br + 8);
          mma_bf16(c[nt], a0, a1, a2, a3, b0, b1);
        }
      }
    }
  }
  __syncthreads();
  #pragma unroll
  for (int nt = 0; nt < 8; nt++) {
    int col = db + nt * 8 + lc * 2;
    Cs[(mq + lr) * CSTR + col]         = c[nt][0];
    Cs[(mq + lr) * CSTR + col + 1]     = c[nt][1];
    Cs[(mq + 8 + lr) * CSTR + col]     = c[nt][2];
    Cs[(mq + 8 + lr) * CSTR + col + 1] = c[nt][3];
  }
  __syncthreads();
  #pragma unroll
  for (int r = 0; r < 32; r++) {
    int idx = t + r * 256;
    int cc = idx >> 6, n = idx & 63;
    size_t g = (size_t)(s * CD + c0 + cc) * HW + n0 + n;
    tout[g] = tgt[g] + Cs[n * CSTR + cc];
  }
}

// ================= instance norm =================
__global__ __launch_bounds__(256) void instnorm_kernel(float* __restrict__ x) {
  __shared__ float redS[8];
  __shared__ float redQ[8];
  float* p = x + (size_t)blockIdx.x * HW;
  int t = threadIdx.x, lane = t & 31, warp = t >> 5;
  float v0 = p[t], v1 = p[t + 256], v2 = p[t + 512], v3 = p[t + 768];
  float sum = v0 + v1 + v2 + v3;
  float sq = v0 * v0 + v1 * v1 + v2 * v2 + v3 * v3;
  #pragma unroll
  for (int o = 16; o; o >>= 1) {
    sum += __shfl_xor_sync(0xffffffffu, sum, o);
    sq  += __shfl_xor_sync(0xffffffffu, sq, o);
  }
  if (lane == 0) { redS[warp] = sum; redQ[warp] = sq; }
  __syncthreads();
  sum = redS[0]; sq = redQ[0];
  #pragma unroll
  for (int i = 1; i < 8; i++) { sum += redS[i]; sq += redQ[i]; }
  float mean = sum * (1.0f / HW);
  float var = sq * (1.0f / HW) - mean * mean;
  float rstd = rsqrtf(var + 1e-5f);
  p[t]       = (v0 - mean) * rstd;
  p[t + 256] = (v1 - mean) * rstd;
  p[t + 512] = (v2 - mean) * rstd;
  p[t + 768] = (v3 - mean) * rstd;
}

// ================= cross attention: HMMA split-bf16 scores =================
#define QSTR 136
#define PSTR 132
#define OFF_QH 0
#define OFF_QL 17408
#define OFF_KH 34816
#define OFF_KL 69632
#define OFF_PS 104448
#define OFF_VS 138240
#define OFF_OL 146432
#define OFF_PR 146688
#define SMEM_CROSS 147712

__global__ __launch_bounds__(256, 1) void cross_attn_kernel(
    const __nv_bfloat16* __restrict__ qhi, const __nv_bfloat16* __restrict__ qlo,
    const __nv_bfloat16* __restrict__ khi, const __nv_bfloat16* __restrict__ klo,
    const float* __restrict__ pe, float* __restrict__ part) {
  extern __shared__ char smc[];
  __nv_bfloat16* Qh = (__nv_bfloat16*)(smc + OFF_QH);
  __nv_bfloat16* Ql = (__nv_bfloat16*)(smc + OFF_QL);
  __nv_bfloat16* Kh = (__nv_bfloat16*)(smc + OFF_KH);
  __nv_bfloat16* Kl = (__nv_bfloat16*)(smc + OFF_KL);
  float* Ps   = (float*)(smc + OFF_PS);
  float* Vs   = (float*)(smc + OFF_VS);
  float* Ol   = (float*)(smc + OFF_OL);
  float* Pred = (float*)(smc + OFF_PR);
  int qt = blockIdx.x, s = blockIdx.y, ksp = blockIdx.z;
  int q0 = qt * 64;
  int t = threadIdx.x;
  int w = t >> 5, lane = t & 31;
  int lr = lane >> 2, lc = lane & 3;

  {
    const uint4* gqh = (const uint4*)(qhi + ((size_t)s * HW + q0) * KD);
    const uint4* gql = (const uint4*)(qlo + ((size_t)s * HW + q0) * KD);
    #pragma unroll
    for (int r = 0; r < 4; r++) {
      int idx = t + r * 256;
      int row = idx >> 4, u8 = (idx & 15) * 8;
      *(uint4*)(Qh + row * QSTR + u8) = gqh[idx];
      *(uint4*)(Ql + row * QSTR + u8) = gql[idx];
    }
  }
  if (t < 64) Ol[t] = 0.0f;

  int mq = (w & 3) * 16;
  int kb = (w >> 2) * 64;
  int pq = t >> 2, pve = (t & 3) * 4;
  float4 o = make_float4(0.f, 0.f, 0.f, 0.f);

  for (int kt = 0; kt < NM / (KSPLIT * 128); kt++) {
    int kk0 = ksp * (NM / KSPLIT) + kt * 128;
    __syncthreads();
    {
      const uint4* gh = (const uint4*)(khi + ((size_t)s * NM + kk0) * KD);
      const uint4* gl = (const uint4*)(klo + ((size_t)s * NM + kk0) * KD);
      #pragma unroll
      for (int r = 0; r < 8; r++) {
        int idx = t + r * 256;
        int key = idx >> 4, d8 = (idx & 15) * 8;
        *(uint4*)(Kh + key * QSTR + d8) = gh[idx];
        *(uint4*)(Kl + key * QSTR + d8) = gl[idx];
      }
    }
    {
      int f = kk0 >> 10, nn0 = kk0 & 1023;
      const float* pb = pe + ((size_t)(f * S4 + s)) * CE * HW + nn0;
      #pragma unroll
      for (int r = 0; r < 8; r++) {
        int idx = t + r * 256;
        int e = idx >> 7, k = idx & 127;
        Vs[k * 16 + e] = pb[(size_t)e * HW + k];
      }
    }
    __syncthreads();
    float c[8][4];
    #pragma unroll
    for (int nt = 0; nt < 8; nt++)
      #pragma unroll
      for (int j = 0; j < 4; j++) c[nt][j] = 0.0f;
    const __nv_bfloat16* Ap[3] = {Qh, Ql, Qh};
    const __nv_bfloat16* Bp[3] = {Kh, Kh, Kl};
    #pragma unroll
    for (int pass = 0; pass < 3; pass++) {
      const __nv_bfloat16* A = Ap[pass];
      const __nv_bfloat16* B = Bp[pass];
      #pragma unroll
      for (int ds = 0; ds < 8; ds++) {
        int d0 = ds * 16 + lc * 2;
        uint32_t a0 = *(const uint32_t*)(A + (mq + lr) * QSTR + d0);
        uint32_t a1 = *(const uint32_t*)(A + (mq + 8 + lr) * QSTR + d0);
        uint32_t a2 = *(const uint32_t*)(A + (mq + lr) * QSTR + d0 + 8);
        uint32_t a3 = *(const uint32_t*)(A + (mq + 8 + lr) * QSTR + d0 + 8);
        #pragma unroll
        for (int nt = 0; nt < 8; nt++) {
          const __nv_bfloat16* br = B + (kb + nt * 8 + lr) * QSTR + d0;
          uint32_t b0 = *(const uint32_t*)(br);
          uint32_t b1 = *(const uint32_t*)(br + 8);
          mma_bf16(c[nt], a0, a1, a2, a3, b0, b1);
        }
      }
    }
    float sl = 0.0f, sh = 0.0f;
    #pragma unroll
    for (int nt = 0; nt < 8; nt++) {
      float e0 = __expf(fmaf(c[nt][0], 30.0f, -30.0f));
      float e1 = __expf(fmaf(c[nt][1], 30.0f, -30.0f));
      float e2 = __expf(fmaf(c[nt][2], 30.0f, -30.0f));
      float e3 = __expf(fmaf(c[nt][3], 30.0f, -30.0f));
      int col = kb + nt * 8 + lc * 2;
      *(float2*)(Ps + (mq + lr) * PSTR + col)     = make_float2(e0, e1);
      *(float2*)(Ps + (mq + 8 + lr) * PSTR + col) = make_float2(e2, e3);
      sl += e0 + e1; sh += e2 + e3;
    }
    sl += __shfl_xor_sync(0xffffffffu, sl, 1);
    sl += __shfl_xor_sync(0xffffffffu, sl, 2);
    sh += __shfl_xor_sync(0xffffffffu, sh, 1);
    sh += __shfl_xor_sync(0xffffffffu, sh, 2);
    if (lc == 0) {
      Pred[(mq + lr) * 4 + (w >> 2)]     = sl;
      Pred[(mq + 8 + lr) * 4 + (w >> 2)] = sh;
    }
    __syncthreads();
    if (t < 64) Ol[t] += Pred[t * 4] + Pred[t * 4 + 1];
    {
      const float* prow = Ps + pq * PSTR;
      const float* vb = Vs + pve;
      #pragma unroll 8
      for (int k = 0; k < 128; k++) {
        float p = prow[k];
        float4 v = *(const float4*)(vb + k * 16);
        o.x = fmaf(p, v.x, o.x); o.y = fmaf(p, v.y, o.y);
        o.z = fmaf(p, v.z, o.z); o.w = fmaf(p, v.w, o.w);
      }
    }
  }
  __syncthreads();
  {
    float* pp = part + ((size_t)((ksp * S4 + s) * HW) + q0 + pq) * 18;
    pp[pve + 0] = o.x; pp[pve + 1] = o.y;
    pp[pve + 2] = o.z; pp[pve + 3] = o.w;
    if ((t & 3) == 0) pp[16] = Ol[pq];
  }
}

// ================= merge split-K partials + sigmoid =================
__global__ __launch_bounds__(256) void merge_kernel(
    const float* __restrict__ part, float* __restrict__ out) {
  int g = blockIdx.x * 256 + threadIdx.x;
  int eg = (g & 3) * 4;
  int sn = g >> 2;
  int n = sn & 1023, s = sn >> 10;
  float L = 0.0f;
  float O[4] = {};
  #pragma unroll
  for (int z = 0; z < KSPLIT; z++) {
    const float* pp = part + ((size_t)((z * S4 + s) * HW) + n) * 18;
    L += pp[16];
    #pragma unroll
    for (int e = 0; e < 4; e++) O[e] += pp[eg + e];
  }
  float inv = 1.0f / L;
  #pragma unroll
  for (int e = 0; e < 4; e++) {
    float v = O[e] * inv;
    out[(size_t)(s * CE + eg + e) * HW + n] = 1.0f / (1.0f + __expf(-v));
  }
}

// ================= host =================
extern "C" void kernel_launch(void* const* d_in, const int* in_sizes, int n_in,
                              void* d_out, int out_size) {
  const float* tgt = (const float*)d_in[0];
  const float* mem = (const float*)d_in[1];
  const float* pe  = (const float*)d_in[2];
  const float* wks = (const float*)d_in[3];
  const float* bks = (const float*)d_in[4];
  const float* wkc = (const float*)d_in[5];
  const float* bkc = (const float*)d_in[6];
  float* out = (float*)d_out;

  float *p_sc, *p_t, *p_part;
  __nv_bfloat16 *p_wk_hi, *p_wk_lo, *p_p_hi, *p_p_lo, *p_v_hi, *p_v_lo;
  __nv_bfloat16 *p_qs_hi, *p_qs_lo, *p_qc_hi, *p_qc_lo;
  cudaGetSymbolAddress((void**)&p_sc, g_sc);
  cudaGetSymbolAddress((void**)&p_t, g_t);
  cudaGetSymbolAddress((void**)&p_wk_hi, g_wk_hi);
  cudaGetSymbolAddress((void**)&p_wk_lo, g_wk_lo);
  cudaGetSymbolAddress((void**)&p_p_hi, g_p_hi);
  cudaGetSymbolAddress((void**)&p_p_lo, g_p_lo);
  cudaGetSymbolAddress((void**)&p_v_hi, g_v_hi);
  cudaGetSymbolAddress((void**)&p_v_lo, g_v_lo);
  cudaGetSymbolAddress((void**)&p_qs_hi, g_qs_hi);
  cudaGetSymbolAddress((void**)&p_qs_lo, g_qs_lo);
  cudaGetSymbolAddress((void**)&p_qc_hi, g_qc_hi);
  cudaGetSymbolAddress((void**)&p_qc_lo, g_qc_lo);
  cudaGetSymbolAddress((void**)&p_part, g_part);

  cudaFuncSetAttribute(proj_mma_kernel,
                       cudaFuncAttributeMaxDynamicSharedMemorySize, SMEM_PROJ);
  cudaFuncSetAttribute(self_scores_mma,
                       cudaFuncAttributeMaxDynamicSharedMemorySize, SMEM_SS);
  cudaFuncSetAttribute(pv_mma_kernel,
                       cudaFuncAttributeMaxDynamicSharedMemorySize, SMEM_PV);
  cudaFuncSetAttribute(cross_attn_kernel,
                       cudaFuncAttributeMaxDynamicSharedMemorySize, SMEM_CROSS);

  // self-attention
  proj_mma_kernel<<<dim3(16, 4), 256, SMEM_PROJ>>>(tgt, wks, bks, p_qs_hi, p_qs_lo, HW);
  self_scores_mma<<<dim3(16, 16, 4), 256, SMEM_SS>>>(p_qs_hi, p_qs_lo, p_sc);
  softmax_kernel<<<4096, 256>>>(p_sc, p_p_hi, p_p_lo);
  split_v_kernel<<<2048, 256>>>(tgt, p_v_hi, p_v_lo);
  pv_mma_kernel<<<dim3(16, 4, 4), 256, SMEM_PV>>>(p_p_hi, p_p_lo, p_v_hi, p_v_lo, tgt, p_t);
  instnorm_kernel<<<2048, 256>>>(p_t);

  // cross projections (all HMMA)
  proj_mma_kernel<<<dim3(16, 4), 256, SMEM_PROJ>>>(p_t, wkc, bkc, p_qc_hi, p_qc_lo, HW);
  proj_mma_kernel<<<dim3(256, 4), 256, SMEM_PROJ>>>(mem, wkc, bkc, p_wk_hi, p_wk_lo, NM);

  // HMMA cross-attention
  cross_attn_kernel<<<dim3(16, 4, KSPLIT), 256, SMEM_CROSS>>>(
      p_qc_hi, p_qc_lo, p_wk_hi, p_wk_lo, pe, p_part);
  merge_kernel<<<64, 256>>>(p_part, out);
}

// round 12
// speedup vs baseline: 2.1107x; 1.2215x over previous
#include <cuda_runtime.h>
#include <cuda_bf16.h>
#include <math.h>
#include <stdint.h>

#define S4 4
#define CD 512
#define KD 128
#define HW 1024
#define NM 16384
#define CE 16
#define KSPLIT 16

// ---------------- scratch ----------------
__device__ float g_sc[S4 * HW * HW];
__device__ __nv_bfloat16 g_p_hi[S4 * HW * HW];
__device__ __nv_bfloat16 g_p_lo[S4 * HW * HW];
__device__ __nv_bfloat16 g_v_hi[S4 * CD * HW];
__device__ __nv_bfloat16 g_v_lo[S4 * CD * HW];
__device__ float g_t[S4 * CD * HW];
__device__ __nv_bfloat16 g_qs_hi[S4 * HW * KD];
__device__ __nv_bfloat16 g_qs_lo[S4 * HW * KD];
__device__ __nv_bfloat16 g_qc_hi[S4 * HW * KD];
__device__ __nv_bfloat16 g_qc_lo[S4 * HW * KD];
__device__ __nv_bfloat16 g_wk_hi[S4 * NM * KD];
__device__ __nv_bfloat16 g_wk_lo[S4 * NM * KD];
__device__ float g_part[KSPLIT * S4 * HW * 18];

__device__ __forceinline__ void mma_bf16(float* c, uint32_t a0, uint32_t a1,
                                         uint32_t a2, uint32_t a3,
                                         uint32_t b0, uint32_t b1) {
  asm("mma.sync.aligned.m16n8k16.row.col.f32.bf16.bf16.f32 "
      "{%0,%1,%2,%3}, {%4,%5,%6,%7}, {%8,%9}, {%0,%1,%2,%3};"
      : "+f"(c[0]), "+f"(c[1]), "+f"(c[2]), "+f"(c[3])
      : "r"(a0), "r"(a1), "r"(a2), "r"(a3), "r"(b0), "r"(b1));
}
__device__ __forceinline__ uint32_t pack_hi2(float a, float b, float& la, float& lb) {
  __nv_bfloat16 h0 = __float2bfloat16(a), h1 = __float2bfloat16(b);
  la = a - __bfloat162float(h0);
  lb = b - __bfloat162float(h1);
  return (uint32_t)__bfloat16_as_ushort(h0) | ((uint32_t)__bfloat16_as_ushort(h1) << 16);
}
__device__ __forceinline__ uint32_t pack_bf2(float a, float b) {
  __nv_bfloat16 h0 = __float2bfloat16(a), h1 = __float2bfloat16(b);
  return (uint32_t)__bfloat16_as_ushort(h0) | ((uint32_t)__bfloat16_as_ushort(h1) << 16);
}

// ================= HMMA projection + L2 normalize -> bf16 hi/lo =================
#define PASTR 72
#define POFF_AH 0
#define POFF_AL 9216
#define POFF_BH 18432
#define POFF_BL 36864
#define POFF_RED 55296
#define SMEM_PROJ 55808

__global__ __launch_bounds__(256, 1) void proj_mma_kernel(
    const float* __restrict__ in, const float* __restrict__ W,
    const float* __restrict__ bias,
    __nv_bfloat16* __restrict__ out_hi, __nv_bfloat16* __restrict__ out_lo,
    int NT) {
  extern __shared__ char smp[];
  __nv_bfloat16* Ah = (__nv_bfloat16*)(smp + POFF_AH);
  __nv_bfloat16* Al = (__nv_bfloat16*)(smp + POFF_AL);
  __nv_bfloat16* Bh = (__nv_bfloat16*)(smp + POFF_BH);
  __nv_bfloat16* Bl = (__nv_bfloat16*)(smp + POFF_BL);
  float* red = (float*)(smp + POFF_RED);
  int s = blockIdx.y;
  int tg0 = blockIdx.x * 64;
  int f = tg0 >> 10;
  int n0 = tg0 & 1023;
  const float* inb = in + ((size_t)(f * S4 + s)) * CD * HW + n0;
  int t = threadIdx.x;
  int w = t >> 5, lane = t & 31;
  int lr = lane >> 2, lc = lane & 3;
  int mq = (w & 3) * 16;
  int db = (w >> 2) * 64;
  float c[8][4];
  #pragma unroll
  for (int nt = 0; nt < 8; nt++)
    #pragma unroll
    for (int j = 0; j < 4; j++) c[nt][j] = 0.0f;

  for (int c0 = 0; c0 < CD; c0 += 64) {
    __syncthreads();
    #pragma unroll
    for (int r = 0; r < 16; r++) {
      int idx = t + r * 256;
      int tok = idx & 63, cc = idx >> 6;
      float v = inb[(size_t)(c0 + cc) * HW + tok];
      __nv_bfloat16 h = __float2bfloat16(v);
      Ah[tok * PASTR + cc] = h;
      Al[tok * PASTR + cc] = __float2bfloat16(v - __bfloat162float(h));
    }
    #pragma unroll
    for (int r = 0; r < 32; r++) {
      int idx = t + r * 256;
      int cc = idx & 63, d = idx >> 6;
      float v = W[d * CD + c0 + cc];
      __nv_bfloat16 h = __float2bfloat16(v);
      Bh[d * PASTR + cc] = h;
      Bl[d * PASTR + cc] = __float2bfloat16(v - __bfloat162float(h));
    }
    __syncthreads();
    const __nv_bfloat16* Ap[3] = {Ah, Al, Ah};
    const __nv_bfloat16* Bp[3] = {Bh, Bh, Bl};
    #pragma unroll
    for (int pass = 0; pass < 3; pass++) {
      const __nv_bfloat16* A = Ap[pass];
      const __nv_bfloat16* B = Bp[pass];
      #pragma unroll
      for (int ds = 0; ds < 4; ds++) {
        int d0 = ds * 16 + lc * 2;
        uint32_t a0 = *(const uint32_t*)(A + (mq + lr) * PASTR + d0);
        uint32_t a1 = *(const uint32_t*)(A + (mq + 8 + lr) * PASTR + d0);
        uint32_t a2 = *(const uint32_t*)(A + (mq + lr) * PASTR + d0 + 8);
        uint32_t a3 = *(const uint32_t*)(A + (mq + 8 + lr) * PASTR + d0 + 8);
        #pragma unroll
        for (int nt = 0; nt < 8; nt++) {
          const __nv_bfloat16* br = B + (db + nt * 8 + lr) * PASTR + d0;
          uint32_t b0 = *(const uint32_t*)(br);
          uint32_t b1 = *(const uint32_t*)(br + 8);
          mma_bf16(c[nt], a0, a1, a2, a3, b0, b1);
        }
      }
    }
  }
  float ssl = 0.0f, ssh = 0.0f;
  #pragma unroll
  for (int nt = 0; nt < 8; nt++) {
    int d = db + nt * 8 + lc * 2;
    float b0 = bias[d], b1 = bias[d + 1];
    c[nt][0] += b0; c[nt][1] += b1;
    c[nt][2] += b0; c[nt][3] += b1;
    ssl = fmaf(c[nt][0], c[nt][0], fmaf(c[nt][1], c[nt][1], ssl));
    ssh = fmaf(c[nt][2], c[nt][2], fmaf(c[nt][3], c[nt][3], ssh));
  }
  ssl += __shfl_xor_sync(0xffffffffu, ssl, 1);
  ssl += __shfl_xor_sync(0xffffffffu, ssl, 2);
  ssh += __shfl_xor_sync(0xffffffffu, ssh, 1);
  ssh += __shfl_xor_sync(0xffffffffu, ssh, 2);
  __syncthreads();
  if (lc == 0) {
    red[(mq + lr) * 2 + (w >> 2)]     = ssl;
    red[(mq + 8 + lr) * 2 + (w >> 2)] = ssh;
  }
  __syncthreads();
  float sl = 1.0f / fmaxf(sqrtf(red[(mq + lr) * 2] + red[(mq + lr) * 2 + 1]), 1e-12f);
  float sh = 1.0f / fmaxf(sqrtf(red[(mq + 8 + lr) * 2] + red[(mq + 8 + lr) * 2 + 1]), 1e-12f);
  size_t rb0 = ((size_t)s * NT + tg0 + mq + lr) * KD;
  size_t rb1 = ((size_t)s * NT + tg0 + mq + 8 + lr) * KD;
  #pragma unroll
  for (int nt = 0; nt < 8; nt++) {
    int d = db + nt * 8 + lc * 2;
    float v0 = c[nt][0] * sl, v1 = c[nt][1] * sl;
    float v2 = c[nt][2] * sh, v3 = c[nt][3] * sh;
    float l0, l1, l2, l3;
    uint32_t uh0 = pack_hi2(v0, v1, l0, l1);
    uint32_t uh1 = pack_hi2(v2, v3, l2, l3);
    uint32_t ul0 = pack_bf2(l0, l1);
    uint32_t ul1 = pack_bf2(l2, l3);
    *(uint32_t*)(out_hi + rb0 + d) = uh0;
    *(uint32_t*)(out_hi + rb1 + d) = uh1;
    *(uint32_t*)(out_lo + rb0 + d) = ul0;
    *(uint32_t*)(out_lo + rb1 + d) = ul1;
  }
}

// ================= self-attention scores via HMMA (x30) =================
#define SQSTR 136
#define SOFF_AH 0
#define SOFF_AL 17408
#define SOFF_BH 34816
#define SOFF_BL 52224
#define SMEM_SS 69632

__global__ __launch_bounds__(256) void self_scores_mma(
    const __nv_bfloat16* __restrict__ qhi, const __nv_bfloat16* __restrict__ qlo,
    float* __restrict__ sc) {
  extern __shared__ char sms[];
  __nv_bfloat16* Ah = (__nv_bfloat16*)(sms + SOFF_AH);
  __nv_bfloat16* Al = (__nv_bfloat16*)(sms + SOFF_AL);
  __nv_bfloat16* Bh = (__nv_bfloat16*)(sms + SOFF_BH);
  __nv_bfloat16* Bl = (__nv_bfloat16*)(sms + SOFF_BL);
  int s = blockIdx.z;
  int q0 = blockIdx.x * 64, k0 = blockIdx.y * 64;
  int t = threadIdx.x;
  int w = t >> 5, lane = t & 31;
  int lr = lane >> 2, lc = lane & 3;
  {
    const uint4* gah = (const uint4*)(qhi + ((size_t)s * HW + q0) * KD);
    const uint4* gal = (const uint4*)(qlo + ((size_t)s * HW + q0) * KD);
    const uint4* gbh = (const uint4*)(qhi + ((size_t)s * HW + k0) * KD);
    const uint4* gbl = (const uint4*)(qlo + ((size_t)s * HW + k0) * KD);
    #pragma unroll
    for (int r = 0; r < 4; r++) {
      int idx = t + r * 256;
      int row = idx >> 4, u8 = (idx & 15) * 8;
      *(uint4*)(Ah + row * SQSTR + u8) = gah[idx];
      *(uint4*)(Al + row * SQSTR + u8) = gal[idx];
      *(uint4*)(Bh + row * SQSTR + u8) = gbh[idx];
      *(uint4*)(Bl + row * SQSTR + u8) = gbl[idx];
    }
  }
  __syncthreads();
  int mq = (w & 3) * 16;
  int kb = (w >> 2) * 32;
  float c[4][4];
  #pragma unroll
  for (int nt = 0; nt < 4; nt++)
    #pragma unroll
    for (int j = 0; j < 4; j++) c[nt][j] = 0.0f;
  const __nv_bfloat16* Ap[3] = {Ah, Al, Ah};
  const __nv_bfloat16* Bp[3] = {Bh, Bh, Bl};
  #pragma unroll
  for (int pass = 0; pass < 3; pass++) {
    const __nv_bfloat16* A = Ap[pass];
    const __nv_bfloat16* B = Bp[pass];
    #pragma unroll
    for (int ds = 0; ds < 8; ds++) {
      int d0 = ds * 16 + lc * 2;
      uint32_t a0 = *(const uint32_t*)(A + (mq + lr) * SQSTR + d0);
      uint32_t a1 = *(const uint32_t*)(A + (mq + 8 + lr) * SQSTR + d0);
      uint32_t a2 = *(const uint32_t*)(A + (mq + lr) * SQSTR + d0 + 8);
      uint32_t a3 = *(const uint32_t*)(A + (mq + 8 + lr) * SQSTR + d0 + 8);
      #pragma unroll
      for (int nt = 0; nt < 4; nt++) {
        const __nv_bfloat16* br = B + (kb + nt * 8 + lr) * SQSTR + d0;
        uint32_t b0 = *(const uint32_t*)(br);
        uint32_t b1 = *(const uint32_t*)(br + 8);
        mma_bf16(c[nt], a0, a1, a2, a3, b0, b1);
      }
    }
  }
  #pragma unroll
  for (int nt = 0; nt < 4; nt++) {
    int col = k0 + kb + nt * 8 + lc * 2;
    size_t g0 = ((size_t)s * HW + q0 + mq + lr) * HW + col;
    size_t g1 = ((size_t)s * HW + q0 + mq + 8 + lr) * HW + col;
    *(float2*)(sc + g0) = make_float2(c[nt][0] * 30.0f, c[nt][1] * 30.0f);
    *(float2*)(sc + g1) = make_float2(c[nt][2] * 30.0f, c[nt][3] * 30.0f);
  }
}

// ================= row softmax, static max = 30, emit bf16 hi/lo =================
__global__ __launch_bounds__(256) void softmax_kernel(
    const float* __restrict__ sc,
    __nv_bfloat16* __restrict__ phi, __nv_bfloat16* __restrict__ plo) {
  __shared__ float reds[8];
  const float* p = sc + (size_t)blockIdx.x * HW;
  size_t ob = (size_t)blockIdx.x * HW;
  int t = threadIdx.x, lane = t & 31, warp = t >> 5;
  float v0 = __expf(p[t] - 30.0f),       v1 = __expf(p[t + 256] - 30.0f);
  float v2 = __expf(p[t + 512] - 30.0f), v3 = __expf(p[t + 768] - 30.0f);
  float sum = v0 + v1 + v2 + v3;
  #pragma unroll
  for (int o = 16; o; o >>= 1) sum += __shfl_xor_sync(0xffffffffu, sum, o);
  if (lane == 0) reds[warp] = sum;
  __syncthreads();
  float tot = reds[0];
  #pragma unroll
  for (int i = 1; i < 8; i++) tot += reds[i];
  float inv = 1.0f / tot;
  v0 *= inv; v1 *= inv; v2 *= inv; v3 *= inv;
  __nv_bfloat16 h0 = __float2bfloat16(v0), h1 = __float2bfloat16(v1);
  __nv_bfloat16 h2 = __float2bfloat16(v2), h3 = __float2bfloat16(v3);
  phi[ob + t] = h0; phi[ob + t + 256] = h1;
  phi[ob + t + 512] = h2; phi[ob + t + 768] = h3;
  plo[ob + t]       = __float2bfloat16(v0 - __bfloat162float(h0));
  plo[ob + t + 256] = __float2bfloat16(v1 - __bfloat162float(h1));
  plo[ob + t + 512] = __float2bfloat16(v2 - __bfloat162float(h2));
  plo[ob + t + 768] = __float2bfloat16(v3 - __bfloat162float(h3));
}

// ================= split tgt into bf16 hi/lo =================
__global__ __launch_bounds__(256) void split_v_kernel(
    const float* __restrict__ x,
    __nv_bfloat16* __restrict__ hi, __nv_bfloat16* __restrict__ lo) {
  int i = blockIdx.x * 1024 + threadIdx.x;
  #pragma unroll
  for (int r = 0; r < 4; r++, i += 256) {
    float v = x[i];
    __nv_bfloat16 h = __float2bfloat16(v);
    hi[i] = h;
    lo[i] = __float2bfloat16(v - __bfloat162float(h));
  }
}

// ================= self P.V via HMMA + residual =================
#define CSTR 133
#define SMEM_PV 55296

__global__ __launch_bounds__(256) void pv_mma_kernel(
    const __nv_bfloat16* __restrict__ phi, const __nv_bfloat16* __restrict__ plo,
    const __nv_bfloat16* __restrict__ vhi, const __nv_bfloat16* __restrict__ vlo,
    const float* __restrict__ tgt, float* __restrict__ tout) {
  extern __shared__ char smv[];
  __nv_bfloat16* Ah = (__nv_bfloat16*)(smv + POFF_AH);
  __nv_bfloat16* Al = (__nv_bfloat16*)(smv + POFF_AL);
  __nv_bfloat16* Bh = (__nv_bfloat16*)(smv + POFF_BH);
  __nv_bfloat16* Bl = (__nv_bfloat16*)(smv + POFF_BL);
  float* Cs = (float*)smv;
  int s = blockIdx.z;
  int n0 = blockIdx.x * 64, c0 = blockIdx.y * 128;
  int t = threadIdx.x;
  int w = t >> 5, lane = t & 31;
  int lr = lane >> 2, lc = lane & 3;
  int mq = (w & 3) * 16;
  int db = (w >> 2) * 64;
  float c[8][4];
  #pragma unroll
  for (int nt = 0; nt < 8; nt++)
    #pragma unroll
    for (int j = 0; j < 4; j++) c[nt][j] = 0.0f;

  for (int m0 = 0; m0 < HW; m0 += 64) {
    __syncthreads();
    {
      const __nv_bfloat16* gph = phi + ((size_t)s * HW + n0) * HW + m0;
      const __nv_bfloat16* gpl = plo + ((size_t)s * HW + n0) * HW + m0;
      #pragma unroll
      for (int r = 0; r < 2; r++) {
        int idx = t + r * 256;
        int row = idx >> 3, u4 = (idx & 7) * 8;
        *(uint4*)(Ah + row * PASTR + u4) = *(const uint4*)(gph + (size_t)row * HW + u4);
        *(uint4*)(Al + row * PASTR + u4) = *(const uint4*)(gpl + (size_t)row * HW + u4);
      }
    }
    {
      const __nv_bfloat16* gvh = vhi + ((size_t)s * CD + c0) * HW + m0;
      const __nv_bfloat16* gvl = vlo + ((size_t)s * CD + c0) * HW + m0;
      #pragma unroll
      for (int r = 0; r < 4; r++) {
        int idx = t + r * 256;
        int row = idx >> 3, u4 = (idx & 7) * 8;
        *(uint4*)(Bh + row * PASTR + u4) = *(const uint4*)(gvh + (size_t)row * HW + u4);
        *(uint4*)(Bl + row * PASTR + u4) = *(const uint4*)(gvl + (size_t)row * HW + u4);
      }
    }
    __syncthreads();
    const __nv_bfloat16* Ap[3] = {Ah, Al, Ah};
    const __nv_bfloat16* Bp[3] = {Bh, Bh, Bl};
    #pragma unroll
    for (int pass = 0; pass < 3; pass++) {
      const __nv_bfloat16* A = Ap[pass];
      const __nv_bfloat16* B = Bp[pass];
      #pragma unroll
      for (int ds = 0; ds < 4; ds++) {
        int d0 = ds * 16 + lc * 2;
        uint32_t a0 = *(const uint32_t*)(A + (mq + lr) * PASTR + d0);
        uint32_t a1 = *(const uint32_t*)(A + (mq + 8 + lr) * PASTR + d0);
        uint32_t a2 = *(const uint32_t*)(A + (mq + lr) * PASTR + d0 + 8);
        uint32_t a3 = *(const uint32_t*)(A + (mq + 8 + lr) * PASTR + d0 + 8);
        #pragma unroll
        for (int nt = 0; nt < 8; nt++) {
          const __nv_bfloat16* br = B + (db + nt * 8 + lr) * PASTR + d0;
          uint32_t b0 = *(const uint32_t*)(br);
          uint32_t b1 = *(const uint32_t*)(br + 8);
          mma_bf16(c[nt], a0, a1, a2, a3, b0, b1);
        }
      }
    }
  }
  __syncthreads();
  #pragma unroll
  for (int nt = 0; nt < 8; nt++) {
    int col = db + nt * 8 + lc * 2;
    Cs[(mq + lr) * CSTR + col]         = c[nt][0];
    Cs[(mq + lr) * CSTR + col + 1]     = c[nt][1];
    Cs[(mq + 8 + lr) * CSTR + col]     = c[nt][2];
    Cs[(mq + 8 + lr) * CSTR + col + 1] = c[nt][3];
  }
  __syncthreads();
  #pragma unroll
  for (int r = 0; r < 32; r++) {
    int idx = t + r * 256;
    int cc = idx >> 6, n = idx & 63;
    size_t g = (size_t)(s * CD + c0 + cc) * HW + n0 + n;
    tout[g] = tgt[g] + Cs[n * CSTR + cc];
  }
}

// ================= instance norm =================
__global__ __launch_bounds__(256) void instnorm_kernel(float* __restrict__ x) {
  __shared__ float redS[8];
  __shared__ float redQ[8];
  float* p = x + (size_t)blockIdx.x * HW;
  int t = threadIdx.x, lane = t & 31, warp = t >> 5;
  float v0 = p[t], v1 = p[t + 256], v2 = p[t + 512], v3 = p[t + 768];
  float sum = v0 + v1 + v2 + v3;
  float sq = v0 * v0 + v1 * v1 + v2 * v2 + v3 * v3;
  #pragma unroll
  for (int o = 16; o; o >>= 1) {
    sum += __shfl_xor_sync(0xffffffffu, sum, o);
    sq  += __shfl_xor_sync(0xffffffffu, sq, o);
  }
  if (lane == 0) { redS[warp] = sum; redQ[warp] = sq; }
  __syncthreads();
  sum = redS[0]; sq = redQ[0];
  #pragma unroll
  for (int i = 1; i < 8; i++) { sum += redS[i]; sq += redQ[i]; }
  float mean = sum * (1.0f / HW);
  float var = sq * (1.0f / HW) - mean * mean;
  float rstd = rsqrtf(var + 1e-5f);
  p[t]       = (v0 - mean) * rstd;
  p[t + 256] = (v1 - mean) * rstd;
  p[t + 512] = (v2 - mean) * rstd;
  p[t + 768] = (v3 - mean) * rstd;
}

// ================= cross attention: HMMA scores + fragment-recycled HMMA PV =================
#define QSTR 136
#define VSTR 136
#define OFF_QH 0
#define OFF_QL 17408
#define OFF_KH 34816
#define OFF_KL 69632
#define OFF_VTH 104448
#define OFF_VTL 108800
#define OFF_ACC 113152
#define OFF_PRED 117776
#define SMEM_CROSS 118288

__global__ __launch_bounds__(256, 1) void cross_attn_kernel(
    const __nv_bfloat16* __restrict__ qhi, const __nv_bfloat16* __restrict__ qlo,
    const __nv_bfloat16* __restrict__ khi, const __nv_bfloat16* __restrict__ klo,
    const float* __restrict__ pe, float* __restrict__ part) {
  extern __shared__ char smc[];
  __nv_bfloat16* Qh  = (__nv_bfloat16*)(smc + OFF_QH);
  __nv_bfloat16* Ql  = (__nv_bfloat16*)(smc + OFF_QL);
  __nv_bfloat16* Kh  = (__nv_bfloat16*)(smc + OFF_KH);
  __nv_bfloat16* Kl  = (__nv_bfloat16*)(smc + OFF_KL);
  __nv_bfloat16* Vth = (__nv_bfloat16*)(smc + OFF_VTH);
  __nv_bfloat16* Vtl = (__nv_bfloat16*)(smc + OFF_VTL);
  float* Acc  = (float*)(smc + OFF_ACC);    // [64][17]
  float* Pred = (float*)(smc + OFF_PRED);   // [64][2]
  int qt = blockIdx.x, s = blockIdx.y, ksp = blockIdx.z;
  int q0 = qt * 64;
  int t = threadIdx.x;
  int w = t >> 5, lane = t & 31;
  int lr = lane >> 2, lc = lane & 3;
  int mq = (w & 3) * 16;
  int half = w >> 2;
  int kb = half * 64;

  // load Q hi/lo
  {
    const uint4* gqh = (const uint4*)(qhi + ((size_t)s * HW + q0) * KD);
    const uint4* gql = (const uint4*)(qlo + ((size_t)s * HW + q0) * KD);
    #pragma unroll
    for (int r = 0; r < 4; r++) {
      int idx = t + r * 256;
      int row = idx >> 4, u8 = (idx & 15) * 8;
      *(uint4*)(Qh + row * QSTR + u8) = gqh[idx];
      *(uint4*)(Ql + row * QSTR + u8) = gql[idx];
    }
  }
  float cpv[2][4];
  #pragma unroll
  for (int et = 0; et < 2; et++)
    #pragma unroll
    for (int j = 0; j < 4; j++) cpv[et][j] = 0.0f;
  float slacc = 0.0f, shacc = 0.0f;

  for (int kt = 0; kt < NM / (KSPLIT * 128); kt++) {
    int kk0 = ksp * (NM / KSPLIT) + kt * 128;
    __syncthreads();
    // K hi/lo tiles
    {
      const uint4* gh = (const uint4*)(khi + ((size_t)s * NM + kk0) * KD);
      const uint4* gl = (const uint4*)(klo + ((size_t)s * NM + kk0) * KD);
      #pragma unroll
      for (int r = 0; r < 8; r++) {
        int idx = t + r * 256;
        int key = idx >> 4, d8 = (idx & 15) * 8;
        *(uint4*)(Kh + key * QSTR + d8) = gh[idx];
        *(uint4*)(Kl + key * QSTR + d8) = gl[idx];
      }
    }
    // V transposed: Vt[e][k] (coalesced from pe layout), split hi/lo
    {
      int f = kk0 >> 10, nn0 = kk0 & 1023;
      const float* pb = pe + ((size_t)(f * S4 + s)) * CE * HW + nn0;
      #pragma unroll
      for (int r = 0; r < 8; r++) {
        int idx = t + r * 256;
        int e = idx >> 7, k = idx & 127;
        float v = pb[(size_t)e * HW + k];
        __nv_bfloat16 h = __float2bfloat16(v);
        Vth[e * VSTR + k] = h;
        Vtl[e * VSTR + k] = __float2bfloat16(v - __bfloat162float(h));
      }
    }
    __syncthreads();
    // ---- scores via HMMA: 3 passes ----
    float c[8][4];
    #pragma unroll
    for (int nt = 0; nt < 8; nt++)
      #pragma unroll
      for (int j = 0; j < 4; j++) c[nt][j] = 0.0f;
    const __nv_bfloat16* Ap[3] = {Qh, Ql, Qh};
    const __nv_bfloat16* Bp[3] = {Kh, Kh, Kl};
    #pragma unroll
    for (int pass = 0; pass < 3; pass++) {
      const __nv_bfloat16* A = Ap[pass];
      const __nv_bfloat16* B = Bp[pass];
      #pragma unroll
      for (int ds = 0; ds < 8; ds++) {
        int d0 = ds * 16 + lc * 2;
        uint32_t a0 = *(const uint32_t*)(A + (mq + lr) * QSTR + d0);
        uint32_t a1 = *(const uint32_t*)(A + (mq + 8 + lr) * QSTR + d0);
        uint32_t a2 = *(const uint32_t*)(A + (mq + lr) * QSTR + d0 + 8);
        uint32_t a3 = *(const uint32_t*)(A + (mq + 8 + lr) * QSTR + d0 + 8);
        #pragma unroll
        for (int nt = 0; nt < 8; nt++) {
          const __nv_bfloat16* br = B + (kb + nt * 8 + lr) * QSTR + d0;
          uint32_t b0 = *(const uint32_t*)(br);
          uint32_t b1 = *(const uint32_t*)(br + 8);
          mma_bf16(c[nt], a0, a1, a2, a3, b0, b1);
        }
      }
    }
    // ---- exp in registers, pack A-fragments for PV (hi + lo), row sums ----
    uint32_t ph[4][4], pl[4][4];
    #pragma unroll
    for (int ks = 0; ks < 4; ks++) {
      #pragma unroll
      for (int h2 = 0; h2 < 2; h2++) {
        int nt = 2 * ks + h2;
        float e0 = __expf(fmaf(c[nt][0], 30.0f, -30.0f));
        float e1 = __expf(fmaf(c[nt][1], 30.0f, -30.0f));
        float e2 = __expf(fmaf(c[nt][2], 30.0f, -30.0f));
        float e3 = __expf(fmaf(c[nt][3], 30.0f, -30.0f));
        slacc += e0 + e1;
        shacc += e2 + e3;
        float l0, l1, l2, l3;
        ph[ks][0 + h2 * 2] = pack_hi2(e0, e1, l0, l1);
        ph[ks][1 + h2 * 2] = pack_hi2(e2, e3, l2, l3);
        pl[ks][0 + h2 * 2] = pack_bf2(l0, l1);
        pl[ks][1 + h2 * 2] = pack_bf2(l2, l3);
      }
    }
    // ---- PV via HMMA, P fragments recycled from registers ----
    #pragma unroll
    for (int pass = 0; pass < 3; pass++) {
      const __nv_bfloat16* Vt = (pass == 2) ? Vtl : Vth;
      #pragma unroll
      for (int ks = 0; ks < 4; ks++) {
        uint32_t a0, a1, a2, a3;
        if (pass == 1) { a0 = pl[ks][0]; a1 = pl[ks][1]; a2 = pl[ks][2]; a3 = pl[ks][3]; }
        else           { a0 = ph[ks][0]; a1 = ph[ks][1]; a2 = ph[ks][2]; a3 = ph[ks][3]; }
        int d0 = kb + ks * 16 + lc * 2;
        #pragma unroll
        for (int et = 0; et < 2; et++) {
          const __nv_bfloat16* br = Vt + (et * 8 + lr) * VSTR + d0;
          uint32_t b0 = *(const uint32_t*)(br);
          uint32_t b1 = *(const uint32_t*)(br + 8);
          mma_bf16(cpv[et], a0, a1, a2, a3, b0, b1);
        }
      }
    }
  }
  // ---- final combine across k-halves + row sums ----
  slacc += __shfl_xor_sync(0xffffffffu, slacc, 1);
  slacc += __shfl_xor_sync(0xffffffffu, slacc, 2);
  shacc += __shfl_xor_sync(0xffffffffu, shacc, 1);
  shacc += __shfl_xor_sync(0xffffffffu, shacc, 2);
  __syncthreads();
  if (lc == 0) {
    Pred[(mq + lr) * 2 + half]     = slacc;
    Pred[(mq + 8 + lr) * 2 + half] = shacc;
  }
  if (half == 1) {
    #pragma unroll
    for (int et = 0; et < 2; et++) {
      int col = et * 8 + lc * 2;
      Acc[(mq + lr) * 17 + col]         = cpv[et][0];
      Acc[(mq + lr) * 17 + col + 1]     = cpv[et][1];
      Acc[(mq + 8 + lr) * 17 + col]     = cpv[et][2];
      Acc[(mq + 8 + lr) * 17 + col + 1] = cpv[et][3];
    }
  }
  __syncthreads();
  if (half == 0) {
    float* pp0 = part + (((size_t)(ksp * S4 + s) * HW) + q0 + mq + lr) * 18;
    float* pp1 = part + (((size_t)(ksp * S4 + s) * HW) + q0 + mq + 8 + lr) * 18;
    #pragma unroll
    for (int et = 0; et < 2; et++) {
      int col = et * 8 + lc * 2;
      pp0[col]     = cpv[et][0] + Acc[(mq + lr) * 17 + col];
      pp0[col + 1] = cpv[et][1] + Acc[(mq + lr) * 17 + col + 1];
      pp1[col]     = cpv[et][2] + Acc[(mq + 8 + lr) * 17 + col];
      pp1[col + 1] = cpv[et][3] + Acc[(mq + 8 + lr) * 17 + col + 1];
    }
    if (lc == 0) {
      pp0[16] = Pred[(mq + lr) * 2]     + Pred[(mq + lr) * 2 + 1];
      pp1[16] = Pred[(mq + 8 + lr) * 2] + Pred[(mq + 8 + lr) * 2 + 1];
    }
  }
}

// ================= merge split-K partials + sigmoid =================
__global__ __launch_bounds__(256) void merge_kernel(
    const float* __restrict__ part, float* __restrict__ out) {
  int g = blockIdx.x * 256 + threadIdx.x;
  int eg = (g & 3) * 4;
  int sn = g >> 2;
  int n = sn & 1023, s = sn >> 10;
  float L = 0.0f;
  float O[4] = {};
  #pragma unroll
  for (int z = 0; z < KSPLIT; z++) {
    const float* pp = part + ((size_t)((z * S4 + s) * HW) + n) * 18;
    L += pp[16];
    #pragma unroll
    for (int e = 0; e < 4; e++) O[e] += pp[eg + e];
  }
  float inv = 1.0f / L;
  #pragma unroll
  for (int e = 0; e < 4; e++) {
    float v = O[e] * inv;
    out[(size_t)(s * CE + eg + e) * HW + n] = 1.0f / (1.0f + __expf(-v));
  }
}

// ================= host =================
extern "C" void kernel_launch(void* const* d_in, const int* in_sizes, int n_in,
                              void* d_out, int out_size) {
  const float* tgt = (const float*)d_in[0];
  const float* mem = (const float*)d_in[1];
  const float* pe  = (const float*)d_in[2];
  const float* wks = (const float*)d_in[3];
  const float* bks = (const float*)d_in[4];
  const float* wkc = (const float*)d_in[5];
  const float* bkc = (const float*)d_in[6];
  float* out = (float*)d_out;

  float *p_sc, *p_t, *p_part;
  __nv_bfloat16 *p_wk_hi, *p_wk_lo, *p_p_hi, *p_p_lo, *p_v_hi, *p_v_lo;
  __nv_bfloat16 *p_qs_hi, *p_qs_lo, *p_qc_hi, *p_qc_lo;
  cudaGetSymbolAddress((void**)&p_sc, g_sc);
  cudaGetSymbolAddress((void**)&p_t, g_t);
  cudaGetSymbolAddress((void**)&p_wk_hi, g_wk_hi);
  cudaGetSymbolAddress((void**)&p_wk_lo, g_wk_lo);
  cudaGetSymbolAddress((void**)&p_p_hi, g_p_hi);
  cudaGetSymbolAddress((void**)&p_p_lo, g_p_lo);
  cudaGetSymbolAddress((void**)&p_v_hi, g_v_hi);
  cudaGetSymbolAddress((void**)&p_v_lo, g_v_lo);
  cudaGetSymbolAddress((void**)&p_qs_hi, g_qs_hi);
  cudaGetSymbolAddress((void**)&p_qs_lo, g_qs_lo);
  cudaGetSymbolAddress((void**)&p_qc_hi, g_qc_hi);
  cudaGetSymbolAddress((void**)&p_qc_lo, g_qc_lo);
  cudaGetSymbolAddress((void**)&p_part, g_part);

  cudaFuncSetAttribute(proj_mma_kernel,
                       cudaFuncAttributeMaxDynamicSharedMemorySize, SMEM_PROJ);
  cudaFuncSetAttribute(self_scores_mma,
                       cudaFuncAttributeMaxDynamicSharedMemorySize, SMEM_SS);
  cudaFuncSetAttribute(pv_mma_kernel,
                       cudaFuncAttributeMaxDynamicSharedMemorySize, SMEM_PV);
  cudaFuncSetAttribute(cross_attn_kernel,
                       cudaFuncAttributeMaxDynamicSharedMemorySize, SMEM_CROSS);

  // self-attention
  proj_mma_kernel<<<dim3(16, 4), 256, SMEM_PROJ>>>(tgt, wks, bks, p_qs_hi, p_qs_lo, HW);
  self_scores_mma<<<dim3(16, 16, 4), 256, SMEM_SS>>>(p_qs_hi, p_qs_lo, p_sc);
  softmax_kernel<<<4096, 256>>>(p_sc, p_p_hi, p_p_lo);
  split_v_kernel<<<2048, 256>>>(tgt, p_v_hi, p_v_lo);
  pv_mma_kernel<<<dim3(16, 4, 4), 256, SMEM_PV>>>(p_p_hi, p_p_lo, p_v_hi, p_v_lo, tgt, p_t);
  instnorm_kernel<<<2048, 256>>>(p_t);

  // cross projections (all HMMA)
  proj_mma_kernel<<<dim3(16, 4), 256, SMEM_PROJ>>>(p_t, wkc, bkc, p_qc_hi, p_qc_lo, HW);
  proj_mma_kernel<<<dim3(256, 4), 256, SMEM_PROJ>>>(mem, wkc, bkc, p_wk_hi, p_wk_lo, NM);

  // HMMA cross-attention (PV fused on tensor pipe)
  cross_attn_kernel<<<dim3(16, 4, KSPLIT), 256, SMEM_CROSS>>>(
      p_qc_hi, p_qc_lo, p_wk_hi, p_wk_lo, pe, p_part);
  merge_kernel<<<64, 256>>>(p_part, out);
}

// round 13
// speedup vs baseline: 2.2277x; 1.0554x over previous
#include <cuda_runtime.h>
#include <cuda_bf16.h>
#include <math.h>
#include <stdint.h>

#define S4 4
#define CD 512
#define KD 128
#define HW 1024
#define NM 16384
#define CE 16
#define KSPLIT 16

// ---------------- scratch ----------------
__device__ __nv_bfloat16 g_p_hi[S4 * HW * HW];
__device__ __nv_bfloat16 g_p_lo[S4 * HW * HW];
__device__ __nv_bfloat16 g_v_hi[S4 * CD * HW];
__device__ __nv_bfloat16 g_v_lo[S4 * CD * HW];
__device__ float g_t[S4 * CD * HW];
__device__ __nv_bfloat16 g_qs_hi[S4 * HW * KD];
__device__ __nv_bfloat16 g_qs_lo[S4 * HW * KD];
__device__ __nv_bfloat16 g_qc_hi[S4 * HW * KD];
__device__ __nv_bfloat16 g_qc_lo[S4 * HW * KD];
__device__ __nv_bfloat16 g_wk_hi[S4 * NM * KD];
__device__ __nv_bfloat16 g_wk_lo[S4 * NM * KD];
__device__ __nv_bfloat16 g_w1_hi[KD * CD];
__device__ __nv_bfloat16 g_w1_lo[KD * CD];
__device__ __nv_bfloat16 g_w2_hi[KD * CD];
__device__ __nv_bfloat16 g_w2_lo[KD * CD];
__device__ __nv_bfloat16 g_pe_hi[16 * S4 * CE * HW];
__device__ __nv_bfloat16 g_pe_lo[16 * S4 * CE * HW];
__device__ float g_lpart[S4 * HW * 32];
__device__ float g_linv[S4 * HW];
__device__ float g_part[KSPLIT * S4 * HW * 18];

__device__ __forceinline__ void mma_bf16(float* c, uint32_t a0, uint32_t a1,
                                         uint32_t a2, uint32_t a3,
                                         uint32_t b0, uint32_t b1) {
  asm("mma.sync.aligned.m16n8k16.row.col.f32.bf16.bf16.f32 "
      "{%0,%1,%2,%3}, {%4,%5,%6,%7}, {%8,%9}, {%0,%1,%2,%3};"
      : "+f"(c[0]), "+f"(c[1]), "+f"(c[2]), "+f"(c[3])
      : "r"(a0), "r"(a1), "r"(a2), "r"(a3), "r"(b0), "r"(b1));
}
__device__ __forceinline__ uint32_t pack_hi2(float a, float b, float& la, float& lb) {
  __nv_bfloat16 h0 = __float2bfloat16(a), h1 = __float2bfloat16(b);
  la = a - __bfloat162float(h0);
  lb = b - __bfloat162float(h1);
  return (uint32_t)__bfloat16_as_ushort(h0) | ((uint32_t)__bfloat16_as_ushort(h1) << 16);
}
__device__ __forceinline__ uint32_t pack_bf2(float a, float b) {
  __nv_bfloat16 h0 = __float2bfloat16(a), h1 = __float2bfloat16(b);
  return (uint32_t)__bfloat16_as_ushort(h0) | ((uint32_t)__bfloat16_as_ushort(h1) << 16);
}

// ================= generic fp32 -> bf16 hi/lo splitter =================
__global__ __launch_bounds__(256) void split_v_kernel(
    const float* __restrict__ x,
    __nv_bfloat16* __restrict__ hi, __nv_bfloat16* __restrict__ lo) {
  int i = blockIdx.x * 1024 + threadIdx.x;
  #pragma unroll
  for (int r = 0; r < 4; r++, i += 256) {
    float v = x[i];
    __nv_bfloat16 h = __float2bfloat16(v);
    hi[i] = h;
    lo[i] = __float2bfloat16(v - __bfloat162float(h));
  }
}

// ================= HMMA projection + L2 normalize -> bf16 hi/lo =================
#define PASTR 72
#define POFF_AH 0
#define POFF_AL 9216
#define POFF_BH 18432
#define POFF_BL 36864
#define POFF_RED 55296
#define SMEM_PROJ 55808

__global__ __launch_bounds__(256, 1) void proj_mma_kernel(
    const float* __restrict__ in,
    const __nv_bfloat16* __restrict__ whi, const __nv_bfloat16* __restrict__ wlo,
    const float* __restrict__ bias,
    __nv_bfloat16* __restrict__ out_hi, __nv_bfloat16* __restrict__ out_lo,
    int NT) {
  extern __shared__ char smp[];
  __nv_bfloat16* Ah = (__nv_bfloat16*)(smp + POFF_AH);
  __nv_bfloat16* Al = (__nv_bfloat16*)(smp + POFF_AL);
  __nv_bfloat16* Bh = (__nv_bfloat16*)(smp + POFF_BH);
  __nv_bfloat16* Bl = (__nv_bfloat16*)(smp + POFF_BL);
  float* red = (float*)(smp + POFF_RED);
  int s = blockIdx.y;
  int tg0 = blockIdx.x * 64;
  int f = tg0 >> 10;
  int n0 = tg0 & 1023;
  const float* inb = in + ((size_t)(f * S4 + s)) * CD * HW + n0;
  int t = threadIdx.x;
  int w = t >> 5, lane = t & 31;
  int lr = lane >> 2, lc = lane & 3;
  int mq = (w & 3) * 16;
  int db = (w >> 2) * 64;
  float c[8][4];
  #pragma unroll
  for (int nt = 0; nt < 8; nt++)
    #pragma unroll
    for (int j = 0; j < 4; j++) c[nt][j] = 0.0f;

  for (int c0 = 0; c0 < CD; c0 += 64) {
    __syncthreads();
    // A chunk: 64 tok x 64 c, split from fp32
    #pragma unroll
    for (int r = 0; r < 16; r++) {
      int idx = t + r * 256;
      int tok = idx & 63, cc = idx >> 6;
      float v = inb[(size_t)(c0 + cc) * HW + tok];
      __nv_bfloat16 h = __float2bfloat16(v);
      Ah[tok * PASTR + cc] = h;
      Al[tok * PASTR + cc] = __float2bfloat16(v - __bfloat162float(h));
    }
    // B chunk: 128 d x 64 c, pre-split bf16 (uint4 = 8 bf16)
    #pragma unroll
    for (int r = 0; r < 4; r++) {
      int idx = t + r * 256;
      int row = idx >> 3, u8 = (idx & 7) * 8;
      *(uint4*)(Bh + row * PASTR + u8) = *(const uint4*)(whi + (size_t)row * CD + c0 + u8);
      *(uint4*)(Bl + row * PASTR + u8) = *(const uint4*)(wlo + (size_t)row * CD + c0 + u8);
    }
    __syncthreads();
    const __nv_bfloat16* Ap[3] = {Ah, Al, Ah};
    const __nv_bfloat16* Bp[3] = {Bh, Bh, Bl};
    #pragma unroll
    for (int pass = 0; pass < 3; pass++) {
      const __nv_bfloat16* A = Ap[pass];
      const __nv_bfloat16* B = Bp[pass];
      #pragma unroll
      for (int ds = 0; ds < 4; ds++) {
        int d0 = ds * 16 + lc * 2;
        uint32_t a0 = *(const uint32_t*)(A + (mq + lr) * PASTR + d0);
        uint32_t a1 = *(const uint32_t*)(A + (mq + 8 + lr) * PASTR + d0);
        uint32_t a2 = *(const uint32_t*)(A + (mq + lr) * PASTR + d0 + 8);
        uint32_t a3 = *(const uint32_t*)(A + (mq + 8 + lr) * PASTR + d0 + 8);
        #pragma unroll
        for (int nt = 0; nt < 8; nt++) {
          const __nv_bfloat16* br = B + (db + nt * 8 + lr) * PASTR + d0;
          uint32_t b0 = *(const uint32_t*)(br);
          uint32_t b1 = *(const uint32_t*)(br + 8);
          mma_bf16(c[nt], a0, a1, a2, a3, b0, b1);
        }
      }
    }
  }
  float ssl = 0.0f, ssh = 0.0f;
  #pragma unroll
  for (int nt = 0; nt < 8; nt++) {
    int d = db + nt * 8 + lc * 2;
    float b0 = bias[d], b1 = bias[d + 1];
    c[nt][0] += b0; c[nt][1] += b1;
    c[nt][2] += b0; c[nt][3] += b1;
    ssl = fmaf(c[nt][0], c[nt][0], fmaf(c[nt][1], c[nt][1], ssl));
    ssh = fmaf(c[nt][2], c[nt][2], fmaf(c[nt][3], c[nt][3], ssh));
  }
  ssl += __shfl_xor_sync(0xffffffffu, ssl, 1);
  ssl += __shfl_xor_sync(0xffffffffu, ssl, 2);
  ssh += __shfl_xor_sync(0xffffffffu, ssh, 1);
  ssh += __shfl_xor_sync(0xffffffffu, ssh, 2);
  __syncthreads();
  if (lc == 0) {
    red[(mq + lr) * 2 + (w >> 2)]     = ssl;
    red[(mq + 8 + lr) * 2 + (w >> 2)] = ssh;
  }
  __syncthreads();
  float sl = 1.0f / fmaxf(sqrtf(red[(mq + lr) * 2] + red[(mq + lr) * 2 + 1]), 1e-12f);
  float sh = 1.0f / fmaxf(sqrtf(red[(mq + 8 + lr) * 2] + red[(mq + 8 + lr) * 2 + 1]), 1e-12f);
  size_t rb0 = ((size_t)s * NT + tg0 + mq + lr) * KD;
  size_t rb1 = ((size_t)s * NT + tg0 + mq + 8 + lr) * KD;
  #pragma unroll
  for (int nt = 0; nt < 8; nt++) {
    int d = db + nt * 8 + lc * 2;
    float v0 = c[nt][0] * sl, v1 = c[nt][1] * sl;
    float v2 = c[nt][2] * sh, v3 = c[nt][3] * sh;
    float l0, l1, l2, l3;
    uint32_t uh0 = pack_hi2(v0, v1, l0, l1);
    uint32_t uh1 = pack_hi2(v2, v3, l2, l3);
    *(uint32_t*)(out_hi + rb0 + d) = uh0;
    *(uint32_t*)(out_hi + rb1 + d) = uh1;
    *(uint32_t*)(out_lo + rb0 + d) = pack_bf2(l0, l1);
    *(uint32_t*)(out_lo + rb1 + d) = pack_bf2(l2, l3);
  }
}

// ================= self scores via HMMA -> exp bf16 hi/lo + row-sum partials =================
#define SQSTR 136
#define SOFF_AH 0
#define SOFF_AL 17408
#define SOFF_BH 34816
#define SOFF_BL 52224
#define SMEM_SS 69632

__global__ __launch_bounds__(256) void self_scores_mma(
    const __nv_bfloat16* __restrict__ qhi, const __nv_bfloat16* __restrict__ qlo,
    __nv_bfloat16* __restrict__ phi, __nv_bfloat16* __restrict__ plo,
    float* __restrict__ lpart) {
  extern __shared__ char sms[];
  __nv_bfloat16* Ah = (__nv_bfloat16*)(sms + SOFF_AH);
  __nv_bfloat16* Al = (__nv_bfloat16*)(sms + SOFF_AL);
  __nv_bfloat16* Bh = (__nv_bfloat16*)(sms + SOFF_BH);
  __nv_bfloat16* Bl = (__nv_bfloat16*)(sms + SOFF_BL);
  int s = blockIdx.z;
  int q0 = blockIdx.x * 64, k0 = blockIdx.y * 64;
  int t = threadIdx.x;
  int w = t >> 5, lane = t & 31;
  int lr = lane >> 2, lc = lane & 3;
  {
    const uint4* gah = (const uint4*)(qhi + ((size_t)s * HW + q0) * KD);
    const uint4* gal = (const uint4*)(qlo + ((size_t)s * HW + q0) * KD);
    const uint4* gbh = (const uint4*)(qhi + ((size_t)s * HW + k0) * KD);
    const uint4* gbl = (const uint4*)(qlo + ((size_t)s * HW + k0) * KD);
    #pragma unroll
    for (int r = 0; r < 4; r++) {
      int idx = t + r * 256;
      int row = idx >> 4, u8 = (idx & 15) * 8;
      *(uint4*)(Ah + row * SQSTR + u8) = gah[idx];
      *(uint4*)(Al + row * SQSTR + u8) = gal[idx];
      *(uint4*)(Bh + row * SQSTR + u8) = gbh[idx];
      *(uint4*)(Bl + row * SQSTR + u8) = gbl[idx];
    }
  }
  __syncthreads();
  int mq = (w & 3) * 16;
  int kb = (w >> 2) * 32;
  float c[4][4];
  #pragma unroll
  for (int nt = 0; nt < 4; nt++)
    #pragma unroll
    for (int j = 0; j < 4; j++) c[nt][j] = 0.0f;
  const __nv_bfloat16* Ap[3] = {Ah, Al, Ah};
  const __nv_bfloat16* Bp[3] = {Bh, Bh, Bl};
  #pragma unroll
  for (int pass = 0; pass < 3; pass++) {
    const __nv_bfloat16* A = Ap[pass];
    const __nv_bfloat16* B = Bp[pass];
    #pragma unroll
    for (int ds = 0; ds < 8; ds++) {
      int d0 = ds * 16 + lc * 2;
      uint32_t a0 = *(const uint32_t*)(A + (mq + lr) * SQSTR + d0);
      uint32_t a1 = *(const uint32_t*)(A + (mq + 8 + lr) * SQSTR + d0);
      uint32_t a2 = *(const uint32_t*)(A + (mq + lr) * SQSTR + d0 + 8);
      uint32_t a3 = *(const uint32_t*)(A + (mq + 8 + lr) * SQSTR + d0 + 8);
      #pragma unroll
      for (int nt = 0; nt < 4; nt++) {
        const __nv_bfloat16* br = B + (kb + nt * 8 + lr) * SQSTR + d0;
        uint32_t b0 = *(const uint32_t*)(br);
        uint32_t b1 = *(const uint32_t*)(br + 8);
        mma_bf16(c[nt], a0, a1, a2, a3, b0, b1);
      }
    }
  }
  float sl = 0.0f, sh = 0.0f;
  #pragma unroll
  for (int nt = 0; nt < 4; nt++) {
    float e0 = __expf(fmaf(c[nt][0], 30.0f, -30.0f));
    float e1 = __expf(fmaf(c[nt][1], 30.0f, -30.0f));
    float e2 = __expf(fmaf(c[nt][2], 30.0f, -30.0f));
    float e3 = __expf(fmaf(c[nt][3], 30.0f, -30.0f));
    sl += e0 + e1; sh += e2 + e3;
    int col = k0 + kb + nt * 8 + lc * 2;
    size_t g0 = ((size_t)s * HW + q0 + mq + lr) * HW + col;
    size_t g1 = ((size_t)s * HW + q0 + mq + 8 + lr) * HW + col;
    float l0, l1, l2, l3;
    *(uint32_t*)(phi + g0) = pack_hi2(e0, e1, l0, l1);
    *(uint32_t*)(phi + g1) = pack_hi2(e2, e3, l2, l3);
    *(uint32_t*)(plo + g0) = pack_bf2(l0, l1);
    *(uint32_t*)(plo + g1) = pack_bf2(l2, l3);
  }
  sl += __shfl_xor_sync(0xffffffffu, sl, 1);
  sl += __shfl_xor_sync(0xffffffffu, sl, 2);
  sh += __shfl_xor_sync(0xffffffffu, sh, 1);
  sh += __shfl_xor_sync(0xffffffffu, sh, 2);
  if (lc == 0) {
    int colp = (k0 >> 6) * 2 + (w >> 2);
    lpart[((size_t)s * HW + q0 + mq + lr) * 32 + colp]     = sl;
    lpart[((size_t)s * HW + q0 + mq + 8 + lr) * 32 + colp] = sh;
  }
}

// ================= row-sum reduce -> 1/L =================
__global__ __launch_bounds__(256) void rowsum_kernel(
    const float* __restrict__ lpart, float* __restrict__ linv) {
  int row = blockIdx.x * 256 + threadIdx.x;   // 4096 rows
  const float4* p = (const float4*)(lpart + (size_t)row * 32);
  float sum = 0.0f;
  #pragma unroll
  for (int i = 0; i < 8; i++) {
    float4 v = p[i];
    sum += v.x + v.y + v.z + v.w;
  }
  linv[row] = 1.0f / sum;
}

// ================= self P.V via HMMA, scaled by 1/L, + residual =================
#define CSTR 133
#define SMEM_PV 55296

__global__ __launch_bounds__(256) void pv_mma_kernel(
    const __nv_bfloat16* __restrict__ phi, const __nv_bfloat16* __restrict__ plo,
    const __nv_bfloat16* __restrict__ vhi, const __nv_bfloat16* __restrict__ vlo,
    const float* __restrict__ tgt, const float* __restrict__ linv,
    float* __restrict__ tout) {
  extern __shared__ char smv[];
  __nv_bfloat16* Ah = (__nv_bfloat16*)(smv + POFF_AH);
  __nv_bfloat16* Al = (__nv_bfloat16*)(smv + POFF_AL);
  __nv_bfloat16* Bh = (__nv_bfloat16*)(smv + POFF_BH);
  __nv_bfloat16* Bl = (__nv_bfloat16*)(smv + POFF_BL);
  float* Cs = (float*)smv;
  int s = blockIdx.z;
  int n0 = blockIdx.x * 64, c0 = blockIdx.y * 128;
  int t = threadIdx.x;
  int w = t >> 5, lane = t & 31;
  int lr = lane >> 2, lc = lane & 3;
  int mq = (w & 3) * 16;
  int db = (w >> 2) * 64;
  float c[8][4];
  #pragma unroll
  for (int nt = 0; nt < 8; nt++)
    #pragma unroll
    for (int j = 0; j < 4; j++) c[nt][j] = 0.0f;

  for (int m0 = 0; m0 < HW; m0 += 64) {
    __syncthreads();
    {
      const __nv_bfloat16* gph = phi + ((size_t)s * HW + n0) * HW + m0;
      const __nv_bfloat16* gpl = plo + ((size_t)s * HW + n0) * HW + m0;
      #pragma unroll
      for (int r = 0; r < 2; r++) {
        int idx = t + r * 256;
        int row = idx >> 3, u4 = (idx & 7) * 8;
        *(uint4*)(Ah + row * PASTR + u4) = *(const uint4*)(gph + (size_t)row * HW + u4);
        *(uint4*)(Al + row * PASTR + u4) = *(const uint4*)(gpl + (size_t)row * HW + u4);
      }
    }
    {
      const __nv_bfloat16* gvh = vhi + ((size_t)s * CD + c0) * HW + m0;
      const __nv_bfloat16* gvl = vlo + ((size_t)s * CD + c0) * HW + m0;
      #pragma unroll
      for (int r = 0; r < 4; r++) {
        int idx = t + r * 256;
        int row = idx >> 3, u4 = (idx & 7) * 8;
        *(uint4*)(Bh + row * PASTR + u4) = *(const uint4*)(gvh + (size_t)row * HW + u4);
        *(uint4*)(Bl + row * PASTR + u4) = *(const uint4*)(gvl + (size_t)row * HW + u4);
      }
    }
    __syncthreads();
    const __nv_bfloat16* Ap[3] = {Ah, Al, Ah};
    const __nv_bfloat16* Bp[3] = {Bh, Bh, Bl};
    #pragma unroll
    for (int pass = 0; pass < 3; pass++) {
      const __nv_bfloat16* A = Ap[pass];
      const __nv_bfloat16* B = Bp[pass];
      #pragma unroll
      for (int ds = 0; ds < 4; ds++) {
        int d0 = ds * 16 + lc * 2;
        uint32_t a0 = *(const uint32_t*)(A + (mq + lr) * PASTR + d0);
        uint32_t a1 = *(const uint32_t*)(A + (mq + 8 + lr) * PASTR + d0);
        uint32_t a2 = *(const uint32_t*)(A + (mq + lr) * PASTR + d0 + 8);
        uint32_t a3 = *(const uint32_t*)(A + (mq + 8 + lr) * PASTR + d0 + 8);
        #pragma unroll
        for (int nt = 0; nt < 8; nt++) {
          const __nv_bfloat16* br = B + (db + nt * 8 + lr) * PASTR + d0;
          uint32_t b0 = *(const uint32_t*)(br);
          uint32_t b1 = *(const uint32_t*)(br + 8);
          mma_bf16(c[nt], a0, a1, a2, a3, b0, b1);
        }
      }
    }
  }
  __syncthreads();
  #pragma unroll
  for (int nt = 0; nt < 8; nt++) {
    int col = db + nt * 8 + lc * 2;
    Cs[(mq + lr) * CSTR + col]         = c[nt][0];
    Cs[(mq + lr) * CSTR + col + 1]     = c[nt][1];
    Cs[(mq + 8 + lr) * CSTR + col]     = c[nt][2];
    Cs[(mq + 8 + lr) * CSTR + col + 1] = c[nt][3];
  }
  __syncthreads();
  #pragma unroll
  for (int r = 0; r < 32; r++) {
    int idx = t + r * 256;
    int cc = idx >> 6, n = idx & 63;
    size_t g = (size_t)(s * CD + c0 + cc) * HW + n0 + n;
    tout[g] = tgt[g] + Cs[n * CSTR + cc] * linv[s * HW + n0 + n];
  }
}

// ================= instance norm =================
__global__ __launch_bounds__(256) void instnorm_kernel(float* __restrict__ x) {
  __shared__ float redS[8];
  __shared__ float redQ[8];
  float* p = x + (size_t)blockIdx.x * HW;
  int t = threadIdx.x, lane = t & 31, warp = t >> 5;
  float v0 = p[t], v1 = p[t + 256], v2 = p[t + 512], v3 = p[t + 768];
  float sum = v0 + v1 + v2 + v3;
  float sq = v0 * v0 + v1 * v1 + v2 * v2 + v3 * v3;
  #pragma unroll
  for (int o = 16; o; o >>= 1) {
    sum += __shfl_xor_sync(0xffffffffu, sum, o);
    sq  += __shfl_xor_sync(0xffffffffu, sq, o);
  }
  if (lane == 0) { redS[warp] = sum; redQ[warp] = sq; }
  __syncthreads();
  sum = redS[0]; sq = redQ[0];
  #pragma unroll
  for (int i = 1; i < 8; i++) { sum += redS[i]; sq += redQ[i]; }
  float mean = sum * (1.0f / HW);
  float var = sq * (1.0f / HW) - mean * mean;
  float rstd = rsqrtf(var + 1e-5f);
  p[t]       = (v0 - mean) * rstd;
  p[t + 256] = (v1 - mean) * rstd;
  p[t + 512] = (v2 - mean) * rstd;
  p[t + 768] = (v3 - mean) * rstd;
}

// ================= cross attention: HMMA scores + fragment-recycled HMMA PV =================
#define QSTR 136
#define VSTR 136
#define OFF_QH 0
#define OFF_QL 17408
#define OFF_KH 34816
#define OFF_KL 69632
#define OFF_VTH 104448
#define OFF_VTL 108800
#define OFF_ACC 113152
#define OFF_PRED 117776
#define SMEM_CROSS 118288

__global__ __launch_bounds__(256, 1) void cross_attn_kernel(
    const __nv_bfloat16* __restrict__ qhi, const __nv_bfloat16* __restrict__ qlo,
    const __nv_bfloat16* __restrict__ khi, const __nv_bfloat16* __restrict__ klo,
    const __nv_bfloat16* __restrict__ pehi, const __nv_bfloat16* __restrict__ pelo,
    float* __restrict__ part) {
  extern __shared__ char smc[];
  __nv_bfloat16* Qh  = (__nv_bfloat16*)(smc + OFF_QH);
  __nv_bfloat16* Ql  = (__nv_bfloat16*)(smc + OFF_QL);
  __nv_bfloat16* Kh  = (__nv_bfloat16*)(smc + OFF_KH);
  __nv_bfloat16* Kl  = (__nv_bfloat16*)(smc + OFF_KL);
  __nv_bfloat16* Vth = (__nv_bfloat16*)(smc + OFF_VTH);
  __nv_bfloat16* Vtl = (__nv_bfloat16*)(smc + OFF_VTL);
  float* Acc  = (float*)(smc + OFF_ACC);
  float* Pred = (float*)(smc + OFF_PRED);
  int qt = blockIdx.x, s = blockIdx.y, ksp = blockIdx.z;
  int q0 = qt * 64;
  int t = threadIdx.x;
  int w = t >> 5, lane = t & 31;
  int lr = lane >> 2, lc = lane & 3;
  int mq = (w & 3) * 16;
  int half = w >> 2;
  int kb = half * 64;

  {
    const uint4* gqh = (const uint4*)(qhi + ((size_t)s * HW + q0) * KD);
    const uint4* gql = (const uint4*)(qlo + ((size_t)s * HW + q0) * KD);
    #pragma unroll
    for (int r = 0; r < 4; r++) {
      int idx = t + r * 256;
      int row = idx >> 4, u8 = (idx & 15) * 8;
      *(uint4*)(Qh + row * QSTR + u8) = gqh[idx];
      *(uint4*)(Ql + row * QSTR + u8) = gql[idx];
    }
  }
  float cpv[2][4];
  #pragma unroll
  for (int et = 0; et < 2; et++)
    #pragma unroll
    for (int j = 0; j < 4; j++) cpv[et][j] = 0.0f;
  float slacc = 0.0f, shacc = 0.0f;

  for (int kt = 0; kt < NM / (KSPLIT * 128); kt++) {
    int kk0 = ksp * (NM / KSPLIT) + kt * 128;
    __syncthreads();
    {
      const uint4* gh = (const uint4*)(khi + ((size_t)s * NM + kk0) * KD);
      const uint4* gl = (const uint4*)(klo + ((size_t)s * NM + kk0) * KD);
      #pragma unroll
      for (int r = 0; r < 8; r++) {
        int idx = t + r * 256;
        int key = idx >> 4, d8 = (idx & 15) * 8;
        *(uint4*)(Kh + key * QSTR + d8) = gh[idx];
        *(uint4*)(Kl + key * QSTR + d8) = gl[idx];
      }
    }
    // V transposed tile from pre-split pe: Vt[e][k]
    {
      int f = kk0 >> 10, nn0 = kk0 & 1023;
      size_t pb = ((size_t)(f * S4 + s) * CE) * HW + nn0;
      int e = t >> 4, k8 = (t & 15) * 8;
      *(uint4*)(Vth + e * VSTR + k8) = *(const uint4*)(pehi + pb + (size_t)e * HW + k8);
      *(uint4*)(Vtl + e * VSTR + k8) = *(const uint4*)(pelo + pb + (size_t)e * HW + k8);
    }
    __syncthreads();
    float c[8][4];
    #pragma unroll
    for (int nt = 0; nt < 8; nt++)
      #pragma unroll
      for (int j = 0; j < 4; j++) c[nt][j] = 0.0f;
    const __nv_bfloat16* Ap[3] = {Qh, Ql, Qh};
    const __nv_bfloat16* Bp[3] = {Kh, Kh, Kl};
    #pragma unroll
    for (int pass = 0; pass < 3; pass++) {
      const __nv_bfloat16* A = Ap[pass];
      const __nv_bfloat16* B = Bp[pass];
      #pragma unroll
      for (int ds = 0; ds < 8; ds++) {
        int d0 = ds * 16 + lc * 2;
        uint32_t a0 = *(const uint32_t*)(A + (mq + lr) * QSTR + d0);
        uint32_t a1 = *(const uint32_t*)(A + (mq + 8 + lr) * QSTR + d0);
        uint32_t a2 = *(const uint32_t*)(A + (mq + lr) * QSTR + d0 + 8);
        uint32_t a3 = *(const uint32_t*)(A + (mq + 8 + lr) * QSTR + d0 + 8);
        #pragma unroll
        for (int nt = 0; nt < 8; nt++) {
          const __nv_bfloat16* br = B + (kb + nt * 8 + lr) * QSTR + d0;
          uint32_t b0 = *(const uint32_t*)(br);
          uint32_t b1 = *(const uint32_t*)(br + 8);
          mma_bf16(c[nt], a0, a1, a2, a3, b0, b1);
        }
      }
    }
    uint32_t ph[4][4], pl[4][4];
    #pragma unroll
    for (int ks = 0; ks < 4; ks++) {
      #pragma unroll
      for (int h2 = 0; h2 < 2; h2++) {
        int nt = 2 * ks + h2;
        float e0 = __expf(fmaf(c[nt][0], 30.0f, -30.0f));
        float e1 = __expf(fmaf(c[nt][1], 30.0f, -30.0f));
        float e2 = __expf(fmaf(c[nt][2], 30.0f, -30.0f));
        float e3 = __expf(fmaf(c[nt][3], 30.0f, -30.0f));
        slacc += e0 + e1;
        shacc += e2 + e3;
        float l0, l1, l2, l3;
        ph[ks][0 + h2 * 2] = pack_hi2(e0, e1, l0, l1);
        ph[ks][1 + h2 * 2] = pack_hi2(e2, e3, l2, l3);
        pl[ks][0 + h2 * 2] = pack_bf2(l0, l1);
        pl[ks][1 + h2 * 2] = pack_bf2(l2, l3);
      }
    }
    #pragma unroll
    for (int pass = 0; pass < 3; pass++) {
      const __nv_bfloat16* Vt = (pass == 2) ? Vtl : Vth;
      #pragma unroll
      for (int ks = 0; ks < 4; ks++) {
        uint32_t a0, a1, a2, a3;
        if (pass == 1) { a0 = pl[ks][0]; a1 = pl[ks][1]; a2 = pl[ks][2]; a3 = pl[ks][3]; }
        else           { a0 = ph[ks][0]; a1 = ph[ks][1]; a2 = ph[ks][2]; a3 = ph[ks][3]; }
        int d0 = kb + ks * 16 + lc * 2;
        #pragma unroll
        for (int et = 0; et < 2; et++) {
          const __nv_bfloat16* br = Vt + (et * 8 + lr) * VSTR + d0;
          uint32_t b0 = *(const uint32_t*)(br);
          uint32_t b1 = *(const uint32_t*)(br + 8);
          mma_bf16(cpv[et], a0, a1, a2, a3, b0, b1);
        }
      }
    }
  }
  slacc += __shfl_xor_sync(0xffffffffu, slacc, 1);
  slacc += __shfl_xor_sync(0xffffffffu, slacc, 2);
  shacc += __shfl_xor_sync(0xffffffffu, shacc, 1);
  shacc += __shfl_xor_sync(0xffffffffu, shacc, 2);
  __syncthreads();
  if (lc == 0) {
    Pred[(mq + lr) * 2 + half]     = slacc;
    Pred[(mq + 8 + lr) * 2 + half] = shacc;
  }
  if (half == 1) {
    #pragma unroll
    for (int et = 0; et < 2; et++) {
      int col = et * 8 + lc * 2;
      Acc[(mq + lr) * 17 + col]         = cpv[et][0];
      Acc[(mq + lr) * 17 + col + 1]     = cpv[et][1];
      Acc[(mq + 8 + lr) * 17 + col]     = cpv[et][2];
      Acc[(mq + 8 + lr) * 17 + col + 1] = cpv[et][3];
    }
  }
  __syncthreads();
  if (half == 0) {
    float* pp0 = part + (((size_t)(ksp * S4 + s) * HW) + q0 + mq + lr) * 18;
    float* pp1 = part + (((size_t)(ksp * S4 + s) * HW) + q0 + mq + 8 + lr) * 18;
    #pragma unroll
    for (int et = 0; et < 2; et++) {
      int col = et * 8 + lc * 2;
      pp0[col]     = cpv[et][0] + Acc[(mq + lr) * 17 + col];
      pp0[col + 1] = cpv[et][1] + Acc[(mq + lr) * 17 + col + 1];
      pp1[col]     = cpv[et][2] + Acc[(mq + 8 + lr) * 17 + col];
      pp1[col + 1] = cpv[et][3] + Acc[(mq + 8 + lr) * 17 + col + 1];
    }
    if (lc == 0) {
      pp0[16] = Pred[(mq + lr) * 2]     + Pred[(mq + lr) * 2 + 1];
      pp1[16] = Pred[(mq + 8 + lr) * 2] + Pred[(mq + 8 + lr) * 2 + 1];
    }
  }
}

// ================= merge split-K partials + sigmoid =================
__global__ __launch_bounds__(256) void merge_kernel(
    const float* __restrict__ part, float* __restrict__ out) {
  int g = blockIdx.x * 256 + threadIdx.x;
  int eg = (g & 3) * 4;
  int sn = g >> 2;
  int n = sn & 1023, s = sn >> 10;
  float L = 0.0f;
  float O[4] = {};
  #pragma unroll
  for (int z = 0; z < KSPLIT; z++) {
    const float* pp = part + ((size_t)((z * S4 + s) * HW) + n) * 18;
    L += pp[16];
    #pragma unroll
    for (int e = 0; e < 4; e++) O[e] += pp[eg + e];
  }
  float inv = 1.0f / L;
  #pragma unroll
  for (int e = 0; e < 4; e++) {
    float v = O[e] * inv;
    out[(size_t)(s * CE + eg + e) * HW + n] = 1.0f / (1.0f + __expf(-v));
  }
}

// ================= host =================
extern "C" void kernel_launch(void* const* d_in, const int* in_sizes, int n_in,
                              void* d_out, int out_size) {
  const float* tgt = (const float*)d_in[0];
  const float* mem = (const float*)d_in[1];
  const float* pe  = (const float*)d_in[2];
  const float* wks = (const float*)d_in[3];
  const float* bks = (const float*)d_in[4];
  const float* wkc = (const float*)d_in[5];
  const float* bkc = (const float*)d_in[6];
  float* out = (float*)d_out;

  float *p_t, *p_part, *p_lpart, *p_linv;
  __nv_bfloat16 *p_wk_hi, *p_wk_lo, *p_p_hi, *p_p_lo, *p_v_hi, *p_v_lo;
  __nv_bfloat16 *p_qs_hi, *p_qs_lo, *p_qc_hi, *p_qc_lo;
  __nv_bfloat16 *p_w1_hi, *p_w1_lo, *p_w2_hi, *p_w2_lo, *p_pe_hi, *p_pe_lo;
  cudaGetSymbolAddress((void**)&p_t, g_t);
  cudaGetSymbolAddress((void**)&p_wk_hi, g_wk_hi);
  cudaGetSymbolAddress((void**)&p_wk_lo, g_wk_lo);
  cudaGetSymbolAddress((void**)&p_p_hi, g_p_hi);
  cudaGetSymbolAddress((void**)&p_p_lo, g_p_lo);
  cudaGetSymbolAddress((void**)&p_v_hi, g_v_hi);
  cudaGetSymbolAddress((void**)&p_v_lo, g_v_lo);
  cudaGetSymbolAddress((void**)&p_qs_hi, g_qs_hi);
  cudaGetSymbolAddress((void**)&p_qs_lo, g_qs_lo);
  cudaGetSymbolAddress((void**)&p_qc_hi, g_qc_hi);
  cudaGetSymbolAddress((void**)&p_qc_lo, g_qc_lo);
  cudaGetSymbolAddress((void**)&p_w1_hi, g_w1_hi);
  cudaGetSymbolAddress((void**)&p_w1_lo, g_w1_lo);
  cudaGetSymbolAddress((void**)&p_w2_hi, g_w2_hi);
  cudaGetSymbolAddress((void**)&p_w2_lo, g_w2_lo);
  cudaGetSymbolAddress((void**)&p_pe_hi, g_pe_hi);
  cudaGetSymbolAddress((void**)&p_pe_lo, g_pe_lo);
  cudaGetSymbolAddress((void**)&p_lpart, g_lpart);
  cudaGetSymbolAddress((void**)&p_linv, g_linv);
  cudaGetSymbolAddress((void**)&p_part, g_part);

  cudaFuncSetAttribute(proj_mma_kernel,
                       cudaFuncAttributeMaxDynamicSharedMemorySize, SMEM_PROJ);
  cudaFuncSetAttribute(self_scores_mma,
                       cudaFuncAttributeMaxDynamicSharedMemorySize, SMEM_SS);
  cudaFuncSetAttribute(pv_mma_kernel,
                       cudaFuncAttributeMaxDynamicSharedMemorySize, SMEM_PV);
  cudaFuncSetAttribute(cross_attn_kernel,
                       cudaFuncAttributeMaxDynamicSharedMemorySize, SMEM_CROSS);

  // constant pre-splits
  split_v_kernel<<<64, 256>>>(wks, p_w1_hi, p_w1_lo);
  split_v_kernel<<<64, 256>>>(wkc, p_w2_hi, p_w2_lo);
  split_v_kernel<<<1024, 256>>>(pe, p_pe_hi, p_pe_lo);
  split_v_kernel<<<2048, 256>>>(tgt, p_v_hi, p_v_lo);

  // self-attention
  proj_mma_kernel<<<dim3(16, 4), 256, SMEM_PROJ>>>(tgt, p_w1_hi, p_w1_lo, bks, p_qs_hi, p_qs_lo, HW);
  self_scores_mma<<<dim3(16, 16, 4), 256, SMEM_SS>>>(p_qs_hi, p_qs_lo, p_p_hi, p_p_lo, p_lpart);
  rowsum_kernel<<<16, 256>>>(p_lpart, p_linv);
  pv_mma_kernel<<<dim3(16, 4, 4), 256, SMEM_PV>>>(p_p_hi, p_p_lo, p_v_hi, p_v_lo, tgt, p_linv, p_t);
  instnorm_kernel<<<2048, 256>>>(p_t);

  // cross projections
  proj_mma_kernel<<<dim3(16, 4), 256, SMEM_PROJ>>>(p_t, p_w2_hi, p_w2_lo, bkc, p_qc_hi, p_qc_lo, HW);
  proj_mma_kernel<<<dim3(256, 4), 256, SMEM_PROJ>>>(mem, p_w2_hi, p_w2_lo, bkc, p_wk_hi, p_wk_lo, NM);

  // HMMA cross-attention
  cross_attn_kernel<<<dim3(16, 4, KSPLIT), 256, SMEM_CROSS>>>(
      p_qc_hi, p_qc_lo, p_wk_hi, p_wk_lo, p_pe_hi, p_pe_lo, p_part);
  merge_kernel<<<64, 256>>>(p_part, out);
}

// round 14
// speedup vs baseline: 2.2796x; 1.0233x over previous
#include <cuda_runtime.h>
#include <cuda_bf16.h>
#include <math.h>
#include <stdint.h>

#define S4 4
#define CD 512
#define KD 128
#define HW 1024
#define NM 16384
#define CE 16
#define KSPLIT 16

// ---------------- scratch ----------------
__device__ __nv_bfloat16 g_p_hi[S4 * HW * HW];
__device__ __nv_bfloat16 g_p_lo[S4 * HW * HW];
__device__ __nv_bfloat16 g_v_hi[S4 * CD * HW];
__device__ __nv_bfloat16 g_v_lo[S4 * CD * HW];
__device__ float g_t[S4 * CD * HW];
__device__ __nv_bfloat16 g_qs_hi[S4 * HW * KD];
__device__ __nv_bfloat16 g_qs_lo[S4 * HW * KD];
__device__ __nv_bfloat16 g_qc_hi[S4 * HW * KD];
__device__ __nv_bfloat16 g_qc_lo[S4 * HW * KD];
__device__ __nv_bfloat16 g_wk_hi[S4 * NM * KD];
__device__ __nv_bfloat16 g_wk_lo[S4 * NM * KD];
__device__ __nv_bfloat16 g_w1_hi[KD * CD];
__device__ __nv_bfloat16 g_w1_lo[KD * CD];
__device__ __nv_bfloat16 g_w2_hi[KD * CD];
__device__ __nv_bfloat16 g_w2_lo[KD * CD];
__device__ __nv_bfloat16 g_pe_hi[16 * S4 * CE * HW];
__device__ __nv_bfloat16 g_pe_lo[16 * S4 * CE * HW];
__device__ float g_lpart[S4 * HW * 32];
__device__ float g_linv[S4 * HW];
__device__ float g_part[KSPLIT * S4 * HW * 18];

__device__ __forceinline__ void mma_bf16(float* c, uint32_t a0, uint32_t a1,
                                         uint32_t a2, uint32_t a3,
                                         uint32_t b0, uint32_t b1) {
  asm("mma.sync.aligned.m16n8k16.row.col.f32.bf16.bf16.f32 "
      "{%0,%1,%2,%3}, {%4,%5,%6,%7}, {%8,%9}, {%0,%1,%2,%3};"
      : "+f"(c[0]), "+f"(c[1]), "+f"(c[2]), "+f"(c[3])
      : "r"(a0), "r"(a1), "r"(a2), "r"(a3), "r"(b0), "r"(b1));
}
__device__ __forceinline__ uint32_t pack_hi2(float a, float b, float& la, float& lb) {
  __nv_bfloat16 h0 = __float2bfloat16(a), h1 = __float2bfloat16(b);
  la = a - __bfloat162float(h0);
  lb = b - __bfloat162float(h1);
  return (uint32_t)__bfloat16_as_ushort(h0) | ((uint32_t)__bfloat16_as_ushort(h1) << 16);
}
__device__ __forceinline__ uint32_t pack_bf2(float a, float b) {
  __nv_bfloat16 h0 = __float2bfloat16(a), h1 = __float2bfloat16(b);
  return (uint32_t)__bfloat16_as_ushort(h0) | ((uint32_t)__bfloat16_as_ushort(h1) << 16);
}

// ================= generic fp32 -> bf16 hi/lo splitter =================
__global__ __launch_bounds__(256) void split_v_kernel(
    const float* __restrict__ x,
    __nv_bfloat16* __restrict__ hi, __nv_bfloat16* __restrict__ lo) {
  int i = blockIdx.x * 1024 + threadIdx.x;
  #pragma unroll
  for (int r = 0; r < 4; r++, i += 256) {
    float v = x[i];
    __nv_bfloat16 h = __float2bfloat16(v);
    hi[i] = h;
    lo[i] = __float2bfloat16(v - __bfloat162float(h));
  }
}

// ================= HMMA projection + L2 normalize -> bf16 hi/lo =================
#define PASTR 72
#define POFF_AH 0
#define POFF_AL 9216
#define POFF_BH 18432
#define POFF_BL 36864
#define POFF_RED 55296
#define SMEM_PROJ 55808

__global__ __launch_bounds__(256, 1) void proj_mma_kernel(
    const float* __restrict__ in,
    const __nv_bfloat16* __restrict__ whi, const __nv_bfloat16* __restrict__ wlo,
    const float* __restrict__ bias,
    __nv_bfloat16* __restrict__ out_hi, __nv_bfloat16* __restrict__ out_lo,
    int NT) {
  extern __shared__ char smp[];
  __nv_bfloat16* Ah = (__nv_bfloat16*)(smp + POFF_AH);
  __nv_bfloat16* Al = (__nv_bfloat16*)(smp + POFF_AL);
  __nv_bfloat16* Bh = (__nv_bfloat16*)(smp + POFF_BH);
  __nv_bfloat16* Bl = (__nv_bfloat16*)(smp + POFF_BL);
  float* red = (float*)(smp + POFF_RED);
  int s = blockIdx.y;
  int tg0 = blockIdx.x * 64;
  int f = tg0 >> 10;
  int n0 = tg0 & 1023;
  const float* inb = in + ((size_t)(f * S4 + s)) * CD * HW + n0;
  int t = threadIdx.x;
  int w = t >> 5, lane = t & 31;
  int lr = lane >> 2, lc = lane & 3;
  int mq = (w & 3) * 16;
  int db = (w >> 2) * 64;
  float c[8][4];
  #pragma unroll
  for (int nt = 0; nt < 8; nt++)
    #pragma unroll
    for (int j = 0; j < 4; j++) c[nt][j] = 0.0f;

  for (int c0 = 0; c0 < CD; c0 += 64) {
    __syncthreads();
    #pragma unroll
    for (int r = 0; r < 16; r++) {
      int idx = t + r * 256;
      int tok = idx & 63, cc = idx >> 6;
      float v = inb[(size_t)(c0 + cc) * HW + tok];
      __nv_bfloat16 h = __float2bfloat16(v);
      Ah[tok * PASTR + cc] = h;
      Al[tok * PASTR + cc] = __float2bfloat16(v - __bfloat162float(h));
    }
    #pragma unroll
    for (int r = 0; r < 4; r++) {
      int idx = t + r * 256;
      int row = idx >> 3, u8 = (idx & 7) * 8;
      *(uint4*)(Bh + row * PASTR + u8) = *(const uint4*)(whi + (size_t)row * CD + c0 + u8);
      *(uint4*)(Bl + row * PASTR + u8) = *(const uint4*)(wlo + (size_t)row * CD + c0 + u8);
    }
    __syncthreads();
    const __nv_bfloat16* Ap[3] = {Ah, Al, Ah};
    const __nv_bfloat16* Bp[3] = {Bh, Bh, Bl};
    #pragma unroll
    for (int pass = 0; pass < 3; pass++) {
      const __nv_bfloat16* A = Ap[pass];
      const __nv_bfloat16* B = Bp[pass];
      #pragma unroll
      for (int ds = 0; ds < 4; ds++) {
        int d0 = ds * 16 + lc * 2;
        uint32_t a0 = *(const uint32_t*)(A + (mq + lr) * PASTR + d0);
        uint32_t a1 = *(const uint32_t*)(A + (mq + 8 + lr) * PASTR + d0);
        uint32_t a2 = *(const uint32_t*)(A + (mq + lr) * PASTR + d0 + 8);
        uint32_t a3 = *(const uint32_t*)(A + (mq + 8 + lr) * PASTR + d0 + 8);
        #pragma unroll
        for (int nt = 0; nt < 8; nt++) {
          const __nv_bfloat16* br = B + (db + nt * 8 + lr) * PASTR + d0;
          uint32_t b0 = *(const uint32_t*)(br);
          uint32_t b1 = *(const uint32_t*)(br + 8);
          mma_bf16(c[nt], a0, a1, a2, a3, b0, b1);
        }
      }
    }
  }
  float ssl = 0.0f, ssh = 0.0f;
  #pragma unroll
  for (int nt = 0; nt < 8; nt++) {
    int d = db + nt * 8 + lc * 2;
    float b0 = bias[d], b1 = bias[d + 1];
    c[nt][0] += b0; c[nt][1] += b1;
    c[nt][2] += b0; c[nt][3] += b1;
    ssl = fmaf(c[nt][0], c[nt][0], fmaf(c[nt][1], c[nt][1], ssl));
    ssh = fmaf(c[nt][2], c[nt][2], fmaf(c[nt][3], c[nt][3], ssh));
  }
  ssl += __shfl_xor_sync(0xffffffffu, ssl, 1);
  ssl += __shfl_xor_sync(0xffffffffu, ssl, 2);
  ssh += __shfl_xor_sync(0xffffffffu, ssh, 1);
  ssh += __shfl_xor_sync(0xffffffffu, ssh, 2);
  __syncthreads();
  if (lc == 0) {
    red[(mq + lr) * 2 + (w >> 2)]     = ssl;
    red[(mq + 8 + lr) * 2 + (w >> 2)] = ssh;
  }
  __syncthreads();
  float sl = 1.0f / fmaxf(sqrtf(red[(mq + lr) * 2] + red[(mq + lr) * 2 + 1]), 1e-12f);
  float sh = 1.0f / fmaxf(sqrtf(red[(mq + 8 + lr) * 2] + red[(mq + 8 + lr) * 2 + 1]), 1e-12f);
  size_t rb0 = ((size_t)s * NT + tg0 + mq + lr) * KD;
  size_t rb1 = ((size_t)s * NT + tg0 + mq + 8 + lr) * KD;
  #pragma unroll
  for (int nt = 0; nt < 8; nt++) {
    int d = db + nt * 8 + lc * 2;
    float v0 = c[nt][0] * sl, v1 = c[nt][1] * sl;
    float v2 = c[nt][2] * sh, v3 = c[nt][3] * sh;
    float l0, l1, l2, l3;
    uint32_t uh0 = pack_hi2(v0, v1, l0, l1);
    uint32_t uh1 = pack_hi2(v2, v3, l2, l3);
    *(uint32_t*)(out_hi + rb0 + d) = uh0;
    *(uint32_t*)(out_hi + rb1 + d) = uh1;
    *(uint32_t*)(out_lo + rb0 + d) = pack_bf2(l0, l1);
    *(uint32_t*)(out_lo + rb1 + d) = pack_bf2(l2, l3);
  }
}

// ================= self scores via HMMA -> exp bf16 hi/lo + row-sum partials =================
#define SQSTR 136
#define SOFF_AH 0
#define SOFF_AL 17408
#define SOFF_BH 34816
#define SOFF_BL 52224
#define SMEM_SS 69632

__global__ __launch_bounds__(256) void self_scores_mma(
    const __nv_bfloat16* __restrict__ qhi, const __nv_bfloat16* __restrict__ qlo,
    __nv_bfloat16* __restrict__ phi, __nv_bfloat16* __restrict__ plo,
    float* __restrict__ lpart) {
  extern __shared__ char sms[];
  __nv_bfloat16* Ah = (__nv_bfloat16*)(sms + SOFF_AH);
  __nv_bfloat16* Al = (__nv_bfloat16*)(sms + SOFF_AL);
  __nv_bfloat16* Bh = (__nv_bfloat16*)(sms + SOFF_BH);
  __nv_bfloat16* Bl = (__nv_bfloat16*)(sms + SOFF_BL);
  int s = blockIdx.z;
  int q0 = blockIdx.x * 64, k0 = blockIdx.y * 64;
  int t = threadIdx.x;
  int w = t >> 5, lane = t & 31;
  int lr = lane >> 2, lc = lane & 3;
  {
    const uint4* gah = (const uint4*)(qhi + ((size_t)s * HW + q0) * KD);
    const uint4* gal = (const uint4*)(qlo + ((size_t)s * HW + q0) * KD);
    const uint4* gbh = (const uint4*)(qhi + ((size_t)s * HW + k0) * KD);
    const uint4* gbl = (const uint4*)(qlo + ((size_t)s * HW + k0) * KD);
    #pragma unroll
    for (int r = 0; r < 4; r++) {
      int idx = t + r * 256;
      int row = idx >> 4, u8 = (idx & 15) * 8;
      *(uint4*)(Ah + row * SQSTR + u8) = gah[idx];
      *(uint4*)(Al + row * SQSTR + u8) = gal[idx];
      *(uint4*)(Bh + row * SQSTR + u8) = gbh[idx];
      *(uint4*)(Bl + row * SQSTR + u8) = gbl[idx];
    }
  }
  __syncthreads();
  int mq = (w & 3) * 16;
  int kb = (w >> 2) * 32;
  float c[4][4];
  #pragma unroll
  for (int nt = 0; nt < 4; nt++)
    #pragma unroll
    for (int j = 0; j < 4; j++) c[nt][j] = 0.0f;
  const __nv_bfloat16* Ap[3] = {Ah, Al, Ah};
  const __nv_bfloat16* Bp[3] = {Bh, Bh, Bl};
  #pragma unroll
  for (int pass = 0; pass < 3; pass++) {
    const __nv_bfloat16* A = Ap[pass];
    const __nv_bfloat16* B = Bp[pass];
    #pragma unroll
    for (int ds = 0; ds < 8; ds++) {
      int d0 = ds * 16 + lc * 2;
      uint32_t a0 = *(const uint32_t*)(A + (mq + lr) * SQSTR + d0);
      uint32_t a1 = *(const uint32_t*)(A + (mq + 8 + lr) * SQSTR + d0);
      uint32_t a2 = *(const uint32_t*)(A + (mq + lr) * SQSTR + d0 + 8);
      uint32_t a3 = *(const uint32_t*)(A + (mq + 8 + lr) * SQSTR + d0 + 8);
      #pragma unroll
      for (int nt = 0; nt < 4; nt++) {
        const __nv_bfloat16* br = B + (kb + nt * 8 + lr) * SQSTR + d0;
        uint32_t b0 = *(const uint32_t*)(br);
        uint32_t b1 = *(const uint32_t*)(br + 8);
        mma_bf16(c[nt], a0, a1, a2, a3, b0, b1);
      }
    }
  }
  float sl = 0.0f, sh = 0.0f;
  #pragma unroll
  for (int nt = 0; nt < 4; nt++) {
    float e0 = __expf(fmaf(c[nt][0], 30.0f, -30.0f));
    float e1 = __expf(fmaf(c[nt][1], 30.0f, -30.0f));
    float e2 = __expf(fmaf(c[nt][2], 30.0f, -30.0f));
    float e3 = __expf(fmaf(c[nt][3], 30.0f, -30.0f));
    sl += e0 + e1; sh += e2 + e3;
    int col = k0 + kb + nt * 8 + lc * 2;
    size_t g0 = ((size_t)s * HW + q0 + mq + lr) * HW + col;
    size_t g1 = ((size_t)s * HW + q0 + mq + 8 + lr) * HW + col;
    float l0, l1, l2, l3;
    *(uint32_t*)(phi + g0) = pack_hi2(e0, e1, l0, l1);
    *(uint32_t*)(phi + g1) = pack_hi2(e2, e3, l2, l3);
    *(uint32_t*)(plo + g0) = pack_bf2(l0, l1);
    *(uint32_t*)(plo + g1) = pack_bf2(l2, l3);
  }
  sl += __shfl_xor_sync(0xffffffffu, sl, 1);
  sl += __shfl_xor_sync(0xffffffffu, sl, 2);
  sh += __shfl_xor_sync(0xffffffffu, sh, 1);
  sh += __shfl_xor_sync(0xffffffffu, sh, 2);
  if (lc == 0) {
    int colp = (k0 >> 6) * 2 + (w >> 2);
    lpart[((size_t)s * HW + q0 + mq + lr) * 32 + colp]     = sl;
    lpart[((size_t)s * HW + q0 + mq + 8 + lr) * 32 + colp] = sh;
  }
}

// ================= row-sum reduce -> 1/L =================
__global__ __launch_bounds__(256) void rowsum_kernel(
    const float* __restrict__ lpart, float* __restrict__ linv) {
  int row = blockIdx.x * 256 + threadIdx.x;
  const float4* p = (const float4*)(lpart + (size_t)row * 32);
  float sum = 0.0f;
  #pragma unroll
  for (int i = 0; i < 8; i++) {
    float4 v = p[i];
    sum += v.x + v.y + v.z + v.w;
  }
  linv[row] = 1.0f / sum;
}

// ================= self P.V via HMMA, scaled by 1/L, + residual =================
#define CSTR 133
#define SMEM_PV 55296

__global__ __launch_bounds__(256) void pv_mma_kernel(
    const __nv_bfloat16* __restrict__ phi, const __nv_bfloat16* __restrict__ plo,
    const __nv_bfloat16* __restrict__ vhi, const __nv_bfloat16* __restrict__ vlo,
    const float* __restrict__ tgt, const float* __restrict__ linv,
    float* __restrict__ tout) {
  extern __shared__ char smv[];
  __nv_bfloat16* Ah = (__nv_bfloat16*)(smv + POFF_AH);
  __nv_bfloat16* Al = (__nv_bfloat16*)(smv + POFF_AL);
  __nv_bfloat16* Bh = (__nv_bfloat16*)(smv + POFF_BH);
  __nv_bfloat16* Bl = (__nv_bfloat16*)(smv + POFF_BL);
  float* Cs = (float*)smv;
  int s = blockIdx.z;
  int n0 = blockIdx.x * 64, c0 = blockIdx.y * 128;
  int t = threadIdx.x;
  int w = t >> 5, lane = t & 31;
  int lr = lane >> 2, lc = lane & 3;
  int mq = (w & 3) * 16;
  int db = (w >> 2) * 64;
  float c[8][4];
  #pragma unroll
  for (int nt = 0; nt < 8; nt++)
    #pragma unroll
    for (int j = 0; j < 4; j++) c[nt][j] = 0.0f;

  for (int m0 = 0; m0 < HW; m0 += 64) {
    __syncthreads();
    {
      const __nv_bfloat16* gph = phi + ((size_t)s * HW + n0) * HW + m0;
      const __nv_bfloat16* gpl = plo + ((size_t)s * HW + n0) * HW + m0;
      #pragma unroll
      for (int r = 0; r < 2; r++) {
        int idx = t + r * 256;
        int row = idx >> 3, u4 = (idx & 7) * 8;
        *(uint4*)(Ah + row * PASTR + u4) = *(const uint4*)(gph + (size_t)row * HW + u4);
        *(uint4*)(Al + row * PASTR + u4) = *(const uint4*)(gpl + (size_t)row * HW + u4);
      }
    }
    {
      const __nv_bfloat16* gvh = vhi + ((size_t)s * CD + c0) * HW + m0;
      const __nv_bfloat16* gvl = vlo + ((size_t)s * CD + c0) * HW + m0;
      #pragma unroll
      for (int r = 0; r < 4; r++) {
        int idx = t + r * 256;
        int row = idx >> 3, u4 = (idx & 7) * 8;
        *(uint4*)(Bh + row * PASTR + u4) = *(const uint4*)(gvh + (size_t)row * HW + u4);
        *(uint4*)(Bl + row * PASTR + u4) = *(const uint4*)(gvl + (size_t)row * HW + u4);
      }
    }
    __syncthreads();
    const __nv_bfloat16* Ap[3] = {Ah, Al, Ah};
    const __nv_bfloat16* Bp[3] = {Bh, Bh, Bl};
    #pragma unroll
    for (int pass = 0; pass < 3; pass++) {
      const __nv_bfloat16* A = Ap[pass];
      const __nv_bfloat16* B = Bp[pass];
      #pragma unroll
      for (int ds = 0; ds < 4; ds++) {
        int d0 = ds * 16 + lc * 2;
        uint32_t a0 = *(const uint32_t*)(A + (mq + lr) * PASTR + d0);
        uint32_t a1 = *(const uint32_t*)(A + (mq + 8 + lr) * PASTR + d0);
        uint32_t a2 = *(const uint32_t*)(A + (mq + lr) * PASTR + d0 + 8);
        uint32_t a3 = *(const uint32_t*)(A + (mq + 8 + lr) * PASTR + d0 + 8);
        #pragma unroll
        for (int nt = 0; nt < 8; nt++) {
          const __nv_bfloat16* br = B + (db + nt * 8 + lr) * PASTR + d0;
          uint32_t b0 = *(const uint32_t*)(br);
          uint32_t b1 = *(const uint32_t*)(br + 8);
          mma_bf16(c[nt], a0, a1, a2, a3, b0, b1);
        }
      }
    }
  }
  __syncthreads();
  #pragma unroll
  for (int nt = 0; nt < 8; nt++) {
    int col = db + nt * 8 + lc * 2;
    Cs[(mq + lr) * CSTR + col]         = c[nt][0];
    Cs[(mq + lr) * CSTR + col + 1]     = c[nt][1];
    Cs[(mq + 8 + lr) * CSTR + col]     = c[nt][2];
    Cs[(mq + 8 + lr) * CSTR + col + 1] = c[nt][3];
  }
  __syncthreads();
  #pragma unroll
  for (int r = 0; r < 32; r++) {
    int idx = t + r * 256;
    int cc = idx >> 6, n = idx & 63;
    size_t g = (size_t)(s * CD + c0 + cc) * HW + n0 + n;
    tout[g] = tgt[g] + Cs[n * CSTR + cc] * linv[s * HW + n0 + n];
  }
}

// ================= instance norm =================
__global__ __launch_bounds__(256) void instnorm_kernel(float* __restrict__ x) {
  __shared__ float redS[8];
  __shared__ float redQ[8];
  float* p = x + (size_t)blockIdx.x * HW;
  int t = threadIdx.x, lane = t & 31, warp = t >> 5;
  float v0 = p[t], v1 = p[t + 256], v2 = p[t + 512], v3 = p[t + 768];
  float sum = v0 + v1 + v2 + v3;
  float sq = v0 * v0 + v1 * v1 + v2 * v2 + v3 * v3;
  #pragma unroll
  for (int o = 16; o; o >>= 1) {
    sum += __shfl_xor_sync(0xffffffffu, sum, o);
    sq  += __shfl_xor_sync(0xffffffffu, sq, o);
  }
  if (lane == 0) { redS[warp] = sum; redQ[warp] = sq; }
  __syncthreads();
  sum = redS[0]; sq = redQ[0];
  #pragma unroll
  for (int i = 1; i < 8; i++) { sum += redS[i]; sq += redQ[i]; }
  float mean = sum * (1.0f / HW);
  float var = sq * (1.0f / HW) - mean * mean;
  float rstd = rsqrtf(var + 1e-5f);
  p[t]       = (v0 - mean) * rstd;
  p[t + 256] = (v1 - mean) * rstd;
  p[t + 512] = (v2 - mean) * rstd;
  p[t + 768] = (v3 - mean) * rstd;
}

// ================= cross attention: 128-q blocks, per-warp row ownership =================
#define QSTR 136
#define VSTR 136
#define XOFF_QH 0
#define XOFF_QL 34816
#define XOFF_KH 69632
#define XOFF_KL 104448
#define XOFF_VTH 139264
#define XOFF_VTL 143616
#define SMEM_CROSS 147968

__global__ __launch_bounds__(256, 1) void cross_attn_kernel(
    const __nv_bfloat16* __restrict__ qhi, const __nv_bfloat16* __restrict__ qlo,
    const __nv_bfloat16* __restrict__ khi, const __nv_bfloat16* __restrict__ klo,
    const __nv_bfloat16* __restrict__ pehi, const __nv_bfloat16* __restrict__ pelo,
    float* __restrict__ part) {
  extern __shared__ char smc[];
  __nv_bfloat16* Qh  = (__nv_bfloat16*)(smc + XOFF_QH);
  __nv_bfloat16* Ql  = (__nv_bfloat16*)(smc + XOFF_QL);
  __nv_bfloat16* Kh  = (__nv_bfloat16*)(smc + XOFF_KH);
  __nv_bfloat16* Kl  = (__nv_bfloat16*)(smc + XOFF_KL);
  __nv_bfloat16* Vth = (__nv_bfloat16*)(smc + XOFF_VTH);
  __nv_bfloat16* Vtl = (__nv_bfloat16*)(smc + XOFF_VTL);
  int qt = blockIdx.x, s = blockIdx.y, ksp = blockIdx.z;
  int q0 = qt * 128;
  int t = threadIdx.x;
  int w = t >> 5, lane = t & 31;
  int lr = lane >> 2, lc = lane & 3;
  int mq = w * 16;   // each warp owns 16 q rows fully

  // load Q hi/lo: 128 rows
  {
    const uint4* gqh = (const uint4*)(qhi + ((size_t)s * HW + q0) * KD);
    const uint4* gql = (const uint4*)(qlo + ((size_t)s * HW + q0) * KD);
    #pragma unroll
    for (int r = 0; r < 8; r++) {
      int idx = t + r * 256;
      int row = idx >> 4, u8 = (idx & 15) * 8;
      *(uint4*)(Qh + row * QSTR + u8) = gqh[idx];
      *(uint4*)(Ql + row * QSTR + u8) = gql[idx];
    }
  }
  float cpv[2][4];
  #pragma unroll
  for (int et = 0; et < 2; et++)
    #pragma unroll
    for (int j = 0; j < 4; j++) cpv[et][j] = 0.0f;
  float slacc = 0.0f, shacc = 0.0f;

  for (int kt = 0; kt < NM / (KSPLIT * 128); kt++) {
    int kk0 = ksp * (NM / KSPLIT) + kt * 128;
    __syncthreads();
    {
      const uint4* gh = (const uint4*)(khi + ((size_t)s * NM + kk0) * KD);
      const uint4* gl = (const uint4*)(klo + ((size_t)s * NM + kk0) * KD);
      #pragma unroll
      for (int r = 0; r < 8; r++) {
        int idx = t + r * 256;
        int key = idx >> 4, d8 = (idx & 15) * 8;
        *(uint4*)(Kh + key * QSTR + d8) = gh[idx];
        *(uint4*)(Kl + key * QSTR + d8) = gl[idx];
      }
    }
    {
      int f = kk0 >> 10, nn0 = kk0 & 1023;
      size_t pb = ((size_t)(f * S4 + s) * CE) * HW + nn0;
      int e = t >> 4, k8 = (t & 15) * 8;
      *(uint4*)(Vth + e * VSTR + k8) = *(const uint4*)(pehi + pb + (size_t)e * HW + k8);
      *(uint4*)(Vtl + e * VSTR + k8) = *(const uint4*)(pelo + pb + (size_t)e * HW + k8);
    }
    __syncthreads();
    // two k-halves processed sequentially by the same warp
    #pragma unroll
    for (int half = 0; half < 2; half++) {
      int kb = half * 64;
      float c[8][4];
      #pragma unroll
      for (int nt = 0; nt < 8; nt++)
        #pragma unroll
        for (int j = 0; j < 4; j++) c[nt][j] = 0.0f;
      const __nv_bfloat16* Ap[3] = {Qh, Ql, Qh};
      const __nv_bfloat16* Bp[3] = {Kh, Kh, Kl};
      #pragma unroll
      for (int pass = 0; pass < 3; pass++) {
        const __nv_bfloat16* A = Ap[pass];
        const __nv_bfloat16* B = Bp[pass];
        #pragma unroll
        for (int ds = 0; ds < 8; ds++) {
          int d0 = ds * 16 + lc * 2;
          uint32_t a0 = *(const uint32_t*)(A + (mq + lr) * QSTR + d0);
          uint32_t a1 = *(const uint32_t*)(A + (mq + 8 + lr) * QSTR + d0);
          uint32_t a2 = *(const uint32_t*)(A + (mq + lr) * QSTR + d0 + 8);
          uint32_t a3 = *(const uint32_t*)(A + (mq + 8 + lr) * QSTR + d0 + 8);
          #pragma unroll
          for (int nt = 0; nt < 8; nt++) {
            const __nv_bfloat16* br = B + (kb + nt * 8 + lr) * QSTR + d0;
            uint32_t b0 = *(const uint32_t*)(br);
            uint32_t b1 = *(const uint32_t*)(br + 8);
            mma_bf16(c[nt], a0, a1, a2, a3, b0, b1);
          }
        }
      }
      uint32_t ph[4][4], pl[4][4];
      #pragma unroll
      for (int ks = 0; ks < 4; ks++) {
        #pragma unroll
        for (int h2 = 0; h2 < 2; h2++) {
          int nt = 2 * ks + h2;
          float e0 = __expf(fmaf(c[nt][0], 30.0f, -30.0f));
          float e1 = __expf(fmaf(c[nt][1], 30.0f, -30.0f));
          float e2 = __expf(fmaf(c[nt][2], 30.0f, -30.0f));
          float e3 = __expf(fmaf(c[nt][3], 30.0f, -30.0f));
          slacc += e0 + e1;
          shacc += e2 + e3;
          float l0, l1, l2, l3;
          ph[ks][0 + h2 * 2] = pack_hi2(e0, e1, l0, l1);
          ph[ks][1 + h2 * 2] = pack_hi2(e2, e3, l2, l3);
          pl[ks][0 + h2 * 2] = pack_bf2(l0, l1);
          pl[ks][1 + h2 * 2] = pack_bf2(l2, l3);
        }
      }
      #pragma unroll
      for (int pass = 0; pass < 3; pass++) {
        const __nv_bfloat16* Vt = (pass == 2) ? Vtl : Vth;
        #pragma unroll
        for (int ks = 0; ks < 4; ks++) {
          uint32_t a0, a1, a2, a3;
          if (pass == 1) { a0 = pl[ks][0]; a1 = pl[ks][1]; a2 = pl[ks][2]; a3 = pl[ks][3]; }
          else           { a0 = ph[ks][0]; a1 = ph[ks][1]; a2 = ph[ks][2]; a3 = ph[ks][3]; }
          int d0 = kb + ks * 16 + lc * 2;
          #pragma unroll
          for (int et = 0; et < 2; et++) {
            const __nv_bfloat16* br = Vt + (et * 8 + lr) * VSTR + d0;
            uint32_t b0 = *(const uint32_t*)(br);
            uint32_t b1 = *(const uint32_t*)(br + 8);
            mma_bf16(cpv[et], a0, a1, a2, a3, b0, b1);
          }
        }
      }
    }
  }
  // row sums: quad-reduce within warp
  slacc += __shfl_xor_sync(0xffffffffu, slacc, 1);
  slacc += __shfl_xor_sync(0xffffffffu, slacc, 2);
  shacc += __shfl_xor_sync(0xffffffffu, shacc, 1);
  shacc += __shfl_xor_sync(0xffffffffu, shacc, 2);
  // write partials straight from registers (warp owns its rows)
  {
    float* pp0 = part + (((size_t)(ksp * S4 + s) * HW) + q0 + mq + lr) * 18;
    float* pp1 = part + (((size_t)(ksp * S4 + s) * HW) + q0 + mq + 8 + lr) * 18;
    #pragma unroll
    for (int et = 0; et < 2; et++) {
      int col = et * 8 + lc * 2;
      pp0[col]     = cpv[et][0];
      pp0[col + 1] = cpv[et][1];
      pp1[col]     = cpv[et][2];
      pp1[col + 1] = cpv[et][3];
    }
    if (lc == 0) {
      pp0[16] = slacc;
      pp1[16] = shacc;
    }
  }
}

// ================= merge split-K partials + sigmoid =================
__global__ __launch_bounds__(256) void merge_kernel(
    const float* __restrict__ part, float* __restrict__ out) {
  int g = blockIdx.x * 256 + threadIdx.x;
  int eg = (g & 3) * 4;
  int sn = g >> 2;
  int n = sn & 1023, s = sn >> 10;
  float L = 0.0f;
  float O[4] = {};
  #pragma unroll
  for (int z = 0; z < KSPLIT; z++) {
    const float* pp = part + ((size_t)((z * S4 + s) * HW) + n) * 18;
    L += pp[16];
    #pragma unroll
    for (int e = 0; e < 4; e++) O[e] += pp[eg + e];
  }
  float inv = 1.0f / L;
  #pragma unroll
  for (int e = 0; e < 4; e++) {
    float v = O[e] * inv;
    out[(size_t)(s * CE + eg + e) * HW + n] = 1.0f / (1.0f + __expf(-v));
  }
}

// ================= host =================
extern "C" void kernel_launch(void* const* d_in, const int* in_sizes, int n_in,
                              void* d_out, int out_size) {
  const float* tgt = (const float*)d_in[0];
  const float* mem = (const float*)d_in[1];
  const float* pe  = (const float*)d_in[2];
  const float* wks = (const float*)d_in[3];
  const float* bks = (const float*)d_in[4];
  const float* wkc = (const float*)d_in[5];
  const float* bkc = (const float*)d_in[6];
  float* out = (float*)d_out;

  float *p_t, *p_part, *p_lpart, *p_linv;
  __nv_bfloat16 *p_wk_hi, *p_wk_lo, *p_p_hi, *p_p_lo, *p_v_hi, *p_v_lo;
  __nv_bfloat16 *p_qs_hi, *p_qs_lo, *p_qc_hi, *p_qc_lo;
  __nv_bfloat16 *p_w1_hi, *p_w1_lo, *p_w2_hi, *p_w2_lo, *p_pe_hi, *p_pe_lo;
  cudaGetSymbolAddress((void**)&p_t, g_t);
  cudaGetSymbolAddress((void**)&p_wk_hi, g_wk_hi);
  cudaGetSymbolAddress((void**)&p_wk_lo, g_wk_lo);
  cudaGetSymbolAddress((void**)&p_p_hi, g_p_hi);
  cudaGetSymbolAddress((void**)&p_p_lo, g_p_lo);
  cudaGetSymbolAddress((void**)&p_v_hi, g_v_hi);
  cudaGetSymbolAddress((void**)&p_v_lo, g_v_lo);
  cudaGetSymbolAddress((void**)&p_qs_hi, g_qs_hi);
  cudaGetSymbolAddress((void**)&p_qs_lo, g_qs_lo);
  cudaGetSymbolAddress((void**)&p_qc_hi, g_qc_hi);
  cudaGetSymbolAddress((void**)&p_qc_lo, g_qc_lo);
  cudaGetSymbolAddress((void**)&p_w1_hi, g_w1_hi);
  cudaGetSymbolAddress((void**)&p_w1_lo, g_w1_lo);
  cudaGetSymbolAddress((void**)&p_w2_hi, g_w2_hi);
  cudaGetSymbolAddress((void**)&p_w2_lo, g_w2_lo);
  cudaGetSymbolAddress((void**)&p_pe_hi, g_pe_hi);
  cudaGetSymbolAddress((void**)&p_pe_lo, g_pe_lo);
  cudaGetSymbolAddress((void**)&p_lpart, g_lpart);
  cudaGetSymbolAddress((void**)&p_linv, g_linv);
  cudaGetSymbolAddress((void**)&p_part, g_part);

  cudaFuncSetAttribute(proj_mma_kernel,
                       cudaFuncAttributeMaxDynamicSharedMemorySize, SMEM_PROJ);
  cudaFuncSetAttribute(self_scores_mma,
                       cudaFuncAttributeMaxDynamicSharedMemorySize, SMEM_SS);
  cudaFuncSetAttribute(pv_mma_kernel,
                       cudaFuncAttributeMaxDynamicSharedMemorySize, SMEM_PV);
  cudaFuncSetAttribute(cross_attn_kernel,
                       cudaFuncAttributeMaxDynamicSharedMemorySize, SMEM_CROSS);

  // constant pre-splits
  split_v_kernel<<<64, 256>>>(wks, p_w1_hi, p_w1_lo);
  split_v_kernel<<<64, 256>>>(wkc, p_w2_hi, p_w2_lo);
  split_v_kernel<<<1024, 256>>>(pe, p_pe_hi, p_pe_lo);
  split_v_kernel<<<2048, 256>>>(tgt, p_v_hi, p_v_lo);

  // self-attention
  proj_mma_kernel<<<dim3(16, 4), 256, SMEM_PROJ>>>(tgt, p_w1_hi, p_w1_lo, bks, p_qs_hi, p_qs_lo, HW);
  self_scores_mma<<<dim3(16, 16, 4), 256, SMEM_SS>>>(p_qs_hi, p_qs_lo, p_p_hi, p_p_lo, p_lpart);
  rowsum_kernel<<<16, 256>>>(p_lpart, p_linv);
  pv_mma_kernel<<<dim3(16, 4, 4), 256, SMEM_PV>>>(p_p_hi, p_p_lo, p_v_hi, p_v_lo, tgt, p_linv, p_t);
  instnorm_kernel<<<2048, 256>>>(p_t);

  // cross projections
  proj_mma_kernel<<<dim3(16, 4), 256, SMEM_PROJ>>>(p_t, p_w2_hi, p_w2_lo, bkc, p_qc_hi, p_qc_lo, HW);
  proj_mma_kernel<<<dim3(256, 4), 256, SMEM_PROJ>>>(mem, p_w2_hi, p_w2_lo, bkc, p_wk_hi, p_wk_lo, NM);

  // HMMA cross-attention (128-q blocks)
  cross_attn_kernel<<<dim3(8, 4, KSPLIT), 256, SMEM_CROSS>>>(
      p_qc_hi, p_qc_lo, p_wk_hi, p_wk_lo, p_pe_hi, p_pe_lo, p_part);
  merge_kernel<<<64, 256>>>(p_part, out);
}

// round 15
// speedup vs baseline: 2.3305x; 1.0223x over previous
#include <cuda_runtime.h>
#include <cuda_bf16.h>
#include <math.h>
#include <stdint.h>

#define S4 4
#define CD 512
#define KD 128
#define HW 1024
#define NM 16384
#define CE 16
#define KSPLIT 16

// ---------------- scratch ----------------
__device__ __nv_bfloat16 g_p_hi[S4 * HW * HW];
__device__ __nv_bfloat16 g_p_lo[S4 * HW * HW];
__device__ __nv_bfloat16 g_v_hi[S4 * CD * HW];
__device__ __nv_bfloat16 g_v_lo[S4 * CD * HW];
__device__ float g_t[S4 * CD * HW];
__device__ __nv_bfloat16 g_qs_hi[S4 * HW * KD];
__device__ __nv_bfloat16 g_qs_lo[S4 * HW * KD];
__device__ __nv_bfloat16 g_qc_hi[S4 * HW * KD];
__device__ __nv_bfloat16 g_qc_lo[S4 * HW * KD];
__device__ __nv_bfloat16 g_wk_hi[S4 * NM * KD];
__device__ __nv_bfloat16 g_wk_lo[S4 * NM * KD];
__device__ __nv_bfloat16 g_w1_hi[KD * CD];
__device__ __nv_bfloat16 g_w1_lo[KD * CD];
__device__ __nv_bfloat16 g_w2_hi[KD * CD];
__device__ __nv_bfloat16 g_w2_lo[KD * CD];
__device__ __nv_bfloat16 g_pe_hi[16 * S4 * CE * HW];
__device__ __nv_bfloat16 g_pe_lo[16 * S4 * CE * HW];
__device__ float g_lpart[S4 * HW * 32];
__device__ float g_linv[S4 * HW];
__device__ float g_part[KSPLIT * S4 * HW * 18];

__device__ __forceinline__ void mma_bf16(float* c, uint32_t a0, uint32_t a1,
                                         uint32_t a2, uint32_t a3,
                                         uint32_t b0, uint32_t b1) {
  asm("mma.sync.aligned.m16n8k16.row.col.f32.bf16.bf16.f32 "
      "{%0,%1,%2,%3}, {%4,%5,%6,%7}, {%8,%9}, {%0,%1,%2,%3};"
      : "+f"(c[0]), "+f"(c[1]), "+f"(c[2]), "+f"(c[3])
      : "r"(a0), "r"(a1), "r"(a2), "r"(a3), "r"(b0), "r"(b1));
}
__device__ __forceinline__ uint32_t pack_hi2(float a, float b, float& la, float& lb) {
  __nv_bfloat16 h0 = __float2bfloat16(a), h1 = __float2bfloat16(b);
  la = a - __bfloat162float(h0);
  lb = b - __bfloat162float(h1);
  return (uint32_t)__bfloat16_as_ushort(h0) | ((uint32_t)__bfloat16_as_ushort(h1) << 16);
}
__device__ __forceinline__ uint32_t pack_bf2(float a, float b) {
  __nv_bfloat16 h0 = __float2bfloat16(a), h1 = __float2bfloat16(b);
  return (uint32_t)__bfloat16_as_ushort(h0) | ((uint32_t)__bfloat16_as_ushort(h1) << 16);
}

// ================= generic fp32 -> bf16 hi/lo splitter =================
__global__ __launch_bounds__(256) void split_v_kernel(
    const float* __restrict__ x,
    __nv_bfloat16* __restrict__ hi, __nv_bfloat16* __restrict__ lo) {
  int i = blockIdx.x * 1024 + threadIdx.x;
  #pragma unroll
  for (int r = 0; r < 4; r++, i += 256) {
    float v = x[i];
    __nv_bfloat16 h = __float2bfloat16(v);
    hi[i] = h;
    lo[i] = __float2bfloat16(v - __bfloat162float(h));
  }
}

// ================= HMMA projection + L2 normalize -> bf16 hi/lo =================
#define PASTR 72
#define POFF_AH 0
#define POFF_AL 9216
#define POFF_BH 18432
#define POFF_BL 36864
#define POFF_RED 55296
#define SMEM_PROJ 55808

__global__ __launch_bounds__(256, 1) void proj_mma_kernel(
    const float* __restrict__ in,
    const __nv_bfloat16* __restrict__ whi, const __nv_bfloat16* __restrict__ wlo,
    const float* __restrict__ bias,
    __nv_bfloat16* __restrict__ out_hi, __nv_bfloat16* __restrict__ out_lo,
    int NT) {
  extern __shared__ char smp[];
  __nv_bfloat16* Ah = (__nv_bfloat16*)(smp + POFF_AH);
  __nv_bfloat16* Al = (__nv_bfloat16*)(smp + POFF_AL);
  __nv_bfloat16* Bh = (__nv_bfloat16*)(smp + POFF_BH);
  __nv_bfloat16* Bl = (__nv_bfloat16*)(smp + POFF_BL);
  float* red = (float*)(smp + POFF_RED);
  int s = blockIdx.y;
  int tg0 = blockIdx.x * 64;
  int f = tg0 >> 10;
  int n0 = tg0 & 1023;
  const float* inb = in + ((size_t)(f * S4 + s)) * CD * HW + n0;
  int t = threadIdx.x;
  int w = t >> 5, lane = t & 31;
  int lr = lane >> 2, lc = lane & 3;
  int mq = (w & 3) * 16;
  int db = (w >> 2) * 64;
  float c[8][4];
  #pragma unroll
  for (int nt = 0; nt < 8; nt++)
    #pragma unroll
    for (int j = 0; j < 4; j++) c[nt][j] = 0.0f;

  for (int c0 = 0; c0 < CD; c0 += 64) {
    __syncthreads();
    #pragma unroll
    for (int r = 0; r < 16; r++) {
      int idx = t + r * 256;
      int tok = idx & 63, cc = idx >> 6;
      float v = inb[(size_t)(c0 + cc) * HW + tok];
      __nv_bfloat16 h = __float2bfloat16(v);
      Ah[tok * PASTR + cc] = h;
      Al[tok * PASTR + cc] = __float2bfloat16(v - __bfloat162float(h));
    }
    #pragma unroll
    for (int r = 0; r < 4; r++) {
      int idx = t + r * 256;
      int row = idx >> 3, u8 = (idx & 7) * 8;
      *(uint4*)(Bh + row * PASTR + u8) = *(const uint4*)(whi + (size_t)row * CD + c0 + u8);
      *(uint4*)(Bl + row * PASTR + u8) = *(const uint4*)(wlo + (size_t)row * CD + c0 + u8);
    }
    __syncthreads();
    // fused 3-pass: c += Ah*Bh + Al*Bh + Ah*Bl
    #pragma unroll
    for (int ds = 0; ds < 4; ds++) {
      int d0 = ds * 16 + lc * 2;
      uint32_t ah0 = *(const uint32_t*)(Ah + (mq + lr) * PASTR + d0);
      uint32_t ah1 = *(const uint32_t*)(Ah + (mq + 8 + lr) * PASTR + d0);
      uint32_t ah2 = *(const uint32_t*)(Ah + (mq + lr) * PASTR + d0 + 8);
      uint32_t ah3 = *(const uint32_t*)(Ah + (mq + 8 + lr) * PASTR + d0 + 8);
      uint32_t al0 = *(const uint32_t*)(Al + (mq + lr) * PASTR + d0);
      uint32_t al1 = *(const uint32_t*)(Al + (mq + 8 + lr) * PASTR + d0);
      uint32_t al2 = *(const uint32_t*)(Al + (mq + lr) * PASTR + d0 + 8);
      uint32_t al3 = *(const uint32_t*)(Al + (mq + 8 + lr) * PASTR + d0 + 8);
      #pragma unroll
      for (int nt = 0; nt < 8; nt++) {
        const __nv_bfloat16* brh = Bh + (db + nt * 8 + lr) * PASTR + d0;
        uint32_t bh0 = *(const uint32_t*)(brh);
        uint32_t bh1 = *(const uint32_t*)(brh + 8);
        mma_bf16(c[nt], ah0, ah1, ah2, ah3, bh0, bh1);
        mma_bf16(c[nt], al0, al1, al2, al3, bh0, bh1);
        const __nv_bfloat16* brl = Bl + (db + nt * 8 + lr) * PASTR + d0;
        uint32_t bl0 = *(const uint32_t*)(brl);
        uint32_t bl1 = *(const uint32_t*)(brl + 8);
        mma_bf16(c[nt], ah0, ah1, ah2, ah3, bl0, bl1);
      }
    }
  }
  float ssl = 0.0f, ssh = 0.0f;
  #pragma unroll
  for (int nt = 0; nt < 8; nt++) {
    int d = db + nt * 8 + lc * 2;
    float b0 = bias[d], b1 = bias[d + 1];
    c[nt][0] += b0; c[nt][1] += b1;
    c[nt][2] += b0; c[nt][3] += b1;
    ssl = fmaf(c[nt][0], c[nt][0], fmaf(c[nt][1], c[nt][1], ssl));
    ssh = fmaf(c[nt][2], c[nt][2], fmaf(c[nt][3], c[nt][3], ssh));
  }
  ssl += __shfl_xor_sync(0xffffffffu, ssl, 1);
  ssl += __shfl_xor_sync(0xffffffffu, ssl, 2);
  ssh += __shfl_xor_sync(0xffffffffu, ssh, 1);
  ssh += __shfl_xor_sync(0xffffffffu, ssh, 2);
  __syncthreads();
  if (lc == 0) {
    red[(mq + lr) * 2 + (w >> 2)]     = ssl;
    red[(mq + 8 + lr) * 2 + (w >> 2)] = ssh;
  }
  __syncthreads();
  float sl = 1.0f / fmaxf(sqrtf(red[(mq + lr) * 2] + red[(mq + lr) * 2 + 1]), 1e-12f);
  float sh = 1.0f / fmaxf(sqrtf(red[(mq + 8 + lr) * 2] + red[(mq + 8 + lr) * 2 + 1]), 1e-12f);
  size_t rb0 = ((size_t)s * NT + tg0 + mq + lr) * KD;
  size_t rb1 = ((size_t)s * NT + tg0 + mq + 8 + lr) * KD;
  #pragma unroll
  for (int nt = 0; nt < 8; nt++) {
    int d = db + nt * 8 + lc * 2;
    float v0 = c[nt][0] * sl, v1 = c[nt][1] * sl;
    float v2 = c[nt][2] * sh, v3 = c[nt][3] * sh;
    float l0, l1, l2, l3;
    uint32_t uh0 = pack_hi2(v0, v1, l0, l1);
    uint32_t uh1 = pack_hi2(v2, v3, l2, l3);
    *(uint32_t*)(out_hi + rb0 + d) = uh0;
    *(uint32_t*)(out_hi + rb1 + d) = uh1;
    *(uint32_t*)(out_lo + rb0 + d) = pack_bf2(l0, l1);
    *(uint32_t*)(out_lo + rb1 + d) = pack_bf2(l2, l3);
  }
}

// ================= self scores via HMMA -> exp bf16 hi/lo + row-sum partials =================
#define SQSTR 136
#define SOFF_AH 0
#define SOFF_AL 17408
#define SOFF_BH 34816
#define SOFF_BL 52224
#define SMEM_SS 69632

__global__ __launch_bounds__(256) void self_scores_mma(
    const __nv_bfloat16* __restrict__ qhi, const __nv_bfloat16* __restrict__ qlo,
    __nv_bfloat16* __restrict__ phi, __nv_bfloat16* __restrict__ plo,
    float* __restrict__ lpart) {
  extern __shared__ char sms[];
  __nv_bfloat16* Ah = (__nv_bfloat16*)(sms + SOFF_AH);
  __nv_bfloat16* Al = (__nv_bfloat16*)(sms + SOFF_AL);
  __nv_bfloat16* Bh = (__nv_bfloat16*)(sms + SOFF_BH);
  __nv_bfloat16* Bl = (__nv_bfloat16*)(sms + SOFF_BL);
  int s = blockIdx.z;
  int q0 = blockIdx.x * 64, k0 = blockIdx.y * 64;
  int t = threadIdx.x;
  int w = t >> 5, lane = t & 31;
  int lr = lane >> 2, lc = lane & 3;
  {
    const uint4* gah = (const uint4*)(qhi + ((size_t)s * HW + q0) * KD);
    const uint4* gal = (const uint4*)(qlo + ((size_t)s * HW + q0) * KD);
    const uint4* gbh = (const uint4*)(qhi + ((size_t)s * HW + k0) * KD);
    const uint4* gbl = (const uint4*)(qlo + ((size_t)s * HW + k0) * KD);
    #pragma unroll
    for (int r = 0; r < 4; r++) {
      int idx = t + r * 256;
      int row = idx >> 4, u8 = (idx & 15) * 8;
      *(uint4*)(Ah + row * SQSTR + u8) = gah[idx];
      *(uint4*)(Al + row * SQSTR + u8) = gal[idx];
      *(uint4*)(Bh + row * SQSTR + u8) = gbh[idx];
      *(uint4*)(Bl + row * SQSTR + u8) = gbl[idx];
    }
  }
  __syncthreads();
  int mq = (w & 3) * 16;
  int kb = (w >> 2) * 32;
  float c[4][4];
  #pragma unroll
  for (int nt = 0; nt < 4; nt++)
    #pragma unroll
    for (int j = 0; j < 4; j++) c[nt][j] = 0.0f;
  #pragma unroll
  for (int ds = 0; ds < 8; ds++) {
    int d0 = ds * 16 + lc * 2;
    uint32_t ah0 = *(const uint32_t*)(Ah + (mq + lr) * SQSTR + d0);
    uint32_t ah1 = *(const uint32_t*)(Ah + (mq + 8 + lr) * SQSTR + d0);
    uint32_t ah2 = *(const uint32_t*)(Ah + (mq + lr) * SQSTR + d0 + 8);
    uint32_t ah3 = *(const uint32_t*)(Ah + (mq + 8 + lr) * SQSTR + d0 + 8);
    uint32_t al0 = *(const uint32_t*)(Al + (mq + lr) * SQSTR + d0);
    uint32_t al1 = *(const uint32_t*)(Al + (mq + 8 + lr) * SQSTR + d0);
    uint32_t al2 = *(const uint32_t*)(Al + (mq + lr) * SQSTR + d0 + 8);
    uint32_t al3 = *(const uint32_t*)(Al + (mq + 8 + lr) * SQSTR + d0 + 8);
    #pragma unroll
    for (int nt = 0; nt < 4; nt++) {
      const __nv_bfloat16* brh = Bh + (kb + nt * 8 + lr) * SQSTR + d0;
      uint32_t bh0 = *(const uint32_t*)(brh);
      uint32_t bh1 = *(const uint32_t*)(brh + 8);
      mma_bf16(c[nt], ah0, ah1, ah2, ah3, bh0, bh1);
      mma_bf16(c[nt], al0, al1, al2, al3, bh0, bh1);
      const __nv_bfloat16* brl = Bl + (kb + nt * 8 + lr) * SQSTR + d0;
      uint32_t bl0 = *(const uint32_t*)(brl);
      uint32_t bl1 = *(const uint32_t*)(brl + 8);
      mma_bf16(c[nt], ah0, ah1, ah2, ah3, bl0, bl1);
    }
  }
  float sl = 0.0f, sh = 0.0f;
  #pragma unroll
  for (int nt = 0; nt < 4; nt++) {
    float e0 = __expf(fmaf(c[nt][0], 30.0f, -30.0f));
    float e1 = __expf(fmaf(c[nt][1], 30.0f, -30.0f));
    float e2 = __expf(fmaf(c[nt][2], 30.0f, -30.0f));
    float e3 = __expf(fmaf(c[nt][3], 30.0f, -30.0f));
    sl += e0 + e1; sh += e2 + e3;
    int col = k0 + kb + nt * 8 + lc * 2;
    size_t g0 = ((size_t)s * HW + q0 + mq + lr) * HW + col;
    size_t g1 = ((size_t)s * HW + q0 + mq + 8 + lr) * HW + col;
    float l0, l1, l2, l3;
    *(uint32_t*)(phi + g0) = pack_hi2(e0, e1, l0, l1);
    *(uint32_t*)(phi + g1) = pack_hi2(e2, e3, l2, l3);
    *(uint32_t*)(plo + g0) = pack_bf2(l0, l1);
    *(uint32_t*)(plo + g1) = pack_bf2(l2, l3);
  }
  sl += __shfl_xor_sync(0xffffffffu, sl, 1);
  sl += __shfl_xor_sync(0xffffffffu, sl, 2);
  sh += __shfl_xor_sync(0xffffffffu, sh, 1);
  sh += __shfl_xor_sync(0xffffffffu, sh, 2);
  if (lc == 0) {
    int colp = (k0 >> 6) * 2 + (w >> 2);
    lpart[((size_t)s * HW + q0 + mq + lr) * 32 + colp]     = sl;
    lpart[((size_t)s * HW + q0 + mq + 8 + lr) * 32 + colp] = sh;
  }
}

// ================= row-sum reduce -> 1/L =================
__global__ __launch_bounds__(256) void rowsum_kernel(
    const float* __restrict__ lpart, float* __restrict__ linv) {
  int row = blockIdx.x * 256 + threadIdx.x;
  const float4* p = (const float4*)(lpart + (size_t)row * 32);
  float sum = 0.0f;
  #pragma unroll
  for (int i = 0; i < 8; i++) {
    float4 v = p[i];
    sum += v.x + v.y + v.z + v.w;
  }
  linv[row] = 1.0f / sum;
}

// ================= self P.V via HMMA, scaled by 1/L, + residual =================
#define CSTR 133
#define SMEM_PV 55296

__global__ __launch_bounds__(256) void pv_mma_kernel(
    const __nv_bfloat16* __restrict__ phi, const __nv_bfloat16* __restrict__ plo,
    const __nv_bfloat16* __restrict__ vhi, const __nv_bfloat16* __restrict__ vlo,
    const float* __restrict__ tgt, const float* __restrict__ linv,
    float* __restrict__ tout) {
  extern __shared__ char smv[];
  __nv_bfloat16* Ah = (__nv_bfloat16*)(smv + POFF_AH);
  __nv_bfloat16* Al = (__nv_bfloat16*)(smv + POFF_AL);
  __nv_bfloat16* Bh = (__nv_bfloat16*)(smv + POFF_BH);
  __nv_bfloat16* Bl = (__nv_bfloat16*)(smv + POFF_BL);
  float* Cs = (float*)smv;
  int s = blockIdx.z;
  int n0 = blockIdx.x * 64, c0 = blockIdx.y * 128;
  int t = threadIdx.x;
  int w = t >> 5, lane = t & 31;
  int lr = lane >> 2, lc = lane & 3;
  int mq = (w & 3) * 16;
  int db = (w >> 2) * 64;
  float c[8][4];
  #pragma unroll
  for (int nt = 0; nt < 8; nt++)
    #pragma unroll
    for (int j = 0; j < 4; j++) c[nt][j] = 0.0f;

  for (int m0 = 0; m0 < HW; m0 += 64) {
    __syncthreads();
    {
      const __nv_bfloat16* gph = phi + ((size_t)s * HW + n0) * HW + m0;
      const __nv_bfloat16* gpl = plo + ((size_t)s * HW + n0) * HW + m0;
      #pragma unroll
      for (int r = 0; r < 2; r++) {
        int idx = t + r * 256;
        int row = idx >> 3, u4 = (idx & 7) * 8;
        *(uint4*)(Ah + row * PASTR + u4) = *(const uint4*)(gph + (size_t)row * HW + u4);
        *(uint4*)(Al + row * PASTR + u4) = *(const uint4*)(gpl + (size_t)row * HW + u4);
      }
    }
    {
      const __nv_bfloat16* gvh = vhi + ((size_t)s * CD + c0) * HW + m0;
      const __nv_bfloat16* gvl = vlo + ((size_t)s * CD + c0) * HW + m0;
      #pragma unroll
      for (int r = 0; r < 4; r++) {
        int idx = t + r * 256;
        int row = idx >> 3, u4 = (idx & 7) * 8;
        *(uint4*)(Bh + row * PASTR + u4) = *(const uint4*)(gvh + (size_t)row * HW + u4);
        *(uint4*)(Bl + row * PASTR + u4) = *(const uint4*)(gvl + (size_t)row * HW + u4);
      }
    }
    __syncthreads();
    #pragma unroll
    for (int ds = 0; ds < 4; ds++) {
      int d0 = ds * 16 + lc * 2;
      uint32_t ah0 = *(const uint32_t*)(Ah + (mq + lr) * PASTR + d0);
      uint32_t ah1 = *(const uint32_t*)(Ah + (mq + 8 + lr) * PASTR + d0);
      uint32_t ah2 = *(const uint32_t*)(Ah + (mq + lr) * PASTR + d0 + 8);
      uint32_t ah3 = *(const uint32_t*)(Ah + (mq + 8 + lr) * PASTR + d0 + 8);
      uint32_t al0 = *(const uint32_t*)(Al + (mq + lr) * PASTR + d0);
      uint32_t al1 = *(const uint32_t*)(Al + (mq + 8 + lr) * PASTR + d0);
      uint32_t al2 = *(const uint32_t*)(Al + (mq + lr) * PASTR + d0 + 8);
      uint32_t al3 = *(const uint32_t*)(Al + (mq + 8 + lr) * PASTR + d0 + 8);
      #pragma unroll
      for (int nt = 0; nt < 8; nt++) {
        const __nv_bfloat16* brh = Bh + (db + nt * 8 + lr) * PASTR + d0;
        uint32_t bh0 = *(const uint32_t*)(brh);
        uint32_t bh1 = *(const uint32_t*)(brh + 8);
        mma_bf16(c[nt], ah0, ah1, ah2, ah3, bh0, bh1);
        mma_bf16(c[nt], al0, al1, al2, al3, bh0, bh1);
        const __nv_bfloat16* brl = Bl + (db + nt * 8 + lr) * PASTR + d0;
        uint32_t bl0 = *(const uint32_t*)(brl);
        uint32_t bl1 = *(const uint32_t*)(brl + 8);
        mma_bf16(c[nt], ah0, ah1, ah2, ah3, bl0, bl1);
      }
    }
  }
  __syncthreads();
  #pragma unroll
  for (int nt = 0; nt < 8; nt++) {
    int col = db + nt * 8 + lc * 2;
    Cs[(mq + lr) * CSTR + col]         = c[nt][0];
    Cs[(mq + lr) * CSTR + col + 1]     = c[nt][1];
    Cs[(mq + 8 + lr) * CSTR + col]     = c[nt][2];
    Cs[(mq + 8 + lr) * CSTR + col + 1] = c[nt][3];
  }
  __syncthreads();
  #pragma unroll
  for (int r = 0; r < 32; r++) {
    int idx = t + r * 256;
    int cc = idx >> 6, n = idx & 63;
    size_t g = (size_t)(s * CD + c0 + cc) * HW + n0 + n;
    tout[g] = tgt[g] + Cs[n * CSTR + cc] * linv[s * HW + n0 + n];
  }
}

// ================= instance norm =================
__global__ __launch_bounds__(256) void instnorm_kernel(float* __restrict__ x) {
  __shared__ float redS[8];
  __shared__ float redQ[8];
  float* p = x + (size_t)blockIdx.x * HW;
  int t = threadIdx.x, lane = t & 31, warp = t >> 5;
  float v0 = p[t], v1 = p[t + 256], v2 = p[t + 512], v3 = p[t + 768];
  float sum = v0 + v1 + v2 + v3;
  float sq = v0 * v0 + v1 * v1 + v2 * v2 + v3 * v3;
  #pragma unroll
  for (int o = 16; o; o >>= 1) {
    sum += __shfl_xor_sync(0xffffffffu, sum, o);
    sq  += __shfl_xor_sync(0xffffffffu, sq, o);
  }
  if (lane == 0) { redS[warp] = sum; redQ[warp] = sq; }
  __syncthreads();
  sum = redS[0]; sq = redQ[0];
  #pragma unroll
  for (int i = 1; i < 8; i++) { sum += redS[i]; sq += redQ[i]; }
  float mean = sum * (1.0f / HW);
  float var = sq * (1.0f / HW) - mean * mean;
  float rstd = rsqrtf(var + 1e-5f);
  p[t]       = (v0 - mean) * rstd;
  p[t + 256] = (v1 - mean) * rstd;
  p[t + 512] = (v2 - mean) * rstd;
  p[t + 768] = (v3 - mean) * rstd;
}

// ================= cross attention: 128-q blocks, fused passes =================
#define QSTR 136
#define VSTR 136
#define XOFF_QH 0
#define XOFF_QL 34816
#define XOFF_KH 69632
#define XOFF_KL 104448
#define XOFF_VTH 139264
#define XOFF_VTL 143616
#define SMEM_CROSS 147968

__global__ __launch_bounds__(256, 1) void cross_attn_kernel(
    const __nv_bfloat16* __restrict__ qhi, const __nv_bfloat16* __restrict__ qlo,
    const __nv_bfloat16* __restrict__ khi, const __nv_bfloat16* __restrict__ klo,
    const __nv_bfloat16* __restrict__ pehi, const __nv_bfloat16* __restrict__ pelo,
    float* __restrict__ part) {
  extern __shared__ char smc[];
  __nv_bfloat16* Qh  = (__nv_bfloat16*)(smc + XOFF_QH);
  __nv_bfloat16* Ql  = (__nv_bfloat16*)(smc + XOFF_QL);
  __nv_bfloat16* Kh  = (__nv_bfloat16*)(smc + XOFF_KH);
  __nv_bfloat16* Kl  = (__nv_bfloat16*)(smc + XOFF_KL);
  __nv_bfloat16* Vth = (__nv_bfloat16*)(smc + XOFF_VTH);
  __nv_bfloat16* Vtl = (__nv_bfloat16*)(smc + XOFF_VTL);
  int qt = blockIdx.x, s = blockIdx.y, ksp = blockIdx.z;
  int q0 = qt * 128;
  int t = threadIdx.x;
  int w = t >> 5, lane = t & 31;
  int lr = lane >> 2, lc = lane & 3;
  int mq = w * 16;

  {
    const uint4* gqh = (const uint4*)(qhi + ((size_t)s * HW + q0) * KD);
    const uint4* gql = (const uint4*)(qlo + ((size_t)s * HW + q0) * KD);
    #pragma unroll
    for (int r = 0; r < 8; r++) {
      int idx = t + r * 256;
      int row = idx >> 4, u8 = (idx & 15) * 8;
      *(uint4*)(Qh + row * QSTR + u8) = gqh[idx];
      *(uint4*)(Ql + row * QSTR + u8) = gql[idx];
    }
  }
  float cpv[2][4];
  #pragma unroll
  for (int et = 0; et < 2; et++)
    #pragma unroll
    for (int j = 0; j < 4; j++) cpv[et][j] = 0.0f;
  float slacc = 0.0f, shacc = 0.0f;

  for (int kt = 0; kt < NM / (KSPLIT * 128); kt++) {
    int kk0 = ksp * (NM / KSPLIT) + kt * 128;
    __syncthreads();
    {
      const uint4* gh = (const uint4*)(khi + ((size_t)s * NM + kk0) * KD);
      const uint4* gl = (const uint4*)(klo + ((size_t)s * NM + kk0) * KD);
      #pragma unroll
      for (int r = 0; r < 8; r++) {
        int idx = t + r * 256;
        int key = idx >> 4, d8 = (idx & 15) * 8;
        *(uint4*)(Kh + key * QSTR + d8) = gh[idx];
        *(uint4*)(Kl + key * QSTR + d8) = gl[idx];
      }
    }
    {
      int f = kk0 >> 10, nn0 = kk0 & 1023;
      size_t pb = ((size_t)(f * S4 + s) * CE) * HW + nn0;
      int e = t >> 4, k8 = (t & 15) * 8;
      *(uint4*)(Vth + e * VSTR + k8) = *(const uint4*)(pehi + pb + (size_t)e * HW + k8);
      *(uint4*)(Vtl + e * VSTR + k8) = *(const uint4*)(pelo + pb + (size_t)e * HW + k8);
    }
    __syncthreads();
    // ---- scores: both halves, fused 3-pass ----
    float c[2][8][4];
    #pragma unroll
    for (int h = 0; h < 2; h++)
      #pragma unroll
      for (int nt = 0; nt < 8; nt++)
        #pragma unroll
        for (int j = 0; j < 4; j++) c[h][nt][j] = 0.0f;
    #pragma unroll
    for (int ds = 0; ds < 8; ds++) {
      int d0 = ds * 16 + lc * 2;
      uint32_t ah0 = *(const uint32_t*)(Qh + (mq + lr) * QSTR + d0);
      uint32_t ah1 = *(const uint32_t*)(Qh + (mq + 8 + lr) * QSTR + d0);
      uint32_t ah2 = *(const uint32_t*)(Qh + (mq + lr) * QSTR + d0 + 8);
      uint32_t ah3 = *(const uint32_t*)(Qh + (mq + 8 + lr) * QSTR + d0 + 8);
      uint32_t al0 = *(const uint32_t*)(Ql + (mq + lr) * QSTR + d0);
      uint32_t al1 = *(const uint32_t*)(Ql + (mq + 8 + lr) * QSTR + d0);
      uint32_t al2 = *(const uint32_t*)(Ql + (mq + lr) * QSTR + d0 + 8);
      uint32_t al3 = *(const uint32_t*)(Ql + (mq + 8 + lr) * QSTR + d0 + 8);
      #pragma unroll
      for (int h = 0; h < 2; h++) {
        int kb = h * 64;
        #pragma unroll
        for (int nt = 0; nt < 8; nt++) {
          const __nv_bfloat16* brh = Kh + (kb + nt * 8 + lr) * QSTR + d0;
          uint32_t bh0 = *(const uint32_t*)(brh);
          uint32_t bh1 = *(const uint32_t*)(brh + 8);
          mma_bf16(c[h][nt], ah0, ah1, ah2, ah3, bh0, bh1);
          mma_bf16(c[h][nt], al0, al1, al2, al3, bh0, bh1);
          const __nv_bfloat16* brl = Kl + (kb + nt * 8 + lr) * QSTR + d0;
          uint32_t bl0 = *(const uint32_t*)(brl);
          uint32_t bl1 = *(const uint32_t*)(brl + 8);
          mma_bf16(c[h][nt], ah0, ah1, ah2, ah3, bl0, bl1);
        }
      }
    }
    // ---- per half: exp + fused PV ----
    #pragma unroll
    for (int h = 0; h < 2; h++) {
      int kb = h * 64;
      uint32_t ph[4][4], pl[4][4];
      #pragma unroll
      for (int ks = 0; ks < 4; ks++) {
        #pragma unroll
        for (int h2 = 0; h2 < 2; h2++) {
          int nt = 2 * ks + h2;
          float e0 = __expf(fmaf(c[h][nt][0], 30.0f, -30.0f));
          float e1 = __expf(fmaf(c[h][nt][1], 30.0f, -30.0f));
          float e2 = __expf(fmaf(c[h][nt][2], 30.0f, -30.0f));
          float e3 = __expf(fmaf(c[h][nt][3], 30.0f, -30.0f));
          slacc += e0 + e1;
          shacc += e2 + e3;
          float l0, l1, l2, l3;
          ph[ks][0 + h2 * 2] = pack_hi2(e0, e1, l0, l1);
          ph[ks][1 + h2 * 2] = pack_hi2(e2, e3, l2, l3);
          pl[ks][0 + h2 * 2] = pack_bf2(l0, l1);
          pl[ks][1 + h2 * 2] = pack_bf2(l2, l3);
        }
      }
      #pragma unroll
      for (int ks = 0; ks < 4; ks++) {
        int d0 = kb + ks * 16 + lc * 2;
        #pragma unroll
        for (int et = 0; et < 2; et++) {
          const __nv_bfloat16* brh = Vth + (et * 8 + lr) * VSTR + d0;
          uint32_t bh0 = *(const uint32_t*)(brh);
          uint32_t bh1 = *(const uint32_t*)(brh + 8);
          mma_bf16(cpv[et], ph[ks][0], ph[ks][1], ph[ks][2], ph[ks][3], bh0, bh1);
          mma_bf16(cpv[et], pl[ks][0], pl[ks][1], pl[ks][2], pl[ks][3], bh0, bh1);
          const __nv_bfloat16* brl = Vtl + (et * 8 + lr) * VSTR + d0;
          uint32_t bl0 = *(const uint32_t*)(brl);
          uint32_t bl1 = *(const uint32_t*)(brl + 8);
          mma_bf16(cpv[et], ph[ks][0], ph[ks][1], ph[ks][2], ph[ks][3], bl0, bl1);
        }
      }
    }
  }
  slacc += __shfl_xor_sync(0xffffffffu, slacc, 1);
  slacc += __shfl_xor_sync(0xffffffffu, slacc, 2);
  shacc += __shfl_xor_sync(0xffffffffu, shacc, 1);
  shacc += __shfl_xor_sync(0xffffffffu, shacc, 2);
  {
    float* pp0 = part + (((size_t)(ksp * S4 + s) * HW) + q0 + mq + lr) * 18;
    float* pp1 = part + (((size_t)(ksp * S4 + s) * HW) + q0 + mq + 8 + lr) * 18;
    #pragma unroll
    for (int et = 0; et < 2; et++) {
      int col = et * 8 + lc * 2;
      pp0[col]     = cpv[et][0];
      pp0[col + 1] = cpv[et][1];
      pp1[col]     = cpv[et][2];
      pp1[col + 1] = cpv[et][3];
    }
    if (lc == 0) {
      pp0[16] = slacc;
      pp1[16] = shacc;
    }
  }
}

// ================= merge split-K partials + sigmoid =================
__global__ __launch_bounds__(256) void merge_kernel(
    const float* __restrict__ part, float* __restrict__ out) {
  int g = blockIdx.x * 256 + threadIdx.x;
  int eg = (g & 3) * 4;
  int sn = g >> 2;
  int n = sn & 1023, s = sn >> 10;
  float L = 0.0f;
  float O[4] = {};
  #pragma unroll
  for (int z = 0; z < KSPLIT; z++) {
    const float* pp = part + ((size_t)((z * S4 + s) * HW) + n) * 18;
    L += pp[16];
    #pragma unroll
    for (int e = 0; e < 4; e++) O[e] += pp[eg + e];
  }
  float inv = 1.0f / L;
  #pragma unroll
  for (int e = 0; e < 4; e++) {
    float v = O[e] * inv;
    out[(size_t)(s * CE + eg + e) * HW + n] = 1.0f / (1.0f + __expf(-v));
  }
}

// ================= host =================
extern "C" void kernel_launch(void* const* d_in, const int* in_sizes, int n_in,
                              void* d_out, int out_size) {
  const float* tgt = (const float*)d_in[0];
  const float* mem = (const float*)d_in[1];
  const float* pe  = (const float*)d_in[2];
  const float* wks = (const float*)d_in[3];
  const float* bks = (const float*)d_in[4];
  const float* wkc = (const float*)d_in[5];
  const float* bkc = (const float*)d_in[6];
  float* out = (float*)d_out;

  float *p_t, *p_part, *p_lpart, *p_linv;
  __nv_bfloat16 *p_wk_hi, *p_wk_lo, *p_p_hi, *p_p_lo, *p_v_hi, *p_v_lo;
  __nv_bfloat16 *p_qs_hi, *p_qs_lo, *p_qc_hi, *p_qc_lo;
  __nv_bfloat16 *p_w1_hi, *p_w1_lo, *p_w2_hi, *p_w2_lo, *p_pe_hi, *p_pe_lo;
  cudaGetSymbolAddress((void**)&p_t, g_t);
  cudaGetSymbolAddress((void**)&p_wk_hi, g_wk_hi);
  cudaGetSymbolAddress((void**)&p_wk_lo, g_wk_lo);
  cudaGetSymbolAddress((void**)&p_p_hi, g_p_hi);
  cudaGetSymbolAddress((void**)&p_p_lo, g_p_lo);
  cudaGetSymbolAddress((void**)&p_v_hi, g_v_hi);
  cudaGetSymbolAddress((void**)&p_v_lo, g_v_lo);
  cudaGetSymbolAddress((void**)&p_qs_hi, g_qs_hi);
  cudaGetSymbolAddress((void**)&p_qs_lo, g_qs_lo);
  cudaGetSymbolAddress((void**)&p_qc_hi, g_qc_hi);
  cudaGetSymbolAddress((void**)&p_qc_lo, g_qc_lo);
  cudaGetSymbolAddress((void**)&p_w1_hi, g_w1_hi);
  cudaGetSymbolAddress((void**)&p_w1_lo, g_w1_lo);
  cudaGetSymbolAddress((void**)&p_w2_hi, g_w2_hi);
  cudaGetSymbolAddress((void**)&p_w2_lo, g_w2_lo);
  cudaGetSymbolAddress((void**)&p_pe_hi, g_pe_hi);
  cudaGetSymbolAddress((void**)&p_pe_lo, g_pe_lo);
  cudaGetSymbolAddress((void**)&p_lpart, g_lpart);
  cudaGetSymbolAddress((void**)&p_linv, g_linv);
  cudaGetSymbolAddress((void**)&p_part, g_part);

  cudaFuncSetAttribute(proj_mma_kernel,
                       cudaFuncAttributeMaxDynamicSharedMemorySize, SMEM_PROJ);
  cudaFuncSetAttribute(self_scores_mma,
                       cudaFuncAttributeMaxDynamicSharedMemorySize, SMEM_SS);
  cudaFuncSetAttribute(pv_mma_kernel,
                       cudaFuncAttributeMaxDynamicSharedMemorySize, SMEM_PV);
  cudaFuncSetAttribute(cross_attn_kernel,
                       cudaFuncAttributeMaxDynamicSharedMemorySize, SMEM_CROSS);

  // constant pre-splits
  split_v_kernel<<<64, 256>>>(wks, p_w1_hi, p_w1_lo);
  split_v_kernel<<<64, 256>>>(wkc, p_w2_hi, p_w2_lo);
  split_v_kernel<<<1024, 256>>>(pe, p_pe_hi, p_pe_lo);
  split_v_kernel<<<2048, 256>>>(tgt, p_v_hi, p_v_lo);

  // self-attention
  proj_mma_kernel<<<dim3(16, 4), 256, SMEM_PROJ>>>(tgt, p_w1_hi, p_w1_lo, bks, p_qs_hi, p_qs_lo, HW);
  self_scores_mma<<<dim3(16, 16, 4), 256, SMEM_SS>>>(p_qs_hi, p_qs_lo, p_p_hi, p_p_lo, p_lpart);
  rowsum_kernel<<<16, 256>>>(p_lpart, p_linv);
  pv_mma_kernel<<<dim3(16, 4, 4), 256, SMEM_PV>>>(p_p_hi, p_p_lo, p_v_hi, p_v_lo, tgt, p_linv, p_t);
  instnorm_kernel<<<2048, 256>>>(p_t);

  // cross projections
  proj_mma_kernel<<<dim3(16, 4), 256, SMEM_PROJ>>>(p_t, p_w2_hi, p_w2_lo, bkc, p_qc_hi, p_qc_lo, HW);
  proj_mma_kernel<<<dim3(256, 4), 256, SMEM_PROJ>>>(mem, p_w2_hi, p_w2_lo, bkc, p_wk_hi, p_wk_lo, NM);

  // HMMA cross-attention
  cross_attn_kernel<<<dim3(8, 4, KSPLIT), 256, SMEM_CROSS>>>(
      p_qc_hi, p_qc_lo, p_wk_hi, p_wk_lo, p_pe_hi, p_pe_lo, p_part);
  merge_kernel<<<64, 256>>>(p_part, out);
}